// round 1
// baseline (speedup 1.0000x reference)
#include <cuda_runtime.h>
#include <math.h>
#include <stdint.h>

// ---------------------------------------------------------------------------
// Problem constants
// ---------------------------------------------------------------------------
#define NTOK   8192
#define INDIM  1024
#define DMODEL 512
#define NHEADS 8
#define DH     64
#define MLAND  256
#define LWIN   33
#define NP     8448          // padded attention length (8282 + 166)
#define NHTOK  8282          // tokens incl cls (1 + 8281)
#define PADF   166
#define HSQ    91
#define NFEAT  8281
#define NWRAP  89            // 91*91 - 8192
#define EPSLN  1e-5f

#define FLAG_RELU 1
#define FLAG_ACC  2

// ---------------------------------------------------------------------------
// Scratch (device globals; no runtime allocation)
// ---------------------------------------------------------------------------
__device__ float g_H  [NHTOK * DMODEL];
__device__ float g_H2 [NHTOK * DMODEL];
__device__ float g_XP [NP * DMODEL];
__device__ float g_QKV[NP * 3 * DMODEL];
__device__ float g_QL [NHEADS * MLAND * DH];
__device__ float g_KL [NHEADS * MLAND * DH];
__device__ float g_A2 [NHEADS * MLAND * MLAND];
__device__ float g_Z0 [NHEADS * MLAND * MLAND];
__device__ float g_Z1 [NHEADS * MLAND * MLAND];
__device__ float g_W1 [NHEADS * MLAND * MLAND];
__device__ float g_W2 [NHEADS * MLAND * MLAND];
__device__ float g_W3 [NHEADS * MLAND * MLAND];
__device__ float g_S  [NHEADS * MLAND * NP];      // a3 logits -> exp values
__device__ float g_RS [NHEADS * MLAND];           // a3 row sums
__device__ float g_A3V[NHEADS * MLAND * DH];
__device__ float g_Bm [NHEADS * MLAND * DH];      // pinv(a2) @ (a3 @ v)
__device__ float g_O  [NP * DMODEL];              // attention output (pre-proj)

// ---------------------------------------------------------------------------
// Generic SGEMM: C = op(A@B)  (128x128 tile, 8x8 per thread, BK=16)
//   A: Mn x Kn, B: Kn x Nn, C: Mn x Nn (all row-major).  Nn % 128 == 0,
//   Kn % 16 == 0 required.  Columns < scale_cols are multiplied by `scale`
//   before bias/relu (used for the q part of the qkv projection).
// ---------------------------------------------------------------------------
__global__ void sgemm_kernel(const float* __restrict__ A, const float* __restrict__ B,
                             float* __restrict__ C, const float* __restrict__ bias,
                             int Mn, int Nn, int Kn, int flags, int scale_cols, float scale)
{
    __shared__ float As[16][128];
    __shared__ float Bs[16][128];
    const int bm = blockIdx.y * 128;
    const int bn = blockIdx.x * 128;
    const int tid = threadIdx.x;
    const int tx = tid & 15, ty = tid >> 4;
    const int row0 = ty * 8, col0 = tx * 8;
    float acc[8][8];
#pragma unroll
    for (int i = 0; i < 8; i++)
#pragma unroll
        for (int j = 0; j < 8; j++) acc[i][j] = 0.f;

    for (int k0 = 0; k0 < Kn; k0 += 16) {
#pragma unroll
        for (int i = 0; i < 2; i++) {
            int lin = tid + i * 256;
            int ar = lin >> 2;
            int ac = (lin & 3) << 2;
            float4 v = make_float4(0.f, 0.f, 0.f, 0.f);
            if (bm + ar < Mn)
                v = *reinterpret_cast<const float4*>(A + (size_t)(bm + ar) * Kn + k0 + ac);
            As[ac + 0][ar] = v.x; As[ac + 1][ar] = v.y;
            As[ac + 2][ar] = v.z; As[ac + 3][ar] = v.w;
        }
#pragma unroll
        for (int i = 0; i < 2; i++) {
            int lin = tid + i * 256;
            int br = lin >> 5;
            int bc = (lin & 31) << 2;
            float4 v = *reinterpret_cast<const float4*>(B + (size_t)(k0 + br) * Nn + bn + bc);
            *reinterpret_cast<float4*>(&Bs[br][bc]) = v;
        }
        __syncthreads();
#pragma unroll
        for (int k = 0; k < 16; k++) {
            float a[8], b[8];
            *reinterpret_cast<float4*>(a)     = *reinterpret_cast<const float4*>(&As[k][row0]);
            *reinterpret_cast<float4*>(a + 4) = *reinterpret_cast<const float4*>(&As[k][row0 + 4]);
            *reinterpret_cast<float4*>(b)     = *reinterpret_cast<const float4*>(&Bs[k][col0]);
            *reinterpret_cast<float4*>(b + 4) = *reinterpret_cast<const float4*>(&Bs[k][col0 + 4]);
#pragma unroll
            for (int i = 0; i < 8; i++)
#pragma unroll
                for (int j = 0; j < 8; j++) acc[i][j] += a[i] * b[j];
        }
        __syncthreads();
    }
    const bool relu = (flags & FLAG_RELU) != 0;
    const bool accu = (flags & FLAG_ACC) != 0;
#pragma unroll
    for (int i = 0; i < 8; i++) {
        int r = bm + row0 + i;
        if (r >= Mn) continue;
#pragma unroll
        for (int j = 0; j < 8; j++) {
            int cidx = bn + col0 + j;
            float v = acc[i][j];
            if (cidx < scale_cols) v *= scale;
            if (bias) v += bias[cidx];
            if (relu) v = fmaxf(v, 0.f);
            size_t o = (size_t)r * Nn + cidx;
            if (accu) C[o] += v; else C[o] = v;
        }
    }
}

// ---------------------------------------------------------------------------
// Assemble h: row 0 = cls token, rows 8193..8281 = wrap of relu rows 0..88
// (fc1 gemm already wrote relu rows into g_H rows 1..8192)
// ---------------------------------------------------------------------------
__global__ void assemble_kernel(const float* __restrict__ cls, float* __restrict__ H)
{
    int j = blockIdx.x;        // 0..89
    int c = threadIdx.x;       // 512
    if (j == 0) H[c] = cls[c];
    else        H[(size_t)(NTOK + j) * DMODEL + c] = H[(size_t)j * DMODEL + c];
}

// ---------------------------------------------------------------------------
// LayerNorm of H (8282 x 512) into padded XP (8448 x 512), first 166 rows zero
// ---------------------------------------------------------------------------
__global__ void ln_pad_kernel(const float* __restrict__ Hin, float* __restrict__ XP,
                              const float* __restrict__ g, const float* __restrict__ b)
{
    int row = blockIdx.x;      // 0..8447
    int tid = threadIdx.x;     // 256
    if (row < PADF) {
        XP[(size_t)row * DMODEL + tid] = 0.f;
        XP[(size_t)row * DMODEL + tid + 256] = 0.f;
        return;
    }
    const float* x = Hin + (size_t)(row - PADF) * DMODEL;
    float v0 = x[tid], v1 = x[tid + 256];
    __shared__ float s1[256], s2[256];
    s1[tid] = v0 + v1;
    s2[tid] = v0 * v0 + v1 * v1;
    __syncthreads();
    for (int o = 128; o > 0; o >>= 1) {
        if (tid < o) { s1[tid] += s1[tid + o]; s2[tid] += s2[tid + o]; }
        __syncthreads();
    }
    float mean = s1[0] * (1.f / DMODEL);
    float var  = s2[0] * (1.f / DMODEL) - mean * mean;
    float rs = rsqrtf(var + EPSLN);
    XP[(size_t)row * DMODEL + tid]       = (v0 - mean) * rs * g[tid] + b[tid];
    XP[(size_t)row * DMODEL + tid + 256] = (v1 - mean) * rs * g[tid + 256] + b[tid + 256];
}

// ---------------------------------------------------------------------------
// Landmarks: mean over consecutive groups of 33 tokens
// ---------------------------------------------------------------------------
__global__ void landmarks_kernel(const float* __restrict__ QKV,
                                 float* __restrict__ QL, float* __restrict__ KL)
{
    int hm = blockIdx.x;          // 0..2047
    int h = hm >> 8, m = hm & 255;
    int tid = threadIdx.x;        // 128
    int d = tid & 63;
    int off = (tid < 64) ? 0 : DMODEL;
    size_t base = (size_t)(m * LWIN) * (3 * DMODEL) + off + h * DH + d;
    float s = 0.f;
#pragma unroll
    for (int j = 0; j < LWIN; j++) s += QKV[base + (size_t)j * (3 * DMODEL)];
    s *= (1.0f / LWIN);
    float* dst = (tid < 64) ? QL : KL;
    dst[(size_t)(h * MLAND + m) * DH + d] = s;
}

// ---------------------------------------------------------------------------
// a2 = softmax(q_l @ k_l^T): one block per (m, h); 256 threads = 256 cols
// ---------------------------------------------------------------------------
__global__ void a2_kernel(const float* __restrict__ QL, const float* __restrict__ KL,
                          float* __restrict__ A2)
{
    int m = blockIdx.x, h = blockIdx.y;
    int tid = threadIdx.x;
    __shared__ float q[64];
    __shared__ float red[256];
    if (tid < 64) q[tid] = QL[(size_t)(h * MLAND + m) * DH + tid];
    __syncthreads();
    const float* kr = KL + (size_t)(h * MLAND + tid) * DH;
    float s = 0.f;
#pragma unroll
    for (int i = 0; i < 16; i++) {
        float4 kv = reinterpret_cast<const float4*>(kr)[i];
        float4 qv = reinterpret_cast<const float4*>(q)[i];
        s += kv.x * qv.x + kv.y * qv.y + kv.z * qv.z + kv.w * qv.w;
    }
    red[tid] = s; __syncthreads();
    for (int o = 128; o > 0; o >>= 1) {
        if (tid < o) red[tid] = fmaxf(red[tid], red[tid + o]);
        __syncthreads();
    }
    float mx = red[0]; __syncthreads();
    float e = expf(s - mx);
    red[tid] = e; __syncthreads();
    for (int o = 128; o > 0; o >>= 1) {
        if (tid < o) red[tid] += red[tid + o];
        __syncthreads();
    }
    float sm = red[0];
    A2[(size_t)(h * MLAND + m) * MLAND + tid] = e / sm;
}

// ---------------------------------------------------------------------------
// pinv init: z0 = a2^T / (max_rowsum * max_colsum), per head
// ---------------------------------------------------------------------------
__global__ void pinv_init_kernel(const float* __restrict__ A2, float* __restrict__ Z0)
{
    int h = blockIdx.x;
    int tid = threadIdx.x;
    const float* Ah = A2 + (size_t)h * 65536;
    float rs = 0.f, cs = 0.f;
    for (int j = 0; j < 256; j++) rs += fabsf(Ah[tid * 256 + j]);
    for (int i = 0; i < 256; i++) cs += fabsf(Ah[i * 256 + tid]);
    __shared__ float r1[256], r2[256];
    r1[tid] = rs; r2[tid] = cs; __syncthreads();
    for (int o = 128; o > 0; o >>= 1) {
        if (tid < o) { r1[tid] = fmaxf(r1[tid], r1[tid + o]); r2[tid] = fmaxf(r2[tid], r2[tid + o]); }
        __syncthreads();
    }
    float inv = 1.0f / (r1[0] * r2[0]);
    __syncthreads();
    float* Zh = Z0 + (size_t)h * 65536;
    for (int lin = tid; lin < 65536; lin += 256) {
        int i = lin >> 8, j = lin & 255;
        Zh[i * 256 + j] = Ah[j * 256 + i] * inv;
    }
}

// ---------------------------------------------------------------------------
// Batched 256x256x256 matmul: C = alpha*(A@B) + gamma*A   (per head in z)
// 64x64 tiles, 4x4 per thread
// ---------------------------------------------------------------------------
__global__ void nk256_kernel(const float* __restrict__ A, const float* __restrict__ B,
                             float* __restrict__ C, float alpha, float gamma)
{
    const float* Ah = A + (size_t)blockIdx.z * 65536;
    const float* Bh = B + (size_t)blockIdx.z * 65536;
    float* Ch = C + (size_t)blockIdx.z * 65536;
    __shared__ float As[16][64];
    __shared__ float Bs[16][64];
    const int bm = blockIdx.y * 64;
    const int bn = blockIdx.x * 64;
    const int tid = threadIdx.x;
    const int tx = tid & 15, ty = tid >> 4;
    const int row0 = ty * 4, col0 = tx * 4;
    float acc[4][4];
#pragma unroll
    for (int i = 0; i < 4; i++)
#pragma unroll
        for (int j = 0; j < 4; j++) acc[i][j] = 0.f;

    for (int k0 = 0; k0 < 256; k0 += 16) {
        {
            int ar = tid >> 2;
            int ac = (tid & 3) << 2;
            float4 v = *reinterpret_cast<const float4*>(Ah + (size_t)(bm + ar) * 256 + k0 + ac);
            As[ac + 0][ar] = v.x; As[ac + 1][ar] = v.y;
            As[ac + 2][ar] = v.z; As[ac + 3][ar] = v.w;
        }
        {
            int br = tid >> 4;
            int bc = (tid & 15) << 2;
            float4 v = *reinterpret_cast<const float4*>(Bh + (size_t)(k0 + br) * 256 + bn + bc);
            *reinterpret_cast<float4*>(&Bs[br][bc]) = v;
        }
        __syncthreads();
#pragma unroll
        for (int k = 0; k < 16; k++) {
            float a[4], b[4];
            *reinterpret_cast<float4*>(a) = *reinterpret_cast<const float4*>(&As[k][row0]);
            *reinterpret_cast<float4*>(b) = *reinterpret_cast<const float4*>(&Bs[k][col0]);
#pragma unroll
            for (int i = 0; i < 4; i++)
#pragma unroll
                for (int j = 0; j < 4; j++) acc[i][j] += a[i] * b[j];
        }
        __syncthreads();
    }
#pragma unroll
    for (int i = 0; i < 4; i++)
#pragma unroll
        for (int j = 0; j < 4; j++) {
            size_t o = (size_t)(bm + row0 + i) * 256 + bn + col0 + j;
            Ch[o] = alpha * acc[i][j] + gamma * Ah[o];
        }
}

// ---------------------------------------------------------------------------
// a3 logits: S[h][m][n] = dot(q_l[h][m], k[h][n]); one block per (m,h)
// ---------------------------------------------------------------------------
__global__ void a3_logits_kernel(const float* __restrict__ QKV, const float* __restrict__ QL,
                                 float* __restrict__ S)
{
    int m = blockIdx.x, h = blockIdx.y;
    int tid = threadIdx.x;
    __shared__ float q[64];
    if (tid < 64) q[tid] = QL[(size_t)(h * MLAND + m) * DH + tid];
    __syncthreads();
    float* Srow = S + (size_t)(h * MLAND + m) * NP;
    for (int n = tid; n < NP; n += 256) {
        const float* kr = QKV + (size_t)n * (3 * DMODEL) + DMODEL + h * DH;
        float s = 0.f;
#pragma unroll
        for (int i = 0; i < 16; i++) {
            float4 kv = reinterpret_cast<const float4*>(kr)[i];
            float4 qv = reinterpret_cast<const float4*>(q)[i];
            s += kv.x * qv.x + kv.y * qv.y + kv.z * qv.z + kv.w * qv.w;
        }
        Srow[n] = s;
    }
}

// ---------------------------------------------------------------------------
// a3 softmax (stores unnormalized exp; row sum in RS)
// ---------------------------------------------------------------------------
__global__ void a3_softmax_kernel(float* __restrict__ S, float* __restrict__ RS)
{
    int m = blockIdx.x, h = blockIdx.y;
    int tid = threadIdx.x;
    float* row = S + (size_t)(h * MLAND + m) * NP;
    __shared__ float red[256];
    float mx = -1e30f;
    for (int n = tid; n < NP; n += 256) mx = fmaxf(mx, row[n]);
    red[tid] = mx; __syncthreads();
    for (int o = 128; o > 0; o >>= 1) {
        if (tid < o) red[tid] = fmaxf(red[tid], red[tid + o]);
        __syncthreads();
    }
    mx = red[0]; __syncthreads();
    float sum = 0.f;
    for (int n = tid; n < NP; n += 256) {
        float e = expf(row[n] - mx);
        row[n] = e;
        sum += e;
    }
    red[tid] = sum; __syncthreads();
    for (int o = 128; o > 0; o >>= 1) {
        if (tid < o) red[tid] += red[tid + o];
        __syncthreads();
    }
    if (tid == 0) RS[h * MLAND + m] = red[0];
}

// ---------------------------------------------------------------------------
// a3v = (exp @ v) / rowsum : block handles 16 landmark rows of one head
// ---------------------------------------------------------------------------
__global__ void a3v_kernel(const float* __restrict__ S, const float* __restrict__ QKV,
                           const float* __restrict__ RS, float* __restrict__ A3V)
{
    int h = blockIdx.y;
    int mt = blockIdx.x * 16;
    __shared__ float vs[64][64];
    __shared__ float es[16][64];
    int tid = threadIdx.x;
    int d = tid & 63, g = tid >> 6;
    float acc[4] = {0.f, 0.f, 0.f, 0.f};
    for (int n0 = 0; n0 < NP; n0 += 64) {
        for (int lin = tid; lin < 4096; lin += 256) {
            int r = lin >> 6, c = lin & 63;
            vs[r][c] = QKV[(size_t)(n0 + r) * (3 * DMODEL) + 2 * DMODEL + h * DH + c];
        }
        for (int lin = tid; lin < 1024; lin += 256) {
            int r = lin >> 6, c = lin & 63;
            es[r][c] = S[(size_t)(h * MLAND + mt + r) * NP + n0 + c];
        }
        __syncthreads();
#pragma unroll 4
        for (int j = 0; j < 64; j++) {
            float vv = vs[j][d];
#pragma unroll
            for (int r = 0; r < 4; r++) acc[r] += es[g * 4 + r][j] * vv;
        }
        __syncthreads();
    }
#pragma unroll
    for (int r = 0; r < 4; r++) {
        int m = mt + g * 4 + r;
        A3V[(size_t)(h * MLAND + m) * DH + d] = acc[r] / RS[h * MLAND + m];
    }
}

// ---------------------------------------------------------------------------
// Bm = pinv(a2) @ a3v : per head; block = 4 rows x 64 dims
// ---------------------------------------------------------------------------
__global__ void bmat_kernel(const float* __restrict__ Z, const float* __restrict__ A3V,
                            float* __restrict__ Bm)
{
    int h = blockIdx.y;
    int m0 = blockIdx.x * 4;
    __shared__ float zs[4][256];
    int tid = threadIdx.x;
    int r = tid >> 6, d = tid & 63;
    for (int lin = tid; lin < 1024; lin += 256) {
        int rr = lin >> 8, k = lin & 255;
        zs[rr][k] = Z[(size_t)h * 65536 + (size_t)(m0 + rr) * 256 + k];
    }
    __syncthreads();
    float acc = 0.f;
    for (int k = 0; k < 256; k++)
        acc += zs[r][k] * A3V[(size_t)(h * MLAND + k) * DH + d];
    Bm[(size_t)(h * MLAND + m0 + r) * DH + d] = acc;
}

// ---------------------------------------------------------------------------
// Fused a1 @ Bm: per row, logits vs k_l (smem), softmax, multiply by Bm (smem)
// dyn smem: kl(256x65) + B(256x64) + q(64) + p(256) + red(256) + red2(256)
// ---------------------------------------------------------------------------
__global__ void a1out_kernel(const float* __restrict__ QKV, const float* __restrict__ KL,
                             const float* __restrict__ Bm, float* __restrict__ O)
{
    extern __shared__ float sm[];
    float* kl   = sm;                 // 256*65
    float* bs   = kl + 256 * 65;      // 256*64
    float* q    = bs + 16384;         // 64
    float* p    = q + 64;             // 256
    float* red  = p + 256;            // 256
    float* red2 = red + 256;          // 256
    int h = blockIdx.y;
    int r0 = blockIdx.x * 32;
    int tid = threadIdx.x;
    for (int lin = tid; lin < 16384; lin += 256) {
        kl[(lin >> 6) * 65 + (lin & 63)] = KL[(size_t)h * 16384 + lin];
        bs[lin] = Bm[(size_t)h * 16384 + lin];
    }
    __syncthreads();
    const int g = tid >> 6, d = tid & 63;
    for (int rr = 0; rr < 32; rr++) {
        int row = r0 + rr;
        if (tid < 64) q[tid] = QKV[(size_t)row * (3 * DMODEL) + h * DH + tid];
        __syncthreads();
        const float* km = kl + tid * 65;
        float s = 0.f;
#pragma unroll
        for (int i = 0; i < 64; i++) s += q[i] * km[i];
        red[tid] = s; __syncthreads();
        for (int o = 128; o > 0; o >>= 1) {
            if (tid < o) red[tid] = fmaxf(red[tid], red[tid + o]);
            __syncthreads();
        }
        float mx = red[0]; __syncthreads();
        float e = expf(s - mx);
        p[tid] = e;
        red[tid] = e; __syncthreads();
        for (int o = 128; o > 0; o >>= 1) {
            if (tid < o) red[tid] += red[tid + o];
            __syncthreads();
        }
        float inv = 1.0f / red[0];
        // out phase: out[d] = sum_m p[m] * Bm[m][d]
        float part = 0.f;
        const float* bp = bs + g * 64 * 64 + d;
        const float* pp = p + g * 64;
#pragma unroll
        for (int j = 0; j < 64; j++) part += pp[j] * bp[j * 64];
        red2[tid] = part; __syncthreads();
        if (tid < 64) {
            float o_ = (red2[tid] + red2[64 + tid] + red2[128 + tid] + red2[192 + tid]) * inv;
            O[(size_t)row * DMODEL + h * DH + tid] = o_;
        }
        __syncthreads();
    }
}

// ---------------------------------------------------------------------------
// Depthwise conv over sequence (kernel 33, pad 16) on v; adds to O
// ---------------------------------------------------------------------------
__global__ void conv_add_kernel(const float* __restrict__ QKV, const float* __restrict__ W,
                                float* __restrict__ O)
{
    int n = blockIdx.x;        // 0..8447
    int c = threadIdx.x;       // 512
    int h = c >> 6;
    float acc = 0.f;
#pragma unroll
    for (int t = 0; t < LWIN; t++) {
        int j = n + t - (LWIN / 2);
        if ((unsigned)j < (unsigned)NP)
            acc += W[h * LWIN + t] * QKV[(size_t)j * (3 * DMODEL) + 2 * DMODEL + c];
    }
    O[(size_t)n * DMODEL + c] += acc;
}

// ---------------------------------------------------------------------------
// PPEG: depthwise 7x7 + 5x5 + 3x3 on 91x91x512 map (+identity +biases)
// ---------------------------------------------------------------------------
__global__ void ppeg_kernel(const float* __restrict__ Hin, float* __restrict__ Hout,
                            const float* __restrict__ w7, const float* __restrict__ b7,
                            const float* __restrict__ w5, const float* __restrict__ b5,
                            const float* __restrict__ w3, const float* __restrict__ b3)
{
    int t = blockIdx.x;          // 0..8280
    int y = t / HSQ, x = t - y * HSQ;
    int c = threadIdx.x;         // 512
    float acc = Hin[(size_t)(1 + t) * DMODEL + c] + b7[c] + b5[c] + b3[c];
    const float* wc7 = w7 + c * 49;
    const float* wc5 = w5 + c * 25;
    const float* wc3 = w3 + c * 9;
#pragma unroll
    for (int a = 0; a < 7; a++) {
        int yy = y + a - 3;
        if ((unsigned)yy >= (unsigned)HSQ) continue;
#pragma unroll
        for (int bq = 0; bq < 7; bq++) {
            int xx = x + bq - 3;
            if ((unsigned)xx >= (unsigned)HSQ) continue;
            acc += wc7[a * 7 + bq] * Hin[(size_t)(1 + yy * HSQ + xx) * DMODEL + c];
        }
    }
#pragma unroll
    for (int a = 0; a < 5; a++) {
        int yy = y + a - 2;
        if ((unsigned)yy >= (unsigned)HSQ) continue;
#pragma unroll
        for (int bq = 0; bq < 5; bq++) {
            int xx = x + bq - 2;
            if ((unsigned)xx >= (unsigned)HSQ) continue;
            acc += wc5[a * 5 + bq] * Hin[(size_t)(1 + yy * HSQ + xx) * DMODEL + c];
        }
    }
#pragma unroll
    for (int a = 0; a < 3; a++) {
        int yy = y + a - 1;
        if ((unsigned)yy >= (unsigned)HSQ) continue;
#pragma unroll
        for (int bq = 0; bq < 3; bq++) {
            int xx = x + bq - 1;
            if ((unsigned)xx >= (unsigned)HSQ) continue;
            acc += wc3[a * 3 + bq] * Hin[(size_t)(1 + yy * HSQ + xx) * DMODEL + c];
        }
    }
    Hout[(size_t)(1 + t) * DMODEL + c] = acc;
}

__global__ void copy_row0_kernel(const float* __restrict__ Hin, float* __restrict__ Hout)
{
    Hout[threadIdx.x] = Hin[threadIdx.x];
}

// ---------------------------------------------------------------------------
// Final: ln(row0) -> emb; logits = emb @ fc2_w + fc2_b; prob; argmax
// out layout: [logits(2), prob(2), yhat(1), emb(512)]
// ---------------------------------------------------------------------------
__global__ void final_kernel(const float* __restrict__ H, const float* __restrict__ g,
                             const float* __restrict__ b, const float* __restrict__ w,
                             const float* __restrict__ bias2, float* __restrict__ out,
                             int out_size)
{
    int c = threadIdx.x;       // 512
    __shared__ float s1[512], s2[512];
    float x = H[c];
    s1[c] = x; s2[c] = x * x;
    __syncthreads();
    for (int o = 256; o > 0; o >>= 1) {
        if (c < o) { s1[c] += s1[c + o]; s2[c] += s2[c + o]; }
        __syncthreads();
    }
    float mean = s1[0] * (1.f / DMODEL);
    float var  = s2[0] * (1.f / DMODEL) - mean * mean;
    float e = (x - mean) * rsqrtf(var + EPSLN) * g[c] + b[c];
    __syncthreads();
    s1[c] = e * w[c * 2 + 0];
    s2[c] = e * w[c * 2 + 1];
    __syncthreads();
    for (int o = 256; o > 0; o >>= 1) {
        if (c < o) { s1[c] += s1[c + o]; s2[c] += s2[c + o]; }
        __syncthreads();
    }
    float l0 = s1[0] + bias2[0];
    float l1 = s2[0] + bias2[1];
    if (c == 0) {
        float m = fmaxf(l0, l1);
        float e0 = expf(l0 - m), e1 = expf(l1 - m);
        float ss = e0 + e1;
        if (out_size > 0) out[0] = l0;
        if (out_size > 1) out[1] = l1;
        if (out_size > 2) out[2] = e0 / ss;
        if (out_size > 3) out[3] = e1 / ss;
        if (out_size > 4) out[4] = (l1 > l0) ? 1.0f : 0.0f;
    }
    if (5 + c < out_size) out[5 + c] = e;
}

// ---------------------------------------------------------------------------
// Host orchestration
// ---------------------------------------------------------------------------
static float* symaddr(const void* sym)
{
    void* p = nullptr;
    cudaGetSymbolAddress(&p, sym);
    return (float*)p;
}

extern "C" void kernel_launch(void* const* d_in, const int* in_sizes, int n_in,
                              void* d_out, int out_size)
{
    const float* x       = (const float*)d_in[0];
    const float* fc1_w   = (const float*)d_in[1];
    const float* fc1_b   = (const float*)d_in[2];
    const float* cls     = (const float*)d_in[3];
    const float* ln1_g   = (const float*)d_in[4];
    const float* ln1_b   = (const float*)d_in[5];
    const float* qkv1_w  = (const float*)d_in[6];
    const float* out1_w  = (const float*)d_in[7];
    const float* out1_b  = (const float*)d_in[8];
    const float* conv1_w = (const float*)d_in[9];
    const float* ln2_g   = (const float*)d_in[10];
    const float* ln2_b   = (const float*)d_in[11];
    const float* qkv2_w  = (const float*)d_in[12];
    const float* out2_w  = (const float*)d_in[13];
    const float* out2_b  = (const float*)d_in[14];
    const float* conv2_w = (const float*)d_in[15];
    const float* pg7_w   = (const float*)d_in[16];
    const float* pg7_b   = (const float*)d_in[17];
    const float* pg5_w   = (const float*)d_in[18];
    const float* pg5_b   = (const float*)d_in[19];
    const float* pg3_w   = (const float*)d_in[20];
    const float* pg3_b   = (const float*)d_in[21];
    const float* norm_g  = (const float*)d_in[22];
    const float* norm_b  = (const float*)d_in[23];
    const float* fc2_w   = (const float*)d_in[24];
    const float* fc2_b   = (const float*)d_in[25];

    float* H   = symaddr(g_H);
    float* H2  = symaddr(g_H2);
    float* XP  = symaddr(g_XP);
    float* QKV = symaddr(g_QKV);
    float* QL  = symaddr(g_QL);
    float* KL  = symaddr(g_KL);
    float* A2  = symaddr(g_A2);
    float* Z0  = symaddr(g_Z0);
    float* Z1  = symaddr(g_Z1);
    float* W1  = symaddr(g_W1);
    float* W2  = symaddr(g_W2);
    float* W3  = symaddr(g_W3);
    float* S   = symaddr(g_S);
    float* RS  = symaddr(g_RS);
    float* A3V = symaddr(g_A3V);
    float* Bm  = symaddr(g_Bm);
    float* O   = symaddr(g_O);

    const int A1_SMEM = (256 * 65 + 256 * 64 + 64 + 256 + 256 + 256) * 4;  // 135424 B
    cudaFuncSetAttribute(a1out_kernel, cudaFuncAttributeMaxDynamicSharedMemorySize, A1_SMEM);

    // fc1 + relu -> H rows 1..8192 ; then cls + wrap rows
    sgemm_kernel<<<dim3(DMODEL / 128, NTOK / 128), 256>>>(
        x, fc1_w, H + DMODEL, fc1_b, NTOK, DMODEL, INDIM, FLAG_RELU, 0, 1.f);
    assemble_kernel<<<NWRAP + 1, DMODEL>>>(cls, H);

    auto attn = [&](float* Hbuf, const float* lng, const float* lnb, const float* qkvw,
                    const float* outw, const float* outb, const float* convw) {
        ln_pad_kernel<<<NP, 256>>>(Hbuf, XP, lng, lnb);
        sgemm_kernel<<<dim3(3 * DMODEL / 128, NP / 128), 256>>>(
            XP, qkvw, QKV, nullptr, NP, 3 * DMODEL, DMODEL, 0, DMODEL, 0.125f);
        landmarks_kernel<<<NHEADS * MLAND, 128>>>(QKV, QL, KL);
        a2_kernel<<<dim3(MLAND, NHEADS), 256>>>(QL, KL, A2);
        pinv_init_kernel<<<NHEADS, 256>>>(A2, Z0);
        float* zi = Z0;
        float* zo = Z1;
        for (int it = 0; it < 6; it++) {
            nk256_kernel<<<dim3(4, 4, NHEADS), 256>>>(A2, zi, W1, 1.f, 0.f);
            nk256_kernel<<<dim3(4, 4, NHEADS), 256>>>(W1, W1, W2, -1.f, 7.f);
            nk256_kernel<<<dim3(4, 4, NHEADS), 256>>>(W1, W2, W3, -1.f, 15.f);
            nk256_kernel<<<dim3(4, 4, NHEADS), 256>>>(zi, W3, zo, -0.25f, 3.25f);
            float* t = zi; zi = zo; zo = t;
        }
        a3_logits_kernel<<<dim3(MLAND, NHEADS), 256>>>(QKV, QL, S);
        a3_softmax_kernel<<<dim3(MLAND, NHEADS), 256>>>(S, RS);
        a3v_kernel<<<dim3(MLAND / 16, NHEADS), 256>>>(S, QKV, RS, A3V);
        bmat_kernel<<<dim3(MLAND / 4, NHEADS), 256>>>(zi, A3V, Bm);
        a1out_kernel<<<dim3(NP / 32, NHEADS), 256, A1_SMEM>>>(QKV, KL, Bm, O);
        conv_add_kernel<<<NP, DMODEL>>>(QKV, convw, O);
        sgemm_kernel<<<dim3(DMODEL / 128, (NHTOK + 127) / 128), 256>>>(
            O + (size_t)PADF * DMODEL, outw, Hbuf, outb, NHTOK, DMODEL, DMODEL,
            FLAG_ACC, 0, 1.f);
    };

    attn(H, ln1_g, ln1_b, qkv1_w, out1_w, out1_b, conv1_w);

    ppeg_kernel<<<NFEAT, DMODEL>>>(H, H2, pg7_w, pg7_b, pg5_w, pg5_b, pg3_w, pg3_b);
    copy_row0_kernel<<<1, DMODEL>>>(H, H2);

    attn(H2, ln2_g, ln2_b, qkv2_w, out2_w, out2_b, conv2_w);

    final_kernel<<<1, DMODEL>>>(H2, norm_g, norm_b, fc2_w, fc2_b, (float*)d_out, out_size);
}

// round 3
// speedup vs baseline: 2.2716x; 2.2716x over previous
#include <cuda_runtime.h>
#include <math.h>
#include <stdint.h>

// ---------------------------------------------------------------------------
// Problem constants
// ---------------------------------------------------------------------------
#define NTOK   8192
#define INDIM  1024
#define DMODEL 512
#define NHEADS 8
#define DH     64
#define MLAND  256
#define LWIN   33
#define NP     8448          // padded attention length
#define NHTOK  8282          // tokens incl cls
#define PADF   166
#define HSQ    91
#define NFEAT  8281
#define NWRAP  89
#define EPSLN  1e-5f

#define FLAG_RELU 1
#define FLAG_ACC  2

// ---------------------------------------------------------------------------
// Scratch (device globals)
// ---------------------------------------------------------------------------
__device__ float g_H  [NHTOK * DMODEL];
__device__ float g_H2 [NHTOK * DMODEL];
__device__ float g_XP [NP * DMODEL];
__device__ float g_QKV[NP * 3 * DMODEL];
__device__ float g_KT [NHEADS * DH * NP];        // K transposed per head [h][d][n]
__device__ float g_QL [NHEADS * MLAND * DH];
__device__ float g_KL [NHEADS * MLAND * DH];
__device__ float g_KLT[NHEADS * DH * MLAND];     // KL transposed [h][d][m]
__device__ float g_A2 [NHEADS * MLAND * MLAND];
__device__ float g_Z0 [NHEADS * MLAND * MLAND];
__device__ float g_Z1 [NHEADS * MLAND * MLAND];
__device__ float g_W1 [NHEADS * MLAND * MLAND];
__device__ float g_W2 [NHEADS * MLAND * MLAND];
__device__ float g_W3 [NHEADS * MLAND * MLAND];
__device__ float g_PS [NHEADS];
__device__ float g_A3V[NHEADS * MLAND * DH];
__device__ float g_Bm [NHEADS * MLAND * DH];
__device__ float g_O  [NP * DMODEL];

// ---------------------------------------------------------------------------
// Generic SGEMM: C = op(A@B)  128x128 tile, 8x8/thread
// ---------------------------------------------------------------------------
__global__ void sgemm_kernel(const float* __restrict__ A, const float* __restrict__ B,
                             float* __restrict__ C, const float* __restrict__ bias,
                             int Mn, int Nn, int Kn, int flags, int scale_cols, float scale)
{
    __shared__ float As[16][128];
    __shared__ float Bs[16][128];
    const int bm = blockIdx.y * 128;
    const int bn = blockIdx.x * 128;
    const int tid = threadIdx.x;
    const int tx = tid & 15, ty = tid >> 4;
    const int row0 = ty * 8, col0 = tx * 8;
    float acc[8][8];
#pragma unroll
    for (int i = 0; i < 8; i++)
#pragma unroll
        for (int j = 0; j < 8; j++) acc[i][j] = 0.f;

    for (int k0 = 0; k0 < Kn; k0 += 16) {
#pragma unroll
        for (int i = 0; i < 2; i++) {
            int lin = tid + i * 256;
            int ar = lin >> 2;
            int ac = (lin & 3) << 2;
            float4 v = make_float4(0.f, 0.f, 0.f, 0.f);
            if (bm + ar < Mn)
                v = *reinterpret_cast<const float4*>(A + (size_t)(bm + ar) * Kn + k0 + ac);
            As[ac + 0][ar] = v.x; As[ac + 1][ar] = v.y;
            As[ac + 2][ar] = v.z; As[ac + 3][ar] = v.w;
        }
#pragma unroll
        for (int i = 0; i < 2; i++) {
            int lin = tid + i * 256;
            int br = lin >> 5;
            int bc = (lin & 31) << 2;
            float4 v = *reinterpret_cast<const float4*>(B + (size_t)(k0 + br) * Nn + bn + bc);
            *reinterpret_cast<float4*>(&Bs[br][bc]) = v;
        }
        __syncthreads();
#pragma unroll
        for (int k = 0; k < 16; k++) {
            float a[8], b[8];
            *reinterpret_cast<float4*>(a)     = *reinterpret_cast<const float4*>(&As[k][row0]);
            *reinterpret_cast<float4*>(a + 4) = *reinterpret_cast<const float4*>(&As[k][row0 + 4]);
            *reinterpret_cast<float4*>(b)     = *reinterpret_cast<const float4*>(&Bs[k][col0]);
            *reinterpret_cast<float4*>(b + 4) = *reinterpret_cast<const float4*>(&Bs[k][col0 + 4]);
#pragma unroll
            for (int i = 0; i < 8; i++)
#pragma unroll
                for (int j = 0; j < 8; j++) acc[i][j] += a[i] * b[j];
        }
        __syncthreads();
    }
    const bool relu = (flags & FLAG_RELU) != 0;
    const bool accu = (flags & FLAG_ACC) != 0;
#pragma unroll
    for (int i = 0; i < 8; i++) {
        int r = bm + row0 + i;
        if (r >= Mn) continue;
#pragma unroll
        for (int j = 0; j < 8; j++) {
            int cidx = bn + col0 + j;
            float v = acc[i][j];
            if (cidx < scale_cols) v *= scale;
            if (bias) v += bias[cidx];
            if (relu) v = fmaxf(v, 0.f);
            size_t o = (size_t)r * Nn + cidx;
            if (accu) C[o] += v; else C[o] = v;
        }
    }
}

// ---------------------------------------------------------------------------
// Assemble h rows: cls + wrap
// ---------------------------------------------------------------------------
__global__ void assemble_kernel(const float* __restrict__ cls, float* __restrict__ H)
{
    int j = blockIdx.x;
    int c = threadIdx.x;
    if (j == 0) H[c] = cls[c];
    else        H[(size_t)(NTOK + j) * DMODEL + c] = H[(size_t)j * DMODEL + c];
}

// ---------------------------------------------------------------------------
// LayerNorm into padded XP
// ---------------------------------------------------------------------------
__global__ void ln_pad_kernel(const float* __restrict__ Hin, float* __restrict__ XP,
                              const float* __restrict__ g, const float* __restrict__ b)
{
    int row = blockIdx.x;
    int tid = threadIdx.x;
    if (row < PADF) {
        XP[(size_t)row * DMODEL + tid] = 0.f;
        XP[(size_t)row * DMODEL + tid + 256] = 0.f;
        return;
    }
    const float* x = Hin + (size_t)(row - PADF) * DMODEL;
    float v0 = x[tid], v1 = x[tid + 256];
    __shared__ float s1[256], s2[256];
    s1[tid] = v0 + v1;
    s2[tid] = v0 * v0 + v1 * v1;
    __syncthreads();
    for (int o = 128; o > 0; o >>= 1) {
        if (tid < o) { s1[tid] += s1[tid + o]; s2[tid] += s2[tid + o]; }
        __syncthreads();
    }
    float mean = s1[0] * (1.f / DMODEL);
    float var  = s2[0] * (1.f / DMODEL) - mean * mean;
    float rs = rsqrtf(var + EPSLN);
    XP[(size_t)row * DMODEL + tid]       = (v0 - mean) * rs * g[tid] + b[tid];
    XP[(size_t)row * DMODEL + tid + 256] = (v1 - mean) * rs * g[tid + 256] + b[tid + 256];
}

// ---------------------------------------------------------------------------
// Transpose K part of QKV into g_KT[h][d][n]
// ---------------------------------------------------------------------------
__global__ void ktr_kernel(const float* __restrict__ QKV, float* __restrict__ KT)
{
    __shared__ float tl[64][65];
    int h = blockIdx.y;
    int n0 = blockIdx.x * 64;
    int t = threadIdx.x;
    for (int lin = t; lin < 4096; lin += 256) {
        int r = lin >> 6, i = lin & 63;
        tl[r][i] = QKV[(size_t)(n0 + r) * (3 * DMODEL) + DMODEL + h * DH + i];
    }
    __syncthreads();
    for (int lin = t; lin < 4096; lin += 256) {
        int i = lin >> 6, c = lin & 63;
        KT[(size_t)(h * DH + i) * NP + n0 + c] = tl[c][i];
    }
}

// ---------------------------------------------------------------------------
// Landmarks (means of 33-groups); also writes KL transposed
// ---------------------------------------------------------------------------
__global__ void landmarks_kernel(const float* __restrict__ QKV,
                                 float* __restrict__ QL, float* __restrict__ KL,
                                 float* __restrict__ KLT)
{
    int hm = blockIdx.x;
    int h = hm >> 8, m = hm & 255;
    int tid = threadIdx.x;
    int d = tid & 63;
    int off = (tid < 64) ? 0 : DMODEL;
    size_t base = (size_t)(m * LWIN) * (3 * DMODEL) + off + h * DH + d;
    float s = 0.f;
#pragma unroll
    for (int j = 0; j < LWIN; j++) s += QKV[base + (size_t)j * (3 * DMODEL)];
    s *= (1.0f / LWIN);
    if (tid < 64) {
        QL[(size_t)(h * MLAND + m) * DH + d] = s;
    } else {
        KL[(size_t)(h * MLAND + m) * DH + d] = s;
        KLT[(size_t)h * DH * MLAND + (size_t)d * MLAND + m] = s;
    }
}

// ---------------------------------------------------------------------------
// a2 = softmax(q_l @ k_l^T)
// ---------------------------------------------------------------------------
__global__ void a2_kernel(const float* __restrict__ QL, const float* __restrict__ KL,
                          float* __restrict__ A2)
{
    int m = blockIdx.x, h = blockIdx.y;
    int tid = threadIdx.x;
    __shared__ float q[64];
    __shared__ float red[256];
    if (tid < 64) q[tid] = QL[(size_t)(h * MLAND + m) * DH + tid];
    __syncthreads();
    const float* kr = KL + (size_t)(h * MLAND + tid) * DH;
    float s = 0.f;
#pragma unroll
    for (int i = 0; i < 16; i++) {
        float4 kv = reinterpret_cast<const float4*>(kr)[i];
        float4 qv = reinterpret_cast<const float4*>(q)[i];
        s += kv.x * qv.x + kv.y * qv.y + kv.z * qv.z + kv.w * qv.w;
    }
    red[tid] = s; __syncthreads();
    for (int o = 128; o > 0; o >>= 1) {
        if (tid < o) red[tid] = fmaxf(red[tid], red[tid + o]);
        __syncthreads();
    }
    float mx = red[0]; __syncthreads();
    float e = __expf(s - mx);
    red[tid] = e; __syncthreads();
    for (int o = 128; o > 0; o >>= 1) {
        if (tid < o) red[tid] += red[tid + o];
        __syncthreads();
    }
    float sm = red[0];
    A2[(size_t)(h * MLAND + m) * MLAND + tid] = e / sm;
}

// ---------------------------------------------------------------------------
// pinv scale: 1 / (max rowsum * max colsum) per head
// ---------------------------------------------------------------------------
__global__ void pinv_scale_kernel(const float* __restrict__ A2, float* __restrict__ PS)
{
    int h = blockIdx.x;
    int t = threadIdx.x;
    int w = t >> 5, lane = t & 31;
    const float* Ah = A2 + (size_t)h * 65536;
    __shared__ float rs[256];
    __shared__ float cs2[256];
    for (int r = w; r < 256; r += 8) {
        float s = 0.f;
        for (int j = lane; j < 256; j += 32) s += fabsf(Ah[r * 256 + j]);
        for (int o = 16; o > 0; o >>= 1) s += __shfl_xor_sync(0xffffffffu, s, o);
        if (lane == 0) rs[r] = s;
    }
    float cs = 0.f;
    for (int i = 0; i < 256; i++) cs += fabsf(Ah[i * 256 + t]);
    cs2[t] = cs;
    __syncthreads();
    for (int o = 128; o > 0; o >>= 1) {
        if (t < o) { rs[t] = fmaxf(rs[t], rs[t + o]); cs2[t] = fmaxf(cs2[t], cs2[t + o]); }
        __syncthreads();
    }
    if (t == 0) PS[h] = 1.0f / (rs[0] * cs2[0]);
}

// ---------------------------------------------------------------------------
// pinv transpose-scale: Z0 = A2^T * scale
// ---------------------------------------------------------------------------
__global__ void pinv_tr_kernel(const float* __restrict__ A2, const float* __restrict__ PS,
                               float* __restrict__ Z0)
{
    __shared__ float tl[64][65];
    int h = blockIdx.y;
    int seg = blockIdx.x;
    int bi = (seg >> 2) * 64, bj = (seg & 3) * 64;
    int t = threadIdx.x;
    float inv = PS[h];
    const float* Ah = A2 + (size_t)h * 65536;
    float* Zh = Z0 + (size_t)h * 65536;
    for (int lin = t; lin < 4096; lin += 256) {
        int r = lin >> 6, c = lin & 63;
        tl[r][c] = Ah[(size_t)(bi + r) * 256 + bj + c];
    }
    __syncthreads();
    for (int lin = t; lin < 4096; lin += 256) {
        int r = lin >> 6, c = lin & 63;
        Zh[(size_t)(bj + r) * 256 + bi + c] = tl[c][r] * inv;
    }
}

// ---------------------------------------------------------------------------
// Batched 256^3 matmul: C = alpha*(A@B) + gamma*A (pinv chain)
// ---------------------------------------------------------------------------
__global__ void nk256_kernel(const float* __restrict__ A, const float* __restrict__ B,
                             float* __restrict__ C, float alpha, float gamma)
{
    const float* Ah = A + (size_t)blockIdx.z * 65536;
    const float* Bh = B + (size_t)blockIdx.z * 65536;
    float* Ch = C + (size_t)blockIdx.z * 65536;
    __shared__ float As[16][64];
    __shared__ float Bs[16][64];
    const int bm = blockIdx.y * 64;
    const int bn = blockIdx.x * 64;
    const int tid = threadIdx.x;
    const int tx = tid & 15, ty = tid >> 4;
    const int row0 = ty * 4, col0 = tx * 4;
    float acc[4][4];
#pragma unroll
    for (int i = 0; i < 4; i++)
#pragma unroll
        for (int j = 0; j < 4; j++) acc[i][j] = 0.f;

    for (int k0 = 0; k0 < 256; k0 += 16) {
        {
            int ar = tid >> 2;
            int ac = (tid & 3) << 2;
            float4 v = *reinterpret_cast<const float4*>(Ah + (size_t)(bm + ar) * 256 + k0 + ac);
            As[ac + 0][ar] = v.x; As[ac + 1][ar] = v.y;
            As[ac + 2][ar] = v.z; As[ac + 3][ar] = v.w;
        }
        {
            int br = tid >> 4;
            int bc = (tid & 15) << 2;
            float4 v = *reinterpret_cast<const float4*>(Bh + (size_t)(k0 + br) * 256 + bn + bc);
            *reinterpret_cast<float4*>(&Bs[br][bc]) = v;
        }
        __syncthreads();
#pragma unroll
        for (int k = 0; k < 16; k++) {
            float a[4], b[4];
            *reinterpret_cast<float4*>(a) = *reinterpret_cast<const float4*>(&As[k][row0]);
            *reinterpret_cast<float4*>(b) = *reinterpret_cast<const float4*>(&Bs[k][col0]);
#pragma unroll
            for (int i = 0; i < 4; i++)
#pragma unroll
                for (int j = 0; j < 4; j++) acc[i][j] += a[i] * b[j];
        }
        __syncthreads();
    }
#pragma unroll
    for (int i = 0; i < 4; i++)
#pragma unroll
        for (int j = 0; j < 4; j++) {
            size_t o = (size_t)(bm + row0 + i) * 256 + bn + col0 + j;
            Ch[o] = alpha * acc[i][j] + gamma * Ah[o];
        }
}

// ---------------------------------------------------------------------------
// Fused a3: online-softmax(q_l @ k^T) @ v  -> A3V  (flash style)
// ---------------------------------------------------------------------------
#define A3_KT   0
#define A3_VS   (64 * 264)                 // 16896
#define A3_QS   (A3_VS + 256 * 64)         // 33280
#define A3_PS   (A3_QS + 16 * 64)          // 34304
#define A3_M    (A3_PS + 16 * 264)         // 38528
#define A3_S    (A3_M + 16)
#define A3_SC   (A3_S + 16)
#define A3_RED  (A3_SC + 16)
#define A3_TOT  (A3_RED + 64)              // 38640 floats

__global__ void a3_fused_kernel(const float* __restrict__ QKV, const float* __restrict__ KT,
                                const float* __restrict__ QL, float* __restrict__ A3V)
{
    extern __shared__ float sm[];
    float* Kt  = sm + A3_KT;
    float* Vs  = sm + A3_VS;
    float* Qs  = sm + A3_QS;
    float* Ps  = sm + A3_PS;
    float* Mr  = sm + A3_M;
    float* Sr  = sm + A3_S;
    float* Scl = sm + A3_SC;
    float* Red = sm + A3_RED;

    int h  = blockIdx.y;
    int m0 = blockIdx.x * 16;
    int t  = threadIdx.x;
    int lane = t & 31, w = t >> 5;

    int la = t >> 6, lc = t & 63;
    int gc = t >> 6, pr = (t >> 4) & 3, td = t & 15;

    for (int lin = t; lin < 16 * 64; lin += 256) {
        int r = lin >> 6, i = lin & 63;
        Qs[r * 64 + i] = QL[(size_t)(h * MLAND + m0 + r) * DH + i];
    }
    if (t < 16) { Mr[t] = -1e30f; Sr[t] = 0.f; }

    float accv[4][4];
#pragma unroll
    for (int i = 0; i < 4; i++)
#pragma unroll
        for (int j = 0; j < 4; j++) accv[i][j] = 0.f;

    for (int n0 = 0; n0 < NP; n0 += 256) {
        for (int lin = t; lin < 4096; lin += 256) {
            int i = lin >> 6, c4 = (lin & 63) << 2;
            *reinterpret_cast<float4*>(&Kt[i * 264 + c4]) =
                *reinterpret_cast<const float4*>(&KT[(size_t)(h * DH + i) * NP + n0 + c4]);
        }
        for (int lin = t; lin < 4096; lin += 256) {
            int r = lin >> 4, c4 = (lin & 15) << 2;
            *reinterpret_cast<float4*>(&Vs[r * 64 + c4]) =
                *reinterpret_cast<const float4*>(&QKV[(size_t)(n0 + r) * (3 * DMODEL) + 2 * DMODEL + h * DH + c4]);
        }
        __syncthreads();

        float lacc[4][4];
#pragma unroll
        for (int i = 0; i < 4; i++)
#pragma unroll
            for (int j = 0; j < 4; j++) lacc[i][j] = 0.f;
#pragma unroll
        for (int i = 0; i < 64; i += 4) {
            float4 aq[4];
#pragma unroll
            for (int rr = 0; rr < 4; rr++)
                aq[rr] = *reinterpret_cast<const float4*>(&Qs[(la * 4 + rr) * 64 + i]);
#pragma unroll
            for (int ii = 0; ii < 4; ii++) {
                float4 b = *reinterpret_cast<const float4*>(&Kt[(i + ii) * 264 + (lc << 2)]);
#pragma unroll
                for (int rr = 0; rr < 4; rr++) {
                    float av = reinterpret_cast<const float*>(&aq[rr])[ii];
                    lacc[rr][0] += av * b.x; lacc[rr][1] += av * b.y;
                    lacc[rr][2] += av * b.z; lacc[rr][3] += av * b.w;
                }
            }
        }
        float pm[4];
#pragma unroll
        for (int rr = 0; rr < 4; rr++)
            pm[rr] = fmaxf(fmaxf(lacc[rr][0], lacc[rr][1]), fmaxf(lacc[rr][2], lacc[rr][3]));
        for (int o = 16; o > 0; o >>= 1)
#pragma unroll
            for (int rr = 0; rr < 4; rr++)
                pm[rr] = fmaxf(pm[rr], __shfl_xor_sync(0xffffffffu, pm[rr], o));
        if (lane == 0)
#pragma unroll
            for (int rr = 0; rr < 4; rr++) Red[w * 4 + rr] = pm[rr];
        __syncthreads();
        if (t < 16) {
            int wb = (t >> 2) * 2;
            float tmax = fmaxf(Red[wb * 4 + (t & 3)], Red[(wb + 1) * 4 + (t & 3)]);
            float oldM = Mr[t], newM = fmaxf(oldM, tmax);
            Scl[t] = __expf(oldM - newM);
            Mr[t] = newM;
        }
        __syncthreads();
        float psum[4];
#pragma unroll
        for (int rr = 0; rr < 4; rr++) {
            float nm = Mr[la * 4 + rr];
            float p0 = __expf(lacc[rr][0] - nm);
            float p1 = __expf(lacc[rr][1] - nm);
            float p2 = __expf(lacc[rr][2] - nm);
            float p3 = __expf(lacc[rr][3] - nm);
            *reinterpret_cast<float4*>(&Ps[(la * 4 + rr) * 264 + (lc << 2)]) =
                make_float4(p0, p1, p2, p3);
            psum[rr] = p0 + p1 + p2 + p3;
        }
        for (int o = 16; o > 0; o >>= 1)
#pragma unroll
            for (int rr = 0; rr < 4; rr++)
                psum[rr] += __shfl_xor_sync(0xffffffffu, psum[rr], o);
        if (lane == 0)
#pragma unroll
            for (int rr = 0; rr < 4; rr++) Red[w * 4 + rr] = psum[rr];
        __syncthreads();
        if (t < 16) {
            int wb = (t >> 2) * 2;
            float ts = Red[wb * 4 + (t & 3)] + Red[(wb + 1) * 4 + (t & 3)];
            Sr[t] = Sr[t] * Scl[t] + ts;
        }
#pragma unroll
        for (int rr = 0; rr < 4; rr++) {
            float sc = Scl[pr * 4 + rr];
            accv[rr][0] *= sc; accv[rr][1] *= sc; accv[rr][2] *= sc; accv[rr][3] *= sc;
        }
#pragma unroll 4
        for (int c = 0; c < 64; c++) {
            int cg = gc * 64 + c;
            float4 v = *reinterpret_cast<const float4*>(&Vs[cg * 64 + (td << 2)]);
#pragma unroll
            for (int rr = 0; rr < 4; rr++) {
                float p = Ps[(pr * 4 + rr) * 264 + cg];
                accv[rr][0] += p * v.x; accv[rr][1] += p * v.y;
                accv[rr][2] += p * v.z; accv[rr][3] += p * v.w;
            }
        }
        __syncthreads();
    }
#pragma unroll
    for (int rr = 0; rr < 4; rr++)
        *reinterpret_cast<float4*>(&sm[gc * 1024 + (pr * 4 + rr) * 64 + (td << 2)]) =
            make_float4(accv[rr][0], accv[rr][1], accv[rr][2], accv[rr][3]);
    __syncthreads();
    for (int lin = t; lin < 1024; lin += 256) {
        int row = lin >> 6, d = lin & 63;
        float v = sm[row * 64 + d] + sm[1024 + row * 64 + d] +
                  sm[2048 + row * 64 + d] + sm[3072 + row * 64 + d];
        A3V[(size_t)(h * MLAND + m0 + row) * DH + d] = v / Sr[row];
    }
}

// ---------------------------------------------------------------------------
// Bm = pinv(a2) @ a3v
// ---------------------------------------------------------------------------
__global__ void bmat_kernel(const float* __restrict__ Z, const float* __restrict__ A3V,
                            float* __restrict__ Bm)
{
    int h = blockIdx.y;
    int m0 = blockIdx.x * 4;
    __shared__ float zs[4][256];
    int tid = threadIdx.x;
    int r = tid >> 6, d = tid & 63;
    for (int lin = tid; lin < 1024; lin += 256) {
        int rr = lin >> 8, k = lin & 255;
        zs[rr][k] = Z[(size_t)h * 65536 + (size_t)(m0 + rr) * 256 + k];
    }
    __syncthreads();
    float acc = 0.f;
    for (int k = 0; k < 256; k++)
        acc += zs[r][k] * A3V[(size_t)(h * MLAND + k) * DH + d];
    Bm[(size_t)(h * MLAND + m0 + r) * DH + d] = acc;
}

// ---------------------------------------------------------------------------
// a1 @ Bm as two tiled GEMMs with warp-shuffle softmax
// ---------------------------------------------------------------------------
#define A1_QS   0                           // [64][65]
#define A1_KLT  (64 * 65)                   // [64][260]
#define A1_PS   (A1_KLT + 64 * 260)         // [64][260]
#define A1_BMS  (A1_PS + 64 * 260)          // [256][64]
#define A1_TOT  (A1_BMS + 256 * 64)         // 53824 floats

__global__ void a1out_kernel(const float* __restrict__ QKV, const float* __restrict__ KLT,
                             const float* __restrict__ Bm, float* __restrict__ O)
{
    extern __shared__ float sm[];
    float* Qs  = sm + A1_QS;
    float* KLt = sm + A1_KLT;
    float* Ps  = sm + A1_PS;
    float* Bms = sm + A1_BMS;

    int h = blockIdx.y;
    int row0 = blockIdx.x * 64;
    int t = threadIdx.x;

    for (int lin = t; lin < 4096; lin += 256) {
        int r = lin >> 6, i = lin & 63;
        Qs[r * 65 + i] = QKV[(size_t)(row0 + r) * (3 * DMODEL) + h * DH + i];
    }
    for (int lin = t; lin < 16384; lin += 256) {
        int i = lin >> 8, m = lin & 255;
        KLt[i * 260 + m] = KLT[(size_t)h * DH * MLAND + lin];
    }
    for (int lin = t; lin < 16384; lin += 256) {
        Bms[lin] = Bm[(size_t)h * MLAND * DH + lin];
    }
    __syncthreads();

    int ty = t >> 5, tx = t & 31;
    float acc[8][8];
#pragma unroll
    for (int i = 0; i < 8; i++)
#pragma unroll
        for (int j = 0; j < 8; j++) acc[i][j] = 0.f;
    for (int i = 0; i < 64; i++) {
        float4 b0 = *reinterpret_cast<const float4*>(&KLt[i * 260 + tx * 8]);
        float4 b1 = *reinterpret_cast<const float4*>(&KLt[i * 260 + tx * 8 + 4]);
#pragma unroll
        for (int j = 0; j < 8; j++) {
            float a = Qs[(ty * 8 + j) * 65 + i];
            acc[j][0] += a * b0.x; acc[j][1] += a * b0.y;
            acc[j][2] += a * b0.z; acc[j][3] += a * b0.w;
            acc[j][4] += a * b1.x; acc[j][5] += a * b1.y;
            acc[j][6] += a * b1.z; acc[j][7] += a * b1.w;
        }
    }
#pragma unroll
    for (int j = 0; j < 8; j++) {
        float m = acc[j][0];
#pragma unroll
        for (int k = 1; k < 8; k++) m = fmaxf(m, acc[j][k]);
        for (int o = 16; o > 0; o >>= 1) m = fmaxf(m, __shfl_xor_sync(0xffffffffu, m, o));
        float s = 0.f;
#pragma unroll
        for (int k = 0; k < 8; k++) { acc[j][k] = __expf(acc[j][k] - m); s += acc[j][k]; }
        for (int o = 16; o > 0; o >>= 1) s += __shfl_xor_sync(0xffffffffu, s, o);
        float inv = 1.0f / s;
        *reinterpret_cast<float4*>(&Ps[(ty * 8 + j) * 260 + tx * 8]) =
            make_float4(acc[j][0] * inv, acc[j][1] * inv, acc[j][2] * inv, acc[j][3] * inv);
        *reinterpret_cast<float4*>(&Ps[(ty * 8 + j) * 260 + tx * 8 + 4]) =
            make_float4(acc[j][4] * inv, acc[j][5] * inv, acc[j][6] * inv, acc[j][7] * inv);
    }
    __syncthreads();

    int rr = t >> 4, cc = t & 15;
    float o4[4][4];
#pragma unroll
    for (int i = 0; i < 4; i++)
#pragma unroll
        for (int j = 0; j < 4; j++) o4[i][j] = 0.f;
    for (int c = 0; c < 256; c++) {
        float4 b = *reinterpret_cast<const float4*>(&Bms[c * 64 + cc * 4]);
#pragma unroll
        for (int k = 0; k < 4; k++) {
            float a = Ps[(rr * 4 + k) * 260 + c];
            o4[k][0] += a * b.x; o4[k][1] += a * b.y;
            o4[k][2] += a * b.z; o4[k][3] += a * b.w;
        }
    }
#pragma unroll
    for (int k = 0; k < 4; k++)
        *reinterpret_cast<float4*>(&O[(size_t)(row0 + rr * 4 + k) * DMODEL + h * DH + cc * 4]) =
            make_float4(o4[k][0], o4[k][1], o4[k][2], o4[k][3]);
}

// ---------------------------------------------------------------------------
// Depthwise seq-conv (k=33) on v, tiled in smem; adds into O
// ---------------------------------------------------------------------------
__global__ void conv_tile_kernel(const float* __restrict__ QKV, const float* __restrict__ W,
                                 float* __restrict__ O)
{
    __shared__ float vs[160 * 64];
    __shared__ float ws[33];
    int h = blockIdx.y;
    int n0 = blockIdx.x * 128;
    int t = threadIdx.x;
    if (t < 33) ws[t] = W[h * LWIN + t];
    for (int lin = t; lin < 160 * 64; lin += 256) {
        int r = lin >> 6, c = lin & 63;
        int n = n0 + r - 16;
        vs[lin] = (n >= 0 && n < NP)
                    ? QKV[(size_t)n * (3 * DMODEL) + 2 * DMODEL + h * DH + c] : 0.f;
    }
    __syncthreads();
    int c = t & 63, rg = t >> 6;
    for (int q = 0; q < 32; q++) {
        int r = rg * 32 + q;
        float acc = 0.f;
#pragma unroll
        for (int k = 0; k < LWIN; k++) acc += ws[k] * vs[(r + k) * 64 + c];
        O[(size_t)(n0 + r) * DMODEL + h * DH + c] += acc;
    }
}

// ---------------------------------------------------------------------------
// PPEG tiled: 8x8 spatial x 64 channels per block, 14x14 halo + weights in smem
// ---------------------------------------------------------------------------
#define PPEG_TILE (14 * 14 * 64)            // 12544
#define PPEG_W7   PPEG_TILE
#define PPEG_W5   (PPEG_W7 + 64 * 49)
#define PPEG_W3   (PPEG_W5 + 64 * 25)
#define PPEG_TOT  (PPEG_W3 + 64 * 9)        // 17856 floats

__global__ void ppeg_tile_kernel(const float* __restrict__ Hin, float* __restrict__ Hout,
                                 const float* __restrict__ w7, const float* __restrict__ b7,
                                 const float* __restrict__ w5, const float* __restrict__ b5,
                                 const float* __restrict__ w3, const float* __restrict__ b3)
{
    extern __shared__ float sm[];
    float* tile = sm;
    float* ws7 = sm + PPEG_W7;
    float* ws5 = sm + PPEG_W5;
    float* ws3 = sm + PPEG_W3;

    int ti = blockIdx.x;
    int ty0 = (ti / 12) * 8, tx0 = (ti % 12) * 8;
    int cg = blockIdx.y * 64;
    int t = threadIdx.x;

    for (int lin = t; lin < PPEG_TILE; lin += 256) {
        int p = lin >> 6, c = lin & 63;
        int gy = ty0 + p / 14 - 3;
        int gx = tx0 + p % 14 - 3;
        float v = 0.f;
        if ((unsigned)gy < (unsigned)HSQ && (unsigned)gx < (unsigned)HSQ)
            v = Hin[(size_t)(1 + gy * HSQ + gx) * DMODEL + cg + c];
        tile[lin] = v;
    }
    for (int lin = t; lin < 64 * 49; lin += 256) ws7[lin] = w7[(size_t)cg * 49 + lin];
    for (int lin = t; lin < 64 * 25; lin += 256) ws5[lin] = w5[(size_t)cg * 25 + lin];
    for (int lin = t; lin < 64 * 9;  lin += 256) ws3[lin] = w3[(size_t)cg * 9 + lin];
    __syncthreads();

    int c = t & 63, pg = t >> 6;
    float bsum = b7[cg + c] + b5[cg + c] + b3[cg + c];
    for (int q = 0; q < 16; q++) {
        int p = pg * 16 + q;
        int oy = p >> 3, ox = p & 7;
        int gy = ty0 + oy, gx = tx0 + ox;
        if (gy >= HSQ || gx >= HSQ) continue;
        float acc = tile[((oy + 3) * 14 + ox + 3) * 64 + c] + bsum;
#pragma unroll
        for (int a = 0; a < 7; a++)
#pragma unroll
            for (int bq = 0; bq < 7; bq++)
                acc += ws7[c * 49 + a * 7 + bq] * tile[((oy + a) * 14 + ox + bq) * 64 + c];
#pragma unroll
        for (int a = 0; a < 5; a++)
#pragma unroll
            for (int bq = 0; bq < 5; bq++)
                acc += ws5[c * 25 + a * 5 + bq] * tile[((oy + a + 1) * 14 + ox + bq + 1) * 64 + c];
#pragma unroll
        for (int a = 0; a < 3; a++)
#pragma unroll
            for (int bq = 0; bq < 3; bq++)
                acc += ws3[c * 9 + a * 3 + bq] * tile[((oy + a + 2) * 14 + ox + bq + 2) * 64 + c];
        Hout[(size_t)(1 + gy * HSQ + gx) * DMODEL + cg + c] = acc;
    }
}

__global__ void copy_row0_kernel(const float* __restrict__ Hin, float* __restrict__ Hout)
{
    Hout[threadIdx.x] = Hin[threadIdx.x];
}

// ---------------------------------------------------------------------------
// Final head
// ---------------------------------------------------------------------------
__global__ void final_kernel(const float* __restrict__ H, const float* __restrict__ g,
                             const float* __restrict__ b, const float* __restrict__ w,
                             const float* __restrict__ bias2, float* __restrict__ out,
                             int out_size)
{
    int c = threadIdx.x;
    __shared__ float s1[512], s2[512];
    float x = H[c];
    s1[c] = x; s2[c] = x * x;
    __syncthreads();
    for (int o = 256; o > 0; o >>= 1) {
        if (c < o) { s1[c] += s1[c + o]; s2[c] += s2[c + o]; }
        __syncthreads();
    }
    float mean = s1[0] * (1.f / DMODEL);
    float var  = s2[0] * (1.f / DMODEL) - mean * mean;
    float e = (x - mean) * rsqrtf(var + EPSLN) * g[c] + b[c];
    __syncthreads();
    s1[c] = e * w[c * 2 + 0];
    s2[c] = e * w[c * 2 + 1];
    __syncthreads();
    for (int o = 256; o > 0; o >>= 1) {
        if (c < o) { s1[c] += s1[c + o]; s2[c] += s2[c + o]; }
        __syncthreads();
    }
    float l0 = s1[0] + bias2[0];
    float l1 = s2[0] + bias2[1];
    if (c == 0) {
        float m = fmaxf(l0, l1);
        float e0 = expf(l0 - m), e1 = expf(l1 - m);
        float ss = e0 + e1;
        if (out_size > 0) out[0] = l0;
        if (out_size > 1) out[1] = l1;
        if (out_size > 2) out[2] = e0 / ss;
        if (out_size > 3) out[3] = e1 / ss;
        if (out_size > 4) out[4] = (l1 > l0) ? 1.0f : 0.0f;
    }
    if (5 + c < out_size) out[5 + c] = e;
}

// ---------------------------------------------------------------------------
// Host orchestration
// ---------------------------------------------------------------------------
static float* symaddr(const void* sym)
{
    void* p = nullptr;
    cudaGetSymbolAddress(&p, sym);
    return (float*)p;
}

extern "C" void kernel_launch(void* const* d_in, const int* in_sizes, int n_in,
                              void* d_out, int out_size)
{
    const float* x       = (const float*)d_in[0];
    const float* fc1_w   = (const float*)d_in[1];
    const float* fc1_b   = (const float*)d_in[2];
    const float* cls     = (const float*)d_in[3];
    const float* ln1_g   = (const float*)d_in[4];
    const float* ln1_b   = (const float*)d_in[5];
    const float* qkv1_w  = (const float*)d_in[6];
    const float* out1_w  = (const float*)d_in[7];
    const float* out1_b  = (const float*)d_in[8];
    const float* conv1_w = (const float*)d_in[9];
    const float* ln2_g   = (const float*)d_in[10];
    const float* ln2_b   = (const float*)d_in[11];
    const float* qkv2_w  = (const float*)d_in[12];
    const float* out2_w  = (const float*)d_in[13];
    const float* out2_b  = (const float*)d_in[14];
    const float* conv2_w = (const float*)d_in[15];
    const float* pg7_w   = (const float*)d_in[16];
    const float* pg7_b   = (const float*)d_in[17];
    const float* pg5_w   = (const float*)d_in[18];
    const float* pg5_b   = (const float*)d_in[19];
    const float* pg3_w   = (const float*)d_in[20];
    const float* pg3_b   = (const float*)d_in[21];
    const float* norm_g  = (const float*)d_in[22];
    const float* norm_b  = (const float*)d_in[23];
    const float* fc2_w   = (const float*)d_in[24];
    const float* fc2_b   = (const float*)d_in[25];

    float* H   = symaddr(g_H);
    float* H2  = symaddr(g_H2);
    float* XP  = symaddr(g_XP);
    float* QKV = symaddr(g_QKV);
    float* KT  = symaddr(g_KT);
    float* QL  = symaddr(g_QL);
    float* KL  = symaddr(g_KL);
    float* KLT = symaddr(g_KLT);
    float* A2  = symaddr(g_A2);
    float* Z0  = symaddr(g_Z0);
    float* Z1  = symaddr(g_Z1);
    float* W1  = symaddr(g_W1);
    float* W2  = symaddr(g_W2);
    float* W3  = symaddr(g_W3);
    float* PS  = symaddr(g_PS);
    float* A3V = symaddr(g_A3V);
    float* Bm  = symaddr(g_Bm);
    float* O   = symaddr(g_O);

    const int A3_SMEM   = A3_TOT * 4;
    const int A1_SMEM   = A1_TOT * 4;
    const int PPEG_SMEM = PPEG_TOT * 4;
    cudaFuncSetAttribute(a3_fused_kernel, cudaFuncAttributeMaxDynamicSharedMemorySize, A3_SMEM);
    cudaFuncSetAttribute(a1out_kernel,    cudaFuncAttributeMaxDynamicSharedMemorySize, A1_SMEM);
    cudaFuncSetAttribute(ppeg_tile_kernel, cudaFuncAttributeMaxDynamicSharedMemorySize, PPEG_SMEM);

    sgemm_kernel<<<dim3(DMODEL / 128, NTOK / 128), 256>>>(
        x, fc1_w, H + DMODEL, fc1_b, NTOK, DMODEL, INDIM, FLAG_RELU, 0, 1.f);
    assemble_kernel<<<NWRAP + 1, DMODEL>>>(cls, H);

    auto attn = [&](float* Hbuf, const float* lng, const float* lnb, const float* qkvw,
                    const float* outw, const float* outb, const float* convw) {
        ln_pad_kernel<<<NP, 256>>>(Hbuf, XP, lng, lnb);
        sgemm_kernel<<<dim3(3 * DMODEL / 128, NP / 128), 256>>>(
            XP, qkvw, QKV, nullptr, NP, 3 * DMODEL, DMODEL, 0, DMODEL, 0.125f);
        ktr_kernel<<<dim3(NP / 64, NHEADS), 256>>>(QKV, KT);
        landmarks_kernel<<<NHEADS * MLAND, 128>>>(QKV, QL, KL, KLT);
        a2_kernel<<<dim3(MLAND, NHEADS), 256>>>(QL, KL, A2);
        pinv_scale_kernel<<<NHEADS, 256>>>(A2, PS);
        pinv_tr_kernel<<<dim3(16, NHEADS), 256>>>(A2, PS, Z0);
        float* zi = Z0;
        float* zo = Z1;
        for (int it = 0; it < 6; it++) {
            nk256_kernel<<<dim3(4, 4, NHEADS), 256>>>(A2, zi, W1, 1.f, 0.f);
            nk256_kernel<<<dim3(4, 4, NHEADS), 256>>>(W1, W1, W2, -1.f, 7.f);
            nk256_kernel<<<dim3(4, 4, NHEADS), 256>>>(W1, W2, W3, -1.f, 15.f);
            nk256_kernel<<<dim3(4, 4, NHEADS), 256>>>(zi, W3, zo, -0.25f, 3.25f);
            float* t = zi; zi = zo; zo = t;
        }
        a3_fused_kernel<<<dim3(MLAND / 16, NHEADS), 256, A3_SMEM>>>(QKV, KT, QL, A3V);
        bmat_kernel<<<dim3(MLAND / 4, NHEADS), 256>>>(zi, A3V, Bm);
        a1out_kernel<<<dim3(NP / 64, NHEADS), 256, A1_SMEM>>>(QKV, KLT, Bm, O);
        conv_tile_kernel<<<dim3(NP / 128, NHEADS), 256>>>(QKV, convw, O);
        sgemm_kernel<<<dim3(DMODEL / 128, (NHTOK + 127) / 128), 256>>>(
            O + (size_t)PADF * DMODEL, outw, Hbuf, outb, NHTOK, DMODEL, DMODEL,
            FLAG_ACC, 0, 1.f);
    };

    attn(H, ln1_g, ln1_b, qkv1_w, out1_w, out1_b, conv1_w);

    ppeg_tile_kernel<<<dim3(144, NHEADS), 256, PPEG_SMEM>>>(
        H, H2, pg7_w, pg7_b, pg5_w, pg5_b, pg3_w, pg3_b);
    copy_row0_kernel<<<1, DMODEL>>>(H, H2);

    attn(H2, ln2_g, ln2_b, qkv2_w, out2_w, out2_b, conv2_w);

    final_kernel<<<1, DMODEL>>>(H2, norm_g, norm_b, fc2_w, fc2_b, (float*)d_out, out_size);
}

// round 4
// speedup vs baseline: 2.3883x; 1.0514x over previous
#include <cuda_runtime.h>
#include <math.h>
#include <stdint.h>

// ---------------------------------------------------------------------------
// Problem constants
// ---------------------------------------------------------------------------
#define NTOK   8192
#define INDIM  1024
#define DMODEL 512
#define NHEADS 8
#define DH     64
#define MLAND  256
#define LWIN   33
#define NP     8448          // padded attention length
#define NHTOK  8282          // tokens incl cls
#define PADF   166
#define HSQ    91
#define NFEAT  8281
#define NWRAP  89
#define EPSLN  1e-5f

#define FLAG_RELU 1
#define FLAG_ACC  2

// ---------------------------------------------------------------------------
// Scratch (device globals)
// ---------------------------------------------------------------------------
__device__ float g_H  [NHTOK * DMODEL];
__device__ float g_H2 [NHTOK * DMODEL];
__device__ float g_XP [NP * DMODEL];
__device__ float g_QKV[NP * 3 * DMODEL];
__device__ float g_KT [NHEADS * DH * NP];        // K transposed per head [h][d][n]
__device__ float g_QL [NHEADS * MLAND * DH];
__device__ float g_KL [NHEADS * MLAND * DH];
__device__ float g_KLT[NHEADS * DH * MLAND];     // KL transposed [h][d][m]
__device__ float g_A2 [NHEADS * MLAND * MLAND];
__device__ float g_Z0 [NHEADS * MLAND * MLAND];
__device__ float g_Z1 [NHEADS * MLAND * MLAND];
__device__ float g_W1 [NHEADS * MLAND * MLAND];
__device__ float g_W2 [NHEADS * MLAND * MLAND];
__device__ float g_W3 [NHEADS * MLAND * MLAND];
__device__ float g_PS [NHEADS];
__device__ float g_A3V[NHEADS * MLAND * DH];
__device__ float g_Bm [NHEADS * MLAND * DH];
__device__ float g_O  [NP * DMODEL];

// ---------------------------------------------------------------------------
// SGEMM: C = op(A@B). 128x128 tile, 8x8/thread, BK=8, double-buffered smem
// with gmem->register prefetch (one __syncthreads per k-tile).
// ---------------------------------------------------------------------------
__global__ void __launch_bounds__(256, 2)
sgemm_kernel(const float* __restrict__ A, const float* __restrict__ B,
             float* __restrict__ C, const float* __restrict__ bias,
             int Mn, int Nn, int Kn, int flags, int scale_cols, float scale)
{
    __shared__ float As[2][8][128];
    __shared__ float Bs[2][8][128];
    const int bm = blockIdx.y * 128;
    const int bn = blockIdx.x * 128;
    const int tid = threadIdx.x;
    const int tx = tid & 15, ty = tid >> 4;
    const int row0 = ty * 8, col0 = tx * 8;
    // load mapping
    const int arow = tid >> 1, acol = (tid & 1) << 2;     // A: 128 rows x 8 k
    const int brow = tid >> 5, bcol = (tid & 31) << 2;    // B: 8 k x 128 cols
    const bool aok = (bm + arow) < Mn;
    const float* Aptr = A + (size_t)(bm + arow) * Kn + acol;
    const float* Bptr = B + (size_t)brow * Nn + bn + bcol;

    float acc[8][8];
#pragma unroll
    for (int i = 0; i < 8; i++)
#pragma unroll
        for (int j = 0; j < 8; j++) acc[i][j] = 0.f;

    // prologue: tile 0
    float4 av = aok ? *reinterpret_cast<const float4*>(Aptr) : make_float4(0.f, 0.f, 0.f, 0.f);
    float4 bv = *reinterpret_cast<const float4*>(Bptr);
    As[0][acol + 0][arow] = av.x; As[0][acol + 1][arow] = av.y;
    As[0][acol + 2][arow] = av.z; As[0][acol + 3][arow] = av.w;
    *reinterpret_cast<float4*>(&Bs[0][brow][bcol]) = bv;
    __syncthreads();

    const int nt = Kn >> 3;
    int buf = 0;
    for (int t = 0; t < nt; t++) {
        float4 av2, bv2;
        const bool more = (t + 1) < nt;
        if (more) {
            av2 = aok ? *reinterpret_cast<const float4*>(Aptr + (size_t)(t + 1) * 8)
                      : make_float4(0.f, 0.f, 0.f, 0.f);
            bv2 = *reinterpret_cast<const float4*>(Bptr + (size_t)(t + 1) * 8 * Nn);
        }
#pragma unroll
        for (int k = 0; k < 8; k++) {
            float a[8], b[8];
            *reinterpret_cast<float4*>(a)     = *reinterpret_cast<const float4*>(&As[buf][k][row0]);
            *reinterpret_cast<float4*>(a + 4) = *reinterpret_cast<const float4*>(&As[buf][k][row0 + 4]);
            *reinterpret_cast<float4*>(b)     = *reinterpret_cast<const float4*>(&Bs[buf][k][col0]);
            *reinterpret_cast<float4*>(b + 4) = *reinterpret_cast<const float4*>(&Bs[buf][k][col0 + 4]);
#pragma unroll
            for (int i = 0; i < 8; i++)
#pragma unroll
                for (int j = 0; j < 8; j++) acc[i][j] += a[i] * b[j];
        }
        if (more) {
            As[buf ^ 1][acol + 0][arow] = av2.x; As[buf ^ 1][acol + 1][arow] = av2.y;
            As[buf ^ 1][acol + 2][arow] = av2.z; As[buf ^ 1][acol + 3][arow] = av2.w;
            *reinterpret_cast<float4*>(&Bs[buf ^ 1][brow][bcol]) = bv2;
        }
        __syncthreads();
        buf ^= 1;
    }

    const bool relu = (flags & FLAG_RELU) != 0;
    const bool accu = (flags & FLAG_ACC) != 0;
#pragma unroll
    for (int i = 0; i < 8; i++) {
        int r = bm + row0 + i;
        if (r >= Mn) continue;
#pragma unroll
        for (int j = 0; j < 8; j++) {
            int cidx = bn + col0 + j;
            float v = acc[i][j];
            if (cidx < scale_cols) v *= scale;
            if (bias) v += bias[cidx];
            if (relu) v = fmaxf(v, 0.f);
            size_t o = (size_t)r * Nn + cidx;
            if (accu) C[o] += v; else C[o] = v;
        }
    }
}

// ---------------------------------------------------------------------------
// Assemble h rows: cls + wrap
// ---------------------------------------------------------------------------
__global__ void assemble_kernel(const float* __restrict__ cls, float* __restrict__ H)
{
    int j = blockIdx.x;
    int c = threadIdx.x;
    if (j == 0) H[c] = cls[c];
    else        H[(size_t)(NTOK + j) * DMODEL + c] = H[(size_t)j * DMODEL + c];
}

// ---------------------------------------------------------------------------
// LayerNorm into padded XP
// ---------------------------------------------------------------------------
__global__ void ln_pad_kernel(const float* __restrict__ Hin, float* __restrict__ XP,
                              const float* __restrict__ g, const float* __restrict__ b)
{
    int row = blockIdx.x;
    int tid = threadIdx.x;
    if (row < PADF) {
        XP[(size_t)row * DMODEL + tid] = 0.f;
        XP[(size_t)row * DMODEL + tid + 256] = 0.f;
        return;
    }
    const float* x = Hin + (size_t)(row - PADF) * DMODEL;
    float v0 = x[tid], v1 = x[tid + 256];
    __shared__ float s1[256], s2[256];
    s1[tid] = v0 + v1;
    s2[tid] = v0 * v0 + v1 * v1;
    __syncthreads();
    for (int o = 128; o > 0; o >>= 1) {
        if (tid < o) { s1[tid] += s1[tid + o]; s2[tid] += s2[tid + o]; }
        __syncthreads();
    }
    float mean = s1[0] * (1.f / DMODEL);
    float var  = s2[0] * (1.f / DMODEL) - mean * mean;
    float rs = rsqrtf(var + EPSLN);
    XP[(size_t)row * DMODEL + tid]       = (v0 - mean) * rs * g[tid] + b[tid];
    XP[(size_t)row * DMODEL + tid + 256] = (v1 - mean) * rs * g[tid + 256] + b[tid + 256];
}

// ---------------------------------------------------------------------------
// Transpose K part of QKV into g_KT[h][d][n]
// ---------------------------------------------------------------------------
__global__ void ktr_kernel(const float* __restrict__ QKV, float* __restrict__ KT)
{
    __shared__ float tl[64][65];
    int h = blockIdx.y;
    int n0 = blockIdx.x * 64;
    int t = threadIdx.x;
    for (int lin = t; lin < 4096; lin += 256) {
        int r = lin >> 6, i = lin & 63;
        tl[r][i] = QKV[(size_t)(n0 + r) * (3 * DMODEL) + DMODEL + h * DH + i];
    }
    __syncthreads();
    for (int lin = t; lin < 4096; lin += 256) {
        int i = lin >> 6, c = lin & 63;
        KT[(size_t)(h * DH + i) * NP + n0 + c] = tl[c][i];
    }
}

// ---------------------------------------------------------------------------
// Landmarks (means of 33-groups); also writes KL transposed
// ---------------------------------------------------------------------------
__global__ void landmarks_kernel(const float* __restrict__ QKV,
                                 float* __restrict__ QL, float* __restrict__ KL,
                                 float* __restrict__ KLT)
{
    int hm = blockIdx.x;
    int h = hm >> 8, m = hm & 255;
    int tid = threadIdx.x;
    int d = tid & 63;
    int off = (tid < 64) ? 0 : DMODEL;
    size_t base = (size_t)(m * LWIN) * (3 * DMODEL) + off + h * DH + d;
    float s = 0.f;
#pragma unroll
    for (int j = 0; j < LWIN; j++) s += QKV[base + (size_t)j * (3 * DMODEL)];
    s *= (1.0f / LWIN);
    if (tid < 64) {
        QL[(size_t)(h * MLAND + m) * DH + d] = s;
    } else {
        KL[(size_t)(h * MLAND + m) * DH + d] = s;
        KLT[(size_t)h * DH * MLAND + (size_t)d * MLAND + m] = s;
    }
}

// ---------------------------------------------------------------------------
// a2 = softmax(q_l @ k_l^T)
// ---------------------------------------------------------------------------
__global__ void a2_kernel(const float* __restrict__ QL, const float* __restrict__ KL,
                          float* __restrict__ A2)
{
    int m = blockIdx.x, h = blockIdx.y;
    int tid = threadIdx.x;
    __shared__ float q[64];
    __shared__ float red[256];
    if (tid < 64) q[tid] = QL[(size_t)(h * MLAND + m) * DH + tid];
    __syncthreads();
    const float* kr = KL + (size_t)(h * MLAND + tid) * DH;
    float s = 0.f;
#pragma unroll
    for (int i = 0; i < 16; i++) {
        float4 kv = reinterpret_cast<const float4*>(kr)[i];
        float4 qv = reinterpret_cast<const float4*>(q)[i];
        s += kv.x * qv.x + kv.y * qv.y + kv.z * qv.z + kv.w * qv.w;
    }
    red[tid] = s; __syncthreads();
    for (int o = 128; o > 0; o >>= 1) {
        if (tid < o) red[tid] = fmaxf(red[tid], red[tid + o]);
        __syncthreads();
    }
    float mx = red[0]; __syncthreads();
    float e = __expf(s - mx);
    red[tid] = e; __syncthreads();
    for (int o = 128; o > 0; o >>= 1) {
        if (tid < o) red[tid] += red[tid + o];
        __syncthreads();
    }
    float sm = red[0];
    A2[(size_t)(h * MLAND + m) * MLAND + tid] = e / sm;
}

// ---------------------------------------------------------------------------
// pinv scale: 1 / (max rowsum * max colsum) per head
// ---------------------------------------------------------------------------
__global__ void pinv_scale_kernel(const float* __restrict__ A2, float* __restrict__ PS)
{
    int h = blockIdx.x;
    int t = threadIdx.x;
    int w = t >> 5, lane = t & 31;
    const float* Ah = A2 + (size_t)h * 65536;
    __shared__ float rs[256];
    __shared__ float cs2[256];
    for (int r = w; r < 256; r += 8) {
        float s = 0.f;
        for (int j = lane; j < 256; j += 32) s += fabsf(Ah[r * 256 + j]);
        for (int o = 16; o > 0; o >>= 1) s += __shfl_xor_sync(0xffffffffu, s, o);
        if (lane == 0) rs[r] = s;
    }
    float cs = 0.f;
    for (int i = 0; i < 256; i++) cs += fabsf(Ah[i * 256 + t]);
    cs2[t] = cs;
    __syncthreads();
    for (int o = 128; o > 0; o >>= 1) {
        if (t < o) { rs[t] = fmaxf(rs[t], rs[t + o]); cs2[t] = fmaxf(cs2[t], cs2[t + o]); }
        __syncthreads();
    }
    if (t == 0) PS[h] = 1.0f / (rs[0] * cs2[0]);
}

// ---------------------------------------------------------------------------
// pinv transpose-scale: Z0 = A2^T * scale
// ---------------------------------------------------------------------------
__global__ void pinv_tr_kernel(const float* __restrict__ A2, const float* __restrict__ PS,
                               float* __restrict__ Z0)
{
    __shared__ float tl[64][65];
    int h = blockIdx.y;
    int seg = blockIdx.x;
    int bi = (seg >> 2) * 64, bj = (seg & 3) * 64;
    int t = threadIdx.x;
    float inv = PS[h];
    const float* Ah = A2 + (size_t)h * 65536;
    float* Zh = Z0 + (size_t)h * 65536;
    for (int lin = t; lin < 4096; lin += 256) {
        int r = lin >> 6, c = lin & 63;
        tl[r][c] = Ah[(size_t)(bi + r) * 256 + bj + c];
    }
    __syncthreads();
    for (int lin = t; lin < 4096; lin += 256) {
        int r = lin >> 6, c = lin & 63;
        Zh[(size_t)(bj + r) * 256 + bi + c] = tl[c][r] * inv;
    }
}

// ---------------------------------------------------------------------------
// Batched 256^3 matmul: C = alpha*(A@B) + gamma*A (pinv chain)
// ---------------------------------------------------------------------------
__global__ void nk256_kernel(const float* __restrict__ A, const float* __restrict__ B,
                             float* __restrict__ C, float alpha, float gamma)
{
    const float* Ah = A + (size_t)blockIdx.z * 65536;
    const float* Bh = B + (size_t)blockIdx.z * 65536;
    float* Ch = C + (size_t)blockIdx.z * 65536;
    __shared__ float As[16][64];
    __shared__ float Bs[16][64];
    const int bm = blockIdx.y * 64;
    const int bn = blockIdx.x * 64;
    const int tid = threadIdx.x;
    const int tx = tid & 15, ty = tid >> 4;
    const int row0 = ty * 4, col0 = tx * 4;
    float acc[4][4];
#pragma unroll
    for (int i = 0; i < 4; i++)
#pragma unroll
        for (int j = 0; j < 4; j++) acc[i][j] = 0.f;

    for (int k0 = 0; k0 < 256; k0 += 16) {
        {
            int ar = tid >> 2;
            int ac = (tid & 3) << 2;
            float4 v = *reinterpret_cast<const float4*>(Ah + (size_t)(bm + ar) * 256 + k0 + ac);
            As[ac + 0][ar] = v.x; As[ac + 1][ar] = v.y;
            As[ac + 2][ar] = v.z; As[ac + 3][ar] = v.w;
        }
        {
            int br = tid >> 4;
            int bc = (tid & 15) << 2;
            float4 v = *reinterpret_cast<const float4*>(Bh + (size_t)(k0 + br) * 256 + bn + bc);
            *reinterpret_cast<float4*>(&Bs[br][bc]) = v;
        }
        __syncthreads();
#pragma unroll
        for (int k = 0; k < 16; k++) {
            float a[4], b[4];
            *reinterpret_cast<float4*>(a) = *reinterpret_cast<const float4*>(&As[k][row0]);
            *reinterpret_cast<float4*>(b) = *reinterpret_cast<const float4*>(&Bs[k][col0]);
#pragma unroll
            for (int i = 0; i < 4; i++)
#pragma unroll
                for (int j = 0; j < 4; j++) acc[i][j] += a[i] * b[j];
        }
        __syncthreads();
    }
#pragma unroll
    for (int i = 0; i < 4; i++)
#pragma unroll
        for (int j = 0; j < 4; j++) {
            size_t o = (size_t)(bm + row0 + i) * 256 + bn + col0 + j;
            Ch[o] = alpha * acc[i][j] + gamma * Ah[o];
        }
}

// ---------------------------------------------------------------------------
// Fused a3: online-softmax(q_l @ k^T) @ v  -> A3V  (flash style)
// ---------------------------------------------------------------------------
#define A3_KT   0
#define A3_VS   (64 * 264)                 // 16896
#define A3_QS   (A3_VS + 256 * 64)         // 33280
#define A3_PS   (A3_QS + 16 * 64)          // 34304
#define A3_M    (A3_PS + 16 * 264)         // 38528
#define A3_S    (A3_M + 16)
#define A3_SC   (A3_S + 16)
#define A3_RED  (A3_SC + 16)
#define A3_TOT  (A3_RED + 64)              // 38640 floats

__global__ void a3_fused_kernel(const float* __restrict__ QKV, const float* __restrict__ KT,
                                const float* __restrict__ QL, float* __restrict__ A3V)
{
    extern __shared__ float sm[];
    float* Kt  = sm + A3_KT;
    float* Vs  = sm + A3_VS;
    float* Qs  = sm + A3_QS;
    float* Ps  = sm + A3_PS;
    float* Mr  = sm + A3_M;
    float* Sr  = sm + A3_S;
    float* Scl = sm + A3_SC;
    float* Red = sm + A3_RED;

    int h  = blockIdx.y;
    int m0 = blockIdx.x * 16;
    int t  = threadIdx.x;
    int lane = t & 31, w = t >> 5;

    int la = t >> 6, lc = t & 63;
    int gc = t >> 6, pr = (t >> 4) & 3, td = t & 15;

    for (int lin = t; lin < 16 * 64; lin += 256) {
        int r = lin >> 6, i = lin & 63;
        Qs[r * 64 + i] = QL[(size_t)(h * MLAND + m0 + r) * DH + i];
    }
    if (t < 16) { Mr[t] = -1e30f; Sr[t] = 0.f; }

    float accv[4][4];
#pragma unroll
    for (int i = 0; i < 4; i++)
#pragma unroll
        for (int j = 0; j < 4; j++) accv[i][j] = 0.f;

    for (int n0 = 0; n0 < NP; n0 += 256) {
        for (int lin = t; lin < 4096; lin += 256) {
            int i = lin >> 6, c4 = (lin & 63) << 2;
            *reinterpret_cast<float4*>(&Kt[i * 264 + c4]) =
                *reinterpret_cast<const float4*>(&KT[(size_t)(h * DH + i) * NP + n0 + c4]);
        }
        for (int lin = t; lin < 4096; lin += 256) {
            int r = lin >> 4, c4 = (lin & 15) << 2;
            *reinterpret_cast<float4*>(&Vs[r * 64 + c4]) =
                *reinterpret_cast<const float4*>(&QKV[(size_t)(n0 + r) * (3 * DMODEL) + 2 * DMODEL + h * DH + c4]);
        }
        __syncthreads();

        float lacc[4][4];
#pragma unroll
        for (int i = 0; i < 4; i++)
#pragma unroll
            for (int j = 0; j < 4; j++) lacc[i][j] = 0.f;
#pragma unroll
        for (int i = 0; i < 64; i += 4) {
            float4 aq[4];
#pragma unroll
            for (int rr = 0; rr < 4; rr++)
                aq[rr] = *reinterpret_cast<const float4*>(&Qs[(la * 4 + rr) * 64 + i]);
#pragma unroll
            for (int ii = 0; ii < 4; ii++) {
                float4 b = *reinterpret_cast<const float4*>(&Kt[(i + ii) * 264 + (lc << 2)]);
#pragma unroll
                for (int rr = 0; rr < 4; rr++) {
                    float av = reinterpret_cast<const float*>(&aq[rr])[ii];
                    lacc[rr][0] += av * b.x; lacc[rr][1] += av * b.y;
                    lacc[rr][2] += av * b.z; lacc[rr][3] += av * b.w;
                }
            }
        }
        float pm[4];
#pragma unroll
        for (int rr = 0; rr < 4; rr++)
            pm[rr] = fmaxf(fmaxf(lacc[rr][0], lacc[rr][1]), fmaxf(lacc[rr][2], lacc[rr][3]));
        for (int o = 16; o > 0; o >>= 1)
#pragma unroll
            for (int rr = 0; rr < 4; rr++)
                pm[rr] = fmaxf(pm[rr], __shfl_xor_sync(0xffffffffu, pm[rr], o));
        if (lane == 0)
#pragma unroll
            for (int rr = 0; rr < 4; rr++) Red[w * 4 + rr] = pm[rr];
        __syncthreads();
        if (t < 16) {
            int wb = (t >> 2) * 2;
            float tmax = fmaxf(Red[wb * 4 + (t & 3)], Red[(wb + 1) * 4 + (t & 3)]);
            float oldM = Mr[t], newM = fmaxf(oldM, tmax);
            Scl[t] = __expf(oldM - newM);
            Mr[t] = newM;
        }
        __syncthreads();
        float psum[4];
#pragma unroll
        for (int rr = 0; rr < 4; rr++) {
            float nm = Mr[la * 4 + rr];
            float p0 = __expf(lacc[rr][0] - nm);
            float p1 = __expf(lacc[rr][1] - nm);
            float p2 = __expf(lacc[rr][2] - nm);
            float p3 = __expf(lacc[rr][3] - nm);
            *reinterpret_cast<float4*>(&Ps[(la * 4 + rr) * 264 + (lc << 2)]) =
                make_float4(p0, p1, p2, p3);
            psum[rr] = p0 + p1 + p2 + p3;
        }
        for (int o = 16; o > 0; o >>= 1)
#pragma unroll
            for (int rr = 0; rr < 4; rr++)
                psum[rr] += __shfl_xor_sync(0xffffffffu, psum[rr], o);
        if (lane == 0)
#pragma unroll
            for (int rr = 0; rr < 4; rr++) Red[w * 4 + rr] = psum[rr];
        __syncthreads();
        if (t < 16) {
            int wb = (t >> 2) * 2;
            float ts = Red[wb * 4 + (t & 3)] + Red[(wb + 1) * 4 + (t & 3)];
            Sr[t] = Sr[t] * Scl[t] + ts;
        }
#pragma unroll
        for (int rr = 0; rr < 4; rr++) {
            float sc = Scl[pr * 4 + rr];
            accv[rr][0] *= sc; accv[rr][1] *= sc; accv[rr][2] *= sc; accv[rr][3] *= sc;
        }
#pragma unroll 4
        for (int c = 0; c < 64; c++) {
            int cg = gc * 64 + c;
            float4 v = *reinterpret_cast<const float4*>(&Vs[cg * 64 + (td << 2)]);
#pragma unroll
            for (int rr = 0; rr < 4; rr++) {
                float p = Ps[(pr * 4 + rr) * 264 + cg];
                accv[rr][0] += p * v.x; accv[rr][1] += p * v.y;
                accv[rr][2] += p * v.z; accv[rr][3] += p * v.w;
            }
        }
        __syncthreads();
    }
#pragma unroll
    for (int rr = 0; rr < 4; rr++)
        *reinterpret_cast<float4*>(&sm[gc * 1024 + (pr * 4 + rr) * 64 + (td << 2)]) =
            make_float4(accv[rr][0], accv[rr][1], accv[rr][2], accv[rr][3]);
    __syncthreads();
    for (int lin = t; lin < 1024; lin += 256) {
        int row = lin >> 6, d = lin & 63;
        float v = sm[row * 64 + d] + sm[1024 + row * 64 + d] +
                  sm[2048 + row * 64 + d] + sm[3072 + row * 64 + d];
        A3V[(size_t)(h * MLAND + m0 + row) * DH + d] = v / Sr[row];
    }
}

// ---------------------------------------------------------------------------
// Bm = pinv(a2) @ a3v
// ---------------------------------------------------------------------------
__global__ void bmat_kernel(const float* __restrict__ Z, const float* __restrict__ A3V,
                            float* __restrict__ Bm)
{
    int h = blockIdx.y;
    int m0 = blockIdx.x * 4;
    __shared__ float zs[4][256];
    int tid = threadIdx.x;
    int r = tid >> 6, d = tid & 63;
    for (int lin = tid; lin < 1024; lin += 256) {
        int rr = lin >> 8, k = lin & 255;
        zs[rr][k] = Z[(size_t)h * 65536 + (size_t)(m0 + rr) * 256 + k];
    }
    __syncthreads();
    float acc = 0.f;
    for (int k = 0; k < 256; k++)
        acc += zs[r][k] * A3V[(size_t)(h * MLAND + k) * DH + d];
    Bm[(size_t)(h * MLAND + m0 + r) * DH + d] = acc;
}

// ---------------------------------------------------------------------------
// a1 @ Bm as two tiled GEMMs with warp-shuffle softmax, plus fused depthwise
// seq-conv (k=33) on v in the epilogue. V halo loads into the (dead) KLt
// region during the PV phase.
// ---------------------------------------------------------------------------
#define A1_QS   0                           // [64][65]
#define A1_KLT  (64 * 65)                   // [64][260] (reused as V[96][64])
#define A1_PS   (A1_KLT + 64 * 260)         // [64][260]
#define A1_BMS  (A1_PS + 64 * 260)          // [256][64]
#define A1_WS   (A1_BMS + 256 * 64)         // 33 conv weights
#define A1_TOT  (A1_WS + 40)                // 53864 floats

__global__ void a1out_kernel(const float* __restrict__ QKV, const float* __restrict__ KLT,
                             const float* __restrict__ Bm, const float* __restrict__ W,
                             float* __restrict__ O)
{
    extern __shared__ float sm[];
    float* Qs  = sm + A1_QS;
    float* KLt = sm + A1_KLT;
    float* Ps  = sm + A1_PS;
    float* Bms = sm + A1_BMS;
    float* ws  = sm + A1_WS;

    int h = blockIdx.y;
    int row0 = blockIdx.x * 64;
    int t = threadIdx.x;

    if (t < 33) ws[t] = W[h * LWIN + t];
    for (int lin = t; lin < 4096; lin += 256) {
        int r = lin >> 6, i = lin & 63;
        Qs[r * 65 + i] = QKV[(size_t)(row0 + r) * (3 * DMODEL) + h * DH + i];
    }
    for (int lin = t; lin < 16384; lin += 256) {
        int i = lin >> 8, m = lin & 255;
        KLt[i * 260 + m] = KLT[(size_t)h * DH * MLAND + lin];
    }
    for (int lin = t; lin < 16384; lin += 256) {
        Bms[lin] = Bm[(size_t)h * MLAND * DH + lin];
    }
    __syncthreads();

    // phase 1: logits (reads Qs, KLt) + softmax -> Ps
    int ty = t >> 5, tx = t & 31;
    float acc[8][8];
#pragma unroll
    for (int i = 0; i < 8; i++)
#pragma unroll
        for (int j = 0; j < 8; j++) acc[i][j] = 0.f;
    for (int i = 0; i < 64; i++) {
        float4 b0 = *reinterpret_cast<const float4*>(&KLt[i * 260 + tx * 8]);
        float4 b1 = *reinterpret_cast<const float4*>(&KLt[i * 260 + tx * 8 + 4]);
#pragma unroll
        for (int j = 0; j < 8; j++) {
            float a = Qs[(ty * 8 + j) * 65 + i];
            acc[j][0] += a * b0.x; acc[j][1] += a * b0.y;
            acc[j][2] += a * b0.z; acc[j][3] += a * b0.w;
            acc[j][4] += a * b1.x; acc[j][5] += a * b1.y;
            acc[j][6] += a * b1.z; acc[j][7] += a * b1.w;
        }
    }
#pragma unroll
    for (int j = 0; j < 8; j++) {
        float m = acc[j][0];
#pragma unroll
        for (int k = 1; k < 8; k++) m = fmaxf(m, acc[j][k]);
        for (int o = 16; o > 0; o >>= 1) m = fmaxf(m, __shfl_xor_sync(0xffffffffu, m, o));
        float s = 0.f;
#pragma unroll
        for (int k = 0; k < 8; k++) { acc[j][k] = __expf(acc[j][k] - m); s += acc[j][k]; }
        for (int o = 16; o > 0; o >>= 1) s += __shfl_xor_sync(0xffffffffu, s, o);
        float inv = 1.0f / s;
        *reinterpret_cast<float4*>(&Ps[(ty * 8 + j) * 260 + tx * 8]) =
            make_float4(acc[j][0] * inv, acc[j][1] * inv, acc[j][2] * inv, acc[j][3] * inv);
        *reinterpret_cast<float4*>(&Ps[(ty * 8 + j) * 260 + tx * 8 + 4]) =
            make_float4(acc[j][4] * inv, acc[j][5] * inv, acc[j][6] * inv, acc[j][7] * inv);
    }
    __syncthreads();   // all KLt reads done; Ps complete

    // phase 2: load V halo into KLt region (96 rows x 64 dims) + PV gemm
    float* Vc = KLt;
    for (int lin = t; lin < 96 * 64; lin += 256) {
        int r = lin >> 6, c = lin & 63;
        int n = row0 - 16 + r;
        Vc[lin] = (n >= 0 && n < NP)
                    ? QKV[(size_t)n * (3 * DMODEL) + 2 * DMODEL + h * DH + c] : 0.f;
    }

    int rr = t >> 4, cc = t & 15;
    float o4[4][4];
#pragma unroll
    for (int i = 0; i < 4; i++)
#pragma unroll
        for (int j = 0; j < 4; j++) o4[i][j] = 0.f;
    for (int c = 0; c < 256; c++) {
        float4 b = *reinterpret_cast<const float4*>(&Bms[c * 64 + cc * 4]);
#pragma unroll
        for (int k = 0; k < 4; k++) {
            float a = Ps[(rr * 4 + k) * 260 + c];
            o4[k][0] += a * b.x; o4[k][1] += a * b.y;
            o4[k][2] += a * b.z; o4[k][3] += a * b.w;
        }
    }
    __syncthreads();   // V halo complete

    // epilogue: add depthwise conv and write O
#pragma unroll
    for (int k = 0; k < 4; k++) {
        int lrow = rr * 4 + k;
        float cv0 = 0.f, cv1 = 0.f, cv2 = 0.f, cv3 = 0.f;
#pragma unroll
        for (int t2 = 0; t2 < LWIN; t2++) {
            float wv = ws[t2];
            float4 v = *reinterpret_cast<const float4*>(&Vc[(lrow + t2) * 64 + cc * 4]);
            cv0 += wv * v.x; cv1 += wv * v.y; cv2 += wv * v.z; cv3 += wv * v.w;
        }
        *reinterpret_cast<float4*>(&O[(size_t)(row0 + lrow) * DMODEL + h * DH + cc * 4]) =
            make_float4(o4[k][0] + cv0, o4[k][1] + cv1, o4[k][2] + cv2, o4[k][3] + cv3);
    }
}

// ---------------------------------------------------------------------------
// PPEG tiled: 8x8 spatial x 64 channels per block, 14x14 halo + weights in smem
// ---------------------------------------------------------------------------
#define PPEG_TILE (14 * 14 * 64)            // 12544
#define PPEG_W7   PPEG_TILE
#define PPEG_W5   (PPEG_W7 + 64 * 49)
#define PPEG_W3   (PPEG_W5 + 64 * 25)
#define PPEG_TOT  (PPEG_W3 + 64 * 9)        // 17856 floats

__global__ void ppeg_tile_kernel(const float* __restrict__ Hin, float* __restrict__ Hout,
                                 const float* __restrict__ w7, const float* __restrict__ b7,
                                 const float* __restrict__ w5, const float* __restrict__ b5,
                                 const float* __restrict__ w3, const float* __restrict__ b3)
{
    extern __shared__ float sm[];
    float* tile = sm;
    float* ws7 = sm + PPEG_W7;
    float* ws5 = sm + PPEG_W5;
    float* ws3 = sm + PPEG_W3;

    int ti = blockIdx.x;
    int ty0 = (ti / 12) * 8, tx0 = (ti % 12) * 8;
    int cg = blockIdx.y * 64;
    int t = threadIdx.x;

    for (int lin = t; lin < PPEG_TILE; lin += 256) {
        int p = lin >> 6, c = lin & 63;
        int gy = ty0 + p / 14 - 3;
        int gx = tx0 + p % 14 - 3;
        float v = 0.f;
        if ((unsigned)gy < (unsigned)HSQ && (unsigned)gx < (unsigned)HSQ)
            v = Hin[(size_t)(1 + gy * HSQ + gx) * DMODEL + cg + c];
        tile[lin] = v;
    }
    for (int lin = t; lin < 64 * 49; lin += 256) ws7[lin] = w7[(size_t)cg * 49 + lin];
    for (int lin = t; lin < 64 * 25; lin += 256) ws5[lin] = w5[(size_t)cg * 25 + lin];
    for (int lin = t; lin < 64 * 9;  lin += 256) ws3[lin] = w3[(size_t)cg * 9 + lin];
    __syncthreads();

    int c = t & 63, pg = t >> 6;
    float bsum = b7[cg + c] + b5[cg + c] + b3[cg + c];
    for (int q = 0; q < 16; q++) {
        int p = pg * 16 + q;
        int oy = p >> 3, ox = p & 7;
        int gy = ty0 + oy, gx = tx0 + ox;
        if (gy >= HSQ || gx >= HSQ) continue;
        float acc = tile[((oy + 3) * 14 + ox + 3) * 64 + c] + bsum;
#pragma unroll
        for (int a = 0; a < 7; a++)
#pragma unroll
            for (int bq = 0; bq < 7; bq++)
                acc += ws7[c * 49 + a * 7 + bq] * tile[((oy + a) * 14 + ox + bq) * 64 + c];
#pragma unroll
        for (int a = 0; a < 5; a++)
#pragma unroll
            for (int bq = 0; bq < 5; bq++)
                acc += ws5[c * 25 + a * 5 + bq] * tile[((oy + a + 1) * 14 + ox + bq + 1) * 64 + c];
#pragma unroll
        for (int a = 0; a < 3; a++)
#pragma unroll
            for (int bq = 0; bq < 3; bq++)
                acc += ws3[c * 9 + a * 3 + bq] * tile[((oy + a + 2) * 14 + ox + bq + 2) * 64 + c];
        Hout[(size_t)(1 + gy * HSQ + gx) * DMODEL + cg + c] = acc;
    }
}

__global__ void copy_row0_kernel(const float* __restrict__ Hin, float* __restrict__ Hout)
{
    Hout[threadIdx.x] = Hin[threadIdx.x];
}

// ---------------------------------------------------------------------------
// Final head
// ---------------------------------------------------------------------------
__global__ void final_kernel(const float* __restrict__ H, const float* __restrict__ g,
                             const float* __restrict__ b, const float* __restrict__ w,
                             const float* __restrict__ bias2, float* __restrict__ out,
                             int out_size)
{
    int c = threadIdx.x;
    __shared__ float s1[512], s2[512];
    float x = H[c];
    s1[c] = x; s2[c] = x * x;
    __syncthreads();
    for (int o = 256; o > 0; o >>= 1) {
        if (c < o) { s1[c] += s1[c + o]; s2[c] += s2[c + o]; }
        __syncthreads();
    }
    float mean = s1[0] * (1.f / DMODEL);
    float var  = s2[0] * (1.f / DMODEL) - mean * mean;
    float e = (x - mean) * rsqrtf(var + EPSLN) * g[c] + b[c];
    __syncthreads();
    s1[c] = e * w[c * 2 + 0];
    s2[c] = e * w[c * 2 + 1];
    __syncthreads();
    for (int o = 256; o > 0; o >>= 1) {
        if (c < o) { s1[c] += s1[c + o]; s2[c] += s2[c + o]; }
        __syncthreads();
    }
    float l0 = s1[0] + bias2[0];
    float l1 = s2[0] + bias2[1];
    if (c == 0) {
        float m = fmaxf(l0, l1);
        float e0 = expf(l0 - m), e1 = expf(l1 - m);
        float ss = e0 + e1;
        if (out_size > 0) out[0] = l0;
        if (out_size > 1) out[1] = l1;
        if (out_size > 2) out[2] = e0 / ss;
        if (out_size > 3) out[3] = e1 / ss;
        if (out_size > 4) out[4] = (l1 > l0) ? 1.0f : 0.0f;
    }
    if (5 + c < out_size) out[5 + c] = e;
}

// ---------------------------------------------------------------------------
// Host orchestration
// ---------------------------------------------------------------------------
static float* symaddr(const void* sym)
{
    void* p = nullptr;
    cudaGetSymbolAddress(&p, sym);
    return (float*)p;
}

static cudaStream_t g_side = nullptr;
static cudaEvent_t  g_evf  = nullptr;
static cudaEvent_t  g_evj  = nullptr;

extern "C" void kernel_launch(void* const* d_in, const int* in_sizes, int n_in,
                              void* d_out, int out_size)
{
    if (!g_side) {
        cudaStreamCreateWithFlags(&g_side, cudaStreamNonBlocking);
        cudaEventCreateWithFlags(&g_evf, cudaEventDisableTiming);
        cudaEventCreateWithFlags(&g_evj, cudaEventDisableTiming);
    }

    const float* x       = (const float*)d_in[0];
    const float* fc1_w   = (const float*)d_in[1];
    const float* fc1_b   = (const float*)d_in[2];
    const float* cls     = (const float*)d_in[3];
    const float* ln1_g   = (const float*)d_in[4];
    const float* ln1_b   = (const float*)d_in[5];
    const float* qkv1_w  = (const float*)d_in[6];
    const float* out1_w  = (const float*)d_in[7];
    const float* out1_b  = (const float*)d_in[8];
    const float* conv1_w = (const float*)d_in[9];
    const float* ln2_g   = (const float*)d_in[10];
    const float* ln2_b   = (const float*)d_in[11];
    const float* qkv2_w  = (const float*)d_in[12];
    const float* out2_w  = (const float*)d_in[13];
    const float* out2_b  = (const float*)d_in[14];
    const float* conv2_w = (const float*)d_in[15];
    const float* pg7_w   = (const float*)d_in[16];
    const float* pg7_b   = (const float*)d_in[17];
    const float* pg5_w   = (const float*)d_in[18];
    const float* pg5_b   = (const float*)d_in[19];
    const float* pg3_w   = (const float*)d_in[20];
    const float* pg3_b   = (const float*)d_in[21];
    const float* norm_g  = (const float*)d_in[22];
    const float* norm_b  = (const float*)d_in[23];
    const float* fc2_w   = (const float*)d_in[24];
    const float* fc2_b   = (const float*)d_in[25];

    float* H   = symaddr(g_H);
    float* H2  = symaddr(g_H2);
    float* XP  = symaddr(g_XP);
    float* QKV = symaddr(g_QKV);
    float* KT  = symaddr(g_KT);
    float* QL  = symaddr(g_QL);
    float* KL  = symaddr(g_KL);
    float* KLT = symaddr(g_KLT);
    float* A2  = symaddr(g_A2);
    float* Z0  = symaddr(g_Z0);
    float* Z1  = symaddr(g_Z1);
    float* W1  = symaddr(g_W1);
    float* W2  = symaddr(g_W2);
    float* W3  = symaddr(g_W3);
    float* PS  = symaddr(g_PS);
    float* A3V = symaddr(g_A3V);
    float* Bm  = symaddr(g_Bm);
    float* O   = symaddr(g_O);

    const int A3_SMEM   = A3_TOT * 4;
    const int A1_SMEM   = A1_TOT * 4;
    const int PPEG_SMEM = PPEG_TOT * 4;
    cudaFuncSetAttribute(a3_fused_kernel, cudaFuncAttributeMaxDynamicSharedMemorySize, A3_SMEM);
    cudaFuncSetAttribute(a1out_kernel,    cudaFuncAttributeMaxDynamicSharedMemorySize, A1_SMEM);
    cudaFuncSetAttribute(ppeg_tile_kernel, cudaFuncAttributeMaxDynamicSharedMemorySize, PPEG_SMEM);

    sgemm_kernel<<<dim3(DMODEL / 128, NTOK / 128), 256>>>(
        x, fc1_w, H + DMODEL, fc1_b, NTOK, DMODEL, INDIM, FLAG_RELU, 0, 1.f);
    assemble_kernel<<<NWRAP + 1, DMODEL>>>(cls, H);

    auto attn = [&](float* Hbuf, const float* lng, const float* lnb, const float* qkvw,
                    const float* outw, const float* outb, const float* convw) {
        ln_pad_kernel<<<NP, 256>>>(Hbuf, XP, lng, lnb);
        sgemm_kernel<<<dim3(3 * DMODEL / 128, NP / 128), 256>>>(
            XP, qkvw, QKV, nullptr, NP, 3 * DMODEL, DMODEL, 0, DMODEL, 0.125f);
        ktr_kernel<<<dim3(NP / 64, NHEADS), 256>>>(QKV, KT);
        landmarks_kernel<<<NHEADS * MLAND, 128>>>(QKV, QL, KL, KLT);
        a2_kernel<<<dim3(MLAND, NHEADS), 256>>>(QL, KL, A2);

        // fork: pinv chain on side stream, overlapped with a3_fused on main
        cudaEventRecord(g_evf, 0);
        cudaStreamWaitEvent(g_side, g_evf, 0);
        pinv_scale_kernel<<<NHEADS, 256, 0, g_side>>>(A2, PS);
        pinv_tr_kernel<<<dim3(16, NHEADS), 256, 0, g_side>>>(A2, PS, Z0);
        float* zi = Z0;
        float* zo = Z1;
        for (int it = 0; it < 6; it++) {
            nk256_kernel<<<dim3(4, 4, NHEADS), 256, 0, g_side>>>(A2, zi, W1, 1.f, 0.f);
            nk256_kernel<<<dim3(4, 4, NHEADS), 256, 0, g_side>>>(W1, W1, W2, -1.f, 7.f);
            nk256_kernel<<<dim3(4, 4, NHEADS), 256, 0, g_side>>>(W1, W2, W3, -1.f, 15.f);
            nk256_kernel<<<dim3(4, 4, NHEADS), 256, 0, g_side>>>(zi, W3, zo, -0.25f, 3.25f);
            float* t = zi; zi = zo; zo = t;
        }
        cudaEventRecord(g_evj, g_side);

        a3_fused_kernel<<<dim3(MLAND / 16, NHEADS), 256, A3_SMEM>>>(QKV, KT, QL, A3V);

        // join
        cudaStreamWaitEvent(0, g_evj, 0);
        bmat_kernel<<<dim3(MLAND / 4, NHEADS), 256>>>(zi, A3V, Bm);
        a1out_kernel<<<dim3(NP / 64, NHEADS), 256, A1_SMEM>>>(QKV, KLT, Bm, convw, O);
        sgemm_kernel<<<dim3(DMODEL / 128, (NHTOK + 127) / 128), 256>>>(
            O + (size_t)PADF * DMODEL, outw, Hbuf, outb, NHTOK, DMODEL, DMODEL,
            FLAG_ACC, 0, 1.f);
    };

    attn(H, ln1_g, ln1_b, qkv1_w, out1_w, out1_b, conv1_w);

    ppeg_tile_kernel<<<dim3(144, NHEADS), 256, PPEG_SMEM>>>(
        H, H2, pg7_w, pg7_b, pg5_w, pg5_b, pg3_w, pg3_b);
    copy_row0_kernel<<<1, DMODEL>>>(H, H2);

    attn(H2, ln2_g, ln2_b, qkv2_w, out2_w, out2_b, conv2_w);

    final_kernel<<<1, DMODEL>>>(H2, norm_g, norm_b, fc2_w, fc2_b, (float*)d_out, out_size);
}

// round 6
// speedup vs baseline: 2.9467x; 1.2338x over previous
#include <cuda_runtime.h>
#include <cuda_bf16.h>
#include <math.h>
#include <stdint.h>

// ---------------------------------------------------------------------------
// Problem constants
// ---------------------------------------------------------------------------
#define NTOK   8192
#define INDIM  1024
#define DMODEL 512
#define NHEADS 8
#define DH     64
#define MLAND  256
#define LWIN   33
#define NP     8448          // padded attention length
#define NHTOK  8282          // tokens incl cls
#define PADF   166
#define HSQ    91
#define NFEAT  8281
#define NWRAP  89
#define EPSLN  1e-5f

#define FLAG_RELU 1
#define FLAG_ACC  2

// ---------------------------------------------------------------------------
// Scratch (device globals)
// ---------------------------------------------------------------------------
__device__ float g_H  [NHTOK * DMODEL];
__device__ float g_H2 [NHTOK * DMODEL];
__device__ float g_XP [NP * DMODEL];
__device__ float g_QKV[NP * 3 * DMODEL];
__device__ float g_KT [NHEADS * DH * NP];
__device__ float g_QL [NHEADS * MLAND * DH];
__device__ float g_KL [NHEADS * MLAND * DH];
__device__ float g_KLT[NHEADS * DH * MLAND];
__device__ float g_A2 [NHEADS * MLAND * MLAND];
__device__ float g_Z0 [NHEADS * MLAND * MLAND];
__device__ float g_Z1 [NHEADS * MLAND * MLAND];
__device__ float g_W1 [NHEADS * MLAND * MLAND];
__device__ float g_W2 [NHEADS * MLAND * MLAND];
__device__ float g_W3 [NHEADS * MLAND * MLAND];
__device__ float g_PS [NHEADS];
__device__ float g_A3V[NHEADS * MLAND * DH];
__device__ float g_Bm [NHEADS * MLAND * DH];
__device__ float g_O  [NP * DMODEL];
// bf16 hi/lo staging for tensor-core GEMMs
__device__ __nv_bfloat16 g_AH[NP * INDIM];
__device__ __nv_bfloat16 g_AL[NP * INDIM];
__device__ __nv_bfloat16 g_WH[3 * DMODEL * DMODEL];
__device__ __nv_bfloat16 g_WL[3 * DMODEL * DMODEL];

// ---------------------------------------------------------------------------
// warp-mma helpers (sm_80+ PTX; compiles for plain sm_100 target)
// ---------------------------------------------------------------------------
__device__ __forceinline__ uint32_t smem_u32(const void* p)
{
    uint32_t a;
    asm("{ .reg .u64 t; cvta.to.shared.u64 t, %1; cvt.u32.u64 %0, t; }" : "=r"(a) : "l"(p));
    return a;
}
__device__ __forceinline__ void ldsm_x4(uint32_t* r, uint32_t addr)
{
    asm volatile("ldmatrix.sync.aligned.m8n8.x4.shared.b16 {%0,%1,%2,%3}, [%4];"
                 : "=r"(r[0]), "=r"(r[1]), "=r"(r[2]), "=r"(r[3]) : "r"(addr));
}
__device__ __forceinline__ void ldsm_x2(uint32_t* r, uint32_t addr)
{
    asm volatile("ldmatrix.sync.aligned.m8n8.x2.shared.b16 {%0,%1}, [%2];"
                 : "=r"(r[0]), "=r"(r[1]) : "r"(addr));
}
__device__ __forceinline__ void mma_bf16(float* d, const uint32_t* a, const uint32_t* b)
{
    asm volatile("mma.sync.aligned.m16n8k16.row.col.f32.bf16.bf16.f32 "
                 "{%0,%1,%2,%3}, {%4,%5,%6,%7}, {%8,%9}, {%0,%1,%2,%3};"
                 : "+f"(d[0]), "+f"(d[1]), "+f"(d[2]), "+f"(d[3])
                 : "r"(a[0]), "r"(a[1]), "r"(a[2]), "r"(a[3]), "r"(b[0]), "r"(b[1]));
}

// ---------------------------------------------------------------------------
// Weight convert+transpose: W [K][N] f32 -> Whi/Wlo [N][K] bf16
// ---------------------------------------------------------------------------
__global__ void wconv_kernel(const float* __restrict__ W,
                             __nv_bfloat16* __restrict__ Whi, __nv_bfloat16* __restrict__ Wlo,
                             int K, int N)
{
    __shared__ float tl[32][33];
    int kb = blockIdx.y * 32, nb = blockIdx.x * 32;
    int t = threadIdx.x;
    for (int i = t; i < 1024; i += 256) {
        int r = i >> 5, c = i & 31;
        tl[r][c] = W[(size_t)(kb + r) * N + nb + c];
    }
    __syncthreads();
    for (int i = t; i < 1024; i += 256) {
        int n = i >> 5, k = i & 31;
        float v = tl[k][n];
        __nv_bfloat16 h = __float2bfloat16(v);
        float lo = v - __bfloat162float(h);
        size_t o = (size_t)(nb + n) * K + kb + k;
        Whi[o] = h;
        Wlo[o] = __float2bfloat16(lo);
    }
}

// ---------------------------------------------------------------------------
// Activation convert: A [Min][K] f32 -> Ahi/Alo [Mpad][K] bf16 (zero pad rows)
// ---------------------------------------------------------------------------
__global__ void aconv_kernel(const float* __restrict__ A,
                             __nv_bfloat16* __restrict__ Ahi, __nv_bfloat16* __restrict__ Alo,
                             int Min, int Kn)
{
    int r = blockIdx.x;
    size_t base = (size_t)r * Kn;
    if (r >= Min) {
        __nv_bfloat162 z = __float2bfloat162_rn(0.f);
        for (int c = threadIdx.x * 2; c < Kn; c += 256) {
            *reinterpret_cast<__nv_bfloat162*>(Ahi + base + c) = z;
            *reinterpret_cast<__nv_bfloat162*>(Alo + base + c) = z;
        }
        return;
    }
    for (int c = threadIdx.x * 2; c < Kn; c += 256) {
        float2 v = *reinterpret_cast<const float2*>(A + base + c);
        __nv_bfloat16 h0 = __float2bfloat16(v.x);
        __nv_bfloat16 h1 = __float2bfloat16(v.y);
        float l0 = v.x - __bfloat162float(h0);
        float l1 = v.y - __bfloat162float(h1);
        __nv_bfloat162 hp; hp.x = h0; hp.y = h1;
        __nv_bfloat162 lp; lp.x = __float2bfloat16(l0); lp.y = __float2bfloat16(l1);
        *reinterpret_cast<__nv_bfloat162*>(Ahi + base + c) = hp;
        *reinterpret_cast<__nv_bfloat162*>(Alo + base + c) = lp;
    }
}

// ---------------------------------------------------------------------------
// warp-MMA GEMM: C[M][N] = op(A @ B^T); A hi/lo [Mpad][K] bf16, B hi/lo [N][K].
// 128x128 CTA tile, 8 warps (4x2), warp tile 32x64, K-chunks of 64.
// Compensated: D += Ah*Bh + Ah*Bl + Al*Bh  (error ~2^-17 relative).
// ---------------------------------------------------------------------------
#define TCB_STR  72                       // padded bf16 row stride (144B, 16B-aligned)
#define TCG_SMEM (4 * 128 * TCB_STR * 2)  // 73728 bytes

__global__ void __launch_bounds__(256)
tc_gemm_kernel(const __nv_bfloat16* __restrict__ Ahi, const __nv_bfloat16* __restrict__ Alo,
               const __nv_bfloat16* __restrict__ Bhi, const __nv_bfloat16* __restrict__ Blo,
               float* __restrict__ C, const float* __restrict__ bias,
               int Mn, int Nn, int Kn, int flags, int scale_cols, float scale)
{
    extern __shared__ __nv_bfloat16 smb[];
    __nv_bfloat16* sAh = smb;
    __nv_bfloat16* sAl = smb + 128 * TCB_STR;
    __nv_bfloat16* sBh = smb + 2 * 128 * TCB_STR;
    __nv_bfloat16* sBl = smb + 3 * 128 * TCB_STR;

    const int t = threadIdx.x, lane = t & 31, wid = t >> 5;
    const int m0 = blockIdx.y * 128, n0 = blockIdx.x * 128;
    const int wm = (wid & 3) * 32;        // warp row offset
    const int wn = (wid >> 2) * 64;       // warp col offset

    const uint32_t sAh_u = smem_u32(sAh), sAl_u = smem_u32(sAl);
    const uint32_t sBh_u = smem_u32(sBh), sBl_u = smem_u32(sBl);

    // ldmatrix lane address offsets
    const int a_row = (lane & 7) + ((lane >> 3) & 1) * 8;   // tiles: (m,k),(m+8,k),(m,k+8),(m+8,k+8)
    const int a_col = (lane >> 4) * 8;
    const int b_row = lane & 7;                              // tiles: (n,k),(n,k+8)
    const int b_col = ((lane >> 3) & 1) * 8;

    float acc[2][8][4];
#pragma unroll
    for (int i = 0; i < 2; i++)
#pragma unroll
        for (int j = 0; j < 8; j++)
#pragma unroll
            for (int k = 0; k < 4; k++) acc[i][j][k] = 0.f;

    for (int k0 = 0; k0 < Kn; k0 += 64) {
        // stage 128x64 bf16 tiles of Ahi/Alo/Bhi/Blo (A rows padded; B rows = N tile)
        for (int i = t; i < 1024; i += 256) {
            int r = i >> 3, kg = (i & 7) << 3;
            int off = r * TCB_STR + kg;
            size_t ga = (size_t)(m0 + r) * Kn + k0 + kg;
            size_t gb = (size_t)(n0 + r) * Kn + k0 + kg;
            *reinterpret_cast<uint4*>(sAh + off) = *reinterpret_cast<const uint4*>(Ahi + ga);
            *reinterpret_cast<uint4*>(sAl + off) = *reinterpret_cast<const uint4*>(Alo + ga);
            *reinterpret_cast<uint4*>(sBh + off) = *reinterpret_cast<const uint4*>(Bhi + gb);
            *reinterpret_cast<uint4*>(sBl + off) = *reinterpret_cast<const uint4*>(Blo + gb);
        }
        __syncthreads();
#pragma unroll
        for (int ks = 0; ks < 4; ks++) {
            const int kl = ks * 16;
            uint32_t ah[2][4], al[2][4];
#pragma unroll
            for (int mt = 0; mt < 2; mt++) {
                uint32_t off = (uint32_t)((wm + mt * 16 + a_row) * TCB_STR + kl + a_col) * 2;
                ldsm_x4(ah[mt], sAh_u + off);
                ldsm_x4(al[mt], sAl_u + off);
            }
#pragma unroll
            for (int ng = 0; ng < 2; ng++) {
                uint32_t bh[4][2], bl[4][2];
#pragma unroll
                for (int nt = 0; nt < 4; nt++) {
                    uint32_t off = (uint32_t)((wn + ng * 32 + nt * 8 + b_row) * TCB_STR + kl + b_col) * 2;
                    ldsm_x2(bh[nt], sBh_u + off);
                    ldsm_x2(bl[nt], sBl_u + off);
                }
#pragma unroll
                for (int mt = 0; mt < 2; mt++)
#pragma unroll
                    for (int nt = 0; nt < 4; nt++) {
                        float* d = acc[mt][ng * 4 + nt];
                        mma_bf16(d, ah[mt], bh[nt]);
                        mma_bf16(d, ah[mt], bl[nt]);
                        mma_bf16(d, al[mt], bh[nt]);
                    }
            }
        }
        __syncthreads();
    }

    // epilogue: fragment layout c0,c1 -> row lane/4, cols 2*(lane%4)+{0,1};
    //           c2,c3 -> row lane/4+8, same cols
    const bool relu = (flags & FLAG_RELU) != 0;
    const bool accu = (flags & FLAG_ACC) != 0;
#pragma unroll
    for (int mt = 0; mt < 2; mt++) {
        int rbase = m0 + wm + mt * 16 + (lane >> 2);
#pragma unroll
        for (int nt = 0; nt < 8; nt++) {
            int c0 = n0 + wn + nt * 8 + (lane & 3) * 2;
#pragma unroll
            for (int half = 0; half < 2; half++) {
                int row = rbase + half * 8;
                if (row >= Mn) continue;
                float v0 = acc[mt][nt][half * 2 + 0];
                float v1 = acc[mt][nt][half * 2 + 1];
                if (c0 < scale_cols)     v0 *= scale;
                if (c0 + 1 < scale_cols) v1 *= scale;
                if (bias) { v0 += bias[c0]; v1 += bias[c0 + 1]; }
                if (relu) { v0 = fmaxf(v0, 0.f); v1 = fmaxf(v1, 0.f); }
                size_t o = (size_t)row * Nn + c0;
                if (accu) { C[o] += v0; C[o + 1] += v1; }
                else      { C[o] = v0;  C[o + 1] = v1; }
            }
        }
    }
}

// ---------------------------------------------------------------------------
// Assemble h rows: cls + wrap
// ---------------------------------------------------------------------------
__global__ void assemble_kernel(const float* __restrict__ cls, float* __restrict__ H)
{
    int j = blockIdx.x;
    int c = threadIdx.x;
    if (j == 0) H[c] = cls[c];
    else        H[(size_t)(NTOK + j) * DMODEL + c] = H[(size_t)j * DMODEL + c];
}

// ---------------------------------------------------------------------------
// LayerNorm into padded XP
// ---------------------------------------------------------------------------
__global__ void ln_pad_kernel(const float* __restrict__ Hin, float* __restrict__ XP,
                              const float* __restrict__ g, const float* __restrict__ b)
{
    int row = blockIdx.x;
    int tid = threadIdx.x;
    if (row < PADF) {
        XP[(size_t)row * DMODEL + tid] = 0.f;
        XP[(size_t)row * DMODEL + tid + 256] = 0.f;
        return;
    }
    const float* x = Hin + (size_t)(row - PADF) * DMODEL;
    float v0 = x[tid], v1 = x[tid + 256];
    __shared__ float s1[256], s2[256];
    s1[tid] = v0 + v1;
    s2[tid] = v0 * v0 + v1 * v1;
    __syncthreads();
    for (int o = 128; o > 0; o >>= 1) {
        if (tid < o) { s1[tid] += s1[tid + o]; s2[tid] += s2[tid + o]; }
        __syncthreads();
    }
    float mean = s1[0] * (1.f / DMODEL);
    float var  = s2[0] * (1.f / DMODEL) - mean * mean;
    float rs = rsqrtf(var + EPSLN);
    XP[(size_t)row * DMODEL + tid]       = (v0 - mean) * rs * g[tid] + b[tid];
    XP[(size_t)row * DMODEL + tid + 256] = (v1 - mean) * rs * g[tid + 256] + b[tid + 256];
}

// ---------------------------------------------------------------------------
// Transpose K part of QKV into g_KT[h][d][n]
// ---------------------------------------------------------------------------
__global__ void ktr_kernel(const float* __restrict__ QKV, float* __restrict__ KT)
{
    __shared__ float tl[64][65];
    int h = blockIdx.y;
    int n0 = blockIdx.x * 64;
    int t = threadIdx.x;
    for (int lin = t; lin < 4096; lin += 256) {
        int r = lin >> 6, i = lin & 63;
        tl[r][i] = QKV[(size_t)(n0 + r) * (3 * DMODEL) + DMODEL + h * DH + i];
    }
    __syncthreads();
    for (int lin = t; lin < 4096; lin += 256) {
        int i = lin >> 6, c = lin & 63;
        KT[(size_t)(h * DH + i) * NP + n0 + c] = tl[c][i];
    }
}

// ---------------------------------------------------------------------------
// Landmarks (means of 33-groups); also writes KL transposed
// ---------------------------------------------------------------------------
__global__ void landmarks_kernel(const float* __restrict__ QKV,
                                 float* __restrict__ QL, float* __restrict__ KL,
                                 float* __restrict__ KLT)
{
    int hm = blockIdx.x;
    int h = hm >> 8, m = hm & 255;
    int tid = threadIdx.x;
    int d = tid & 63;
    int off = (tid < 64) ? 0 : DMODEL;
    size_t base = (size_t)(m * LWIN) * (3 * DMODEL) + off + h * DH + d;
    float s = 0.f;
#pragma unroll
    for (int j = 0; j < LWIN; j++) s += QKV[base + (size_t)j * (3 * DMODEL)];
    s *= (1.0f / LWIN);
    if (tid < 64) {
        QL[(size_t)(h * MLAND + m) * DH + d] = s;
    } else {
        KL[(size_t)(h * MLAND + m) * DH + d] = s;
        KLT[(size_t)h * DH * MLAND + (size_t)d * MLAND + m] = s;
    }
}

// ---------------------------------------------------------------------------
// a2 = softmax(q_l @ k_l^T)
// ---------------------------------------------------------------------------
__global__ void a2_kernel(const float* __restrict__ QL, const float* __restrict__ KL,
                          float* __restrict__ A2)
{
    int m = blockIdx.x, h = blockIdx.y;
    int tid = threadIdx.x;
    __shared__ float q[64];
    __shared__ float red[256];
    if (tid < 64) q[tid] = QL[(size_t)(h * MLAND + m) * DH + tid];
    __syncthreads();
    const float* kr = KL + (size_t)(h * MLAND + tid) * DH;
    float s = 0.f;
#pragma unroll
    for (int i = 0; i < 16; i++) {
        float4 kv = reinterpret_cast<const float4*>(kr)[i];
        float4 qv = reinterpret_cast<const float4*>(q)[i];
        s += kv.x * qv.x + kv.y * qv.y + kv.z * qv.z + kv.w * qv.w;
    }
    red[tid] = s; __syncthreads();
    for (int o = 128; o > 0; o >>= 1) {
        if (tid < o) red[tid] = fmaxf(red[tid], red[tid + o]);
        __syncthreads();
    }
    float mx = red[0]; __syncthreads();
    float e = __expf(s - mx);
    red[tid] = e; __syncthreads();
    for (int o = 128; o > 0; o >>= 1) {
        if (tid < o) red[tid] += red[tid + o];
        __syncthreads();
    }
    float sm = red[0];
    A2[(size_t)(h * MLAND + m) * MLAND + tid] = e / sm;
}

// ---------------------------------------------------------------------------
// pinv scale: 1 / (max rowsum * max colsum) per head
// ---------------------------------------------------------------------------
__global__ void pinv_scale_kernel(const float* __restrict__ A2, float* __restrict__ PS)
{
    int h = blockIdx.x;
    int t = threadIdx.x;
    int w = t >> 5, lane = t & 31;
    const float* Ah = A2 + (size_t)h * 65536;
    __shared__ float rs[256];
    __shared__ float cs2[256];
    for (int r = w; r < 256; r += 8) {
        float s = 0.f;
        for (int j = lane; j < 256; j += 32) s += fabsf(Ah[r * 256 + j]);
        for (int o = 16; o > 0; o >>= 1) s += __shfl_xor_sync(0xffffffffu, s, o);
        if (lane == 0) rs[r] = s;
    }
    float cs = 0.f;
    for (int i = 0; i < 256; i++) cs += fabsf(Ah[i * 256 + t]);
    cs2[t] = cs;
    __syncthreads();
    for (int o = 128; o > 0; o >>= 1) {
        if (t < o) { rs[t] = fmaxf(rs[t], rs[t + o]); cs2[t] = fmaxf(cs2[t], cs2[t + o]); }
        __syncthreads();
    }
    if (t == 0) PS[h] = 1.0f / (rs[0] * cs2[0]);
}

// ---------------------------------------------------------------------------
// pinv transpose-scale: Z0 = A2^T * scale
// ---------------------------------------------------------------------------
__global__ void pinv_tr_kernel(const float* __restrict__ A2, const float* __restrict__ PS,
                               float* __restrict__ Z0)
{
    __shared__ float tl[64][65];
    int h = blockIdx.y;
    int seg = blockIdx.x;
    int bi = (seg >> 2) * 64, bj = (seg & 3) * 64;
    int t = threadIdx.x;
    float inv = PS[h];
    const float* Ah = A2 + (size_t)h * 65536;
    float* Zh = Z0 + (size_t)h * 65536;
    for (int lin = t; lin < 4096; lin += 256) {
        int r = lin >> 6, c = lin & 63;
        tl[r][c] = Ah[(size_t)(bi + r) * 256 + bj + c];
    }
    __syncthreads();
    for (int lin = t; lin < 4096; lin += 256) {
        int r = lin >> 6, c = lin & 63;
        Zh[(size_t)(bj + r) * 256 + bi + c] = tl[c][r] * inv;
    }
}

// ---------------------------------------------------------------------------
// Batched 256^3 matmul: C = alpha*(A@B) + gamma*A (pinv chain)
// ---------------------------------------------------------------------------
__global__ void nk256_kernel(const float* __restrict__ A, const float* __restrict__ B,
                             float* __restrict__ C, float alpha, float gamma)
{
    const float* Ah = A + (size_t)blockIdx.z * 65536;
    const float* Bh = B + (size_t)blockIdx.z * 65536;
    float* Ch = C + (size_t)blockIdx.z * 65536;
    __shared__ float As[16][64];
    __shared__ float Bs[16][64];
    const int bm = blockIdx.y * 64;
    const int bn = blockIdx.x * 64;
    const int tid = threadIdx.x;
    const int tx = tid & 15, ty = tid >> 4;
    const int row0 = ty * 4, col0 = tx * 4;
    float acc[4][4];
#pragma unroll
    for (int i = 0; i < 4; i++)
#pragma unroll
        for (int j = 0; j < 4; j++) acc[i][j] = 0.f;

    for (int k0 = 0; k0 < 256; k0 += 16) {
        {
            int ar = tid >> 2;
            int ac = (tid & 3) << 2;
            float4 v = *reinterpret_cast<const float4*>(Ah + (size_t)(bm + ar) * 256 + k0 + ac);
            As[ac + 0][ar] = v.x; As[ac + 1][ar] = v.y;
            As[ac + 2][ar] = v.z; As[ac + 3][ar] = v.w;
        }
        {
            int br = tid >> 4;
            int bc = (tid & 15) << 2;
            float4 v = *reinterpret_cast<const float4*>(Bh + (size_t)(k0 + br) * 256 + bn + bc);
            *reinterpret_cast<float4*>(&Bs[br][bc]) = v;
        }
        __syncthreads();
#pragma unroll
        for (int k = 0; k < 16; k++) {
            float a[4], b[4];
            *reinterpret_cast<float4*>(a) = *reinterpret_cast<const float4*>(&As[k][row0]);
            *reinterpret_cast<float4*>(b) = *reinterpret_cast<const float4*>(&Bs[k][col0]);
#pragma unroll
            for (int i = 0; i < 4; i++)
#pragma unroll
                for (int j = 0; j < 4; j++) acc[i][j] += a[i] * b[j];
        }
        __syncthreads();
    }
#pragma unroll
    for (int i = 0; i < 4; i++)
#pragma unroll
        for (int j = 0; j < 4; j++) {
            size_t o = (size_t)(bm + row0 + i) * 256 + bn + col0 + j;
            Ch[o] = alpha * acc[i][j] + gamma * Ah[o];
        }
}

// ---------------------------------------------------------------------------
// Fused a3: online-softmax(q_l @ k^T) @ v  -> A3V  (flash style)
// ---------------------------------------------------------------------------
#define A3_KT   0
#define A3_VS   (64 * 264)
#define A3_QS   (A3_VS + 256 * 64)
#define A3_PS   (A3_QS + 16 * 64)
#define A3_M    (A3_PS + 16 * 264)
#define A3_S    (A3_M + 16)
#define A3_SC   (A3_S + 16)
#define A3_RED  (A3_SC + 16)
#define A3_TOT  (A3_RED + 64)

__global__ void a3_fused_kernel(const float* __restrict__ QKV, const float* __restrict__ KT,
                                const float* __restrict__ QL, float* __restrict__ A3V)
{
    extern __shared__ float sm[];
    float* Kt  = sm + A3_KT;
    float* Vs  = sm + A3_VS;
    float* Qs  = sm + A3_QS;
    float* Ps  = sm + A3_PS;
    float* Mr  = sm + A3_M;
    float* Sr  = sm + A3_S;
    float* Scl = sm + A3_SC;
    float* Red = sm + A3_RED;

    int h  = blockIdx.y;
    int m0 = blockIdx.x * 16;
    int t  = threadIdx.x;
    int lane = t & 31, w = t >> 5;

    int la = t >> 6, lc = t & 63;
    int gc = t >> 6, pr = (t >> 4) & 3, td = t & 15;

    for (int lin = t; lin < 16 * 64; lin += 256) {
        int r = lin >> 6, i = lin & 63;
        Qs[r * 64 + i] = QL[(size_t)(h * MLAND + m0 + r) * DH + i];
    }
    if (t < 16) { Mr[t] = -1e30f; Sr[t] = 0.f; }

    float accv[4][4];
#pragma unroll
    for (int i = 0; i < 4; i++)
#pragma unroll
        for (int j = 0; j < 4; j++) accv[i][j] = 0.f;

    for (int n0 = 0; n0 < NP; n0 += 256) {
        for (int lin = t; lin < 4096; lin += 256) {
            int i = lin >> 6, c4 = (lin & 63) << 2;
            *reinterpret_cast<float4*>(&Kt[i * 264 + c4]) =
                *reinterpret_cast<const float4*>(&KT[(size_t)(h * DH + i) * NP + n0 + c4]);
        }
        for (int lin = t; lin < 4096; lin += 256) {
            int r = lin >> 4, c4 = (lin & 15) << 2;
            *reinterpret_cast<float4*>(&Vs[r * 64 + c4]) =
                *reinterpret_cast<const float4*>(&QKV[(size_t)(n0 + r) * (3 * DMODEL) + 2 * DMODEL + h * DH + c4]);
        }
        __syncthreads();

        float lacc[4][4];
#pragma unroll
        for (int i = 0; i < 4; i++)
#pragma unroll
            for (int j = 0; j < 4; j++) lacc[i][j] = 0.f;
#pragma unroll
        for (int i = 0; i < 64; i += 4) {
            float4 aq[4];
#pragma unroll
            for (int rr = 0; rr < 4; rr++)
                aq[rr] = *reinterpret_cast<const float4*>(&Qs[(la * 4 + rr) * 64 + i]);
#pragma unroll
            for (int ii = 0; ii < 4; ii++) {
                float4 b = *reinterpret_cast<const float4*>(&Kt[(i + ii) * 264 + (lc << 2)]);
#pragma unroll
                for (int rr = 0; rr < 4; rr++) {
                    float av = reinterpret_cast<const float*>(&aq[rr])[ii];
                    lacc[rr][0] += av * b.x; lacc[rr][1] += av * b.y;
                    lacc[rr][2] += av * b.z; lacc[rr][3] += av * b.w;
                }
            }
        }
        float pm[4];
#pragma unroll
        for (int rr = 0; rr < 4; rr++)
            pm[rr] = fmaxf(fmaxf(lacc[rr][0], lacc[rr][1]), fmaxf(lacc[rr][2], lacc[rr][3]));
        for (int o = 16; o > 0; o >>= 1)
#pragma unroll
            for (int rr = 0; rr < 4; rr++)
                pm[rr] = fmaxf(pm[rr], __shfl_xor_sync(0xffffffffu, pm[rr], o));
        if (lane == 0)
#pragma unroll
            for (int rr = 0; rr < 4; rr++) Red[w * 4 + rr] = pm[rr];
        __syncthreads();
        if (t < 16) {
            int wb = (t >> 2) * 2;
            float tmax = fmaxf(Red[wb * 4 + (t & 3)], Red[(wb + 1) * 4 + (t & 3)]);
            float oldM = Mr[t], newM = fmaxf(oldM, tmax);
            Scl[t] = __expf(oldM - newM);
            Mr[t] = newM;
        }
        __syncthreads();
        float psum[4];
#pragma unroll
        for (int rr = 0; rr < 4; rr++) {
            float nm = Mr[la * 4 + rr];
            float p0 = __expf(lacc[rr][0] - nm);
            float p1 = __expf(lacc[rr][1] - nm);
            float p2 = __expf(lacc[rr][2] - nm);
            float p3 = __expf(lacc[rr][3] - nm);
            *reinterpret_cast<float4*>(&Ps[(la * 4 + rr) * 264 + (lc << 2)]) =
                make_float4(p0, p1, p2, p3);
            psum[rr] = p0 + p1 + p2 + p3;
        }
        for (int o = 16; o > 0; o >>= 1)
#pragma unroll
            for (int rr = 0; rr < 4; rr++)
                psum[rr] += __shfl_xor_sync(0xffffffffu, psum[rr], o);
        if (lane == 0)
#pragma unroll
            for (int rr = 0; rr < 4; rr++) Red[w * 4 + rr] = psum[rr];
        __syncthreads();
        if (t < 16) {
            int wb = (t >> 2) * 2;
            float ts = Red[wb * 4 + (t & 3)] + Red[(wb + 1) * 4 + (t & 3)];
            Sr[t] = Sr[t] * Scl[t] + ts;
        }
#pragma unroll
        for (int rr = 0; rr < 4; rr++) {
            float sc = Scl[pr * 4 + rr];
            accv[rr][0] *= sc; accv[rr][1] *= sc; accv[rr][2] *= sc; accv[rr][3] *= sc;
        }
#pragma unroll 4
        for (int c = 0; c < 64; c++) {
            int cg = gc * 64 + c;
            float4 v = *reinterpret_cast<const float4*>(&Vs[cg * 64 + (td << 2)]);
#pragma unroll
            for (int rr = 0; rr < 4; rr++) {
                float p = Ps[(pr * 4 + rr) * 264 + cg];
                accv[rr][0] += p * v.x; accv[rr][1] += p * v.y;
                accv[rr][2] += p * v.z; accv[rr][3] += p * v.w;
            }
        }
        __syncthreads();
    }
#pragma unroll
    for (int rr = 0; rr < 4; rr++)
        *reinterpret_cast<float4*>(&sm[gc * 1024 + (pr * 4 + rr) * 64 + (td << 2)]) =
            make_float4(accv[rr][0], accv[rr][1], accv[rr][2], accv[rr][3]);
    __syncthreads();
    for (int lin = t; lin < 1024; lin += 256) {
        int row = lin >> 6, d = lin & 63;
        float v = sm[row * 64 + d] + sm[1024 + row * 64 + d] +
                  sm[2048 + row * 64 + d] + sm[3072 + row * 64 + d];
        A3V[(size_t)(h * MLAND + m0 + row) * DH + d] = v / Sr[row];
    }
}

// ---------------------------------------------------------------------------
// Bm = pinv(a2) @ a3v
// ---------------------------------------------------------------------------
__global__ void bmat_kernel(const float* __restrict__ Z, const float* __restrict__ A3V,
                            float* __restrict__ Bm)
{
    int h = blockIdx.y;
    int m0 = blockIdx.x * 4;
    __shared__ float zs[4][256];
    int tid = threadIdx.x;
    int r = tid >> 6, d = tid & 63;
    for (int lin = tid; lin < 1024; lin += 256) {
        int rr = lin >> 8, k = lin & 255;
        zs[rr][k] = Z[(size_t)h * 65536 + (size_t)(m0 + rr) * 256 + k];
    }
    __syncthreads();
    float acc = 0.f;
    for (int k = 0; k < 256; k++)
        acc += zs[r][k] * A3V[(size_t)(h * MLAND + k) * DH + d];
    Bm[(size_t)(h * MLAND + m0 + r) * DH + d] = acc;
}

// ---------------------------------------------------------------------------
// a1 @ Bm + fused depthwise seq-conv epilogue
// ---------------------------------------------------------------------------
#define A1_QS   0
#define A1_KLT  (64 * 65)
#define A1_PS   (A1_KLT + 64 * 260)
#define A1_BMS  (A1_PS + 64 * 260)
#define A1_WS   (A1_BMS + 256 * 64)
#define A1_TOT  (A1_WS + 40)

__global__ void a1out_kernel(const float* __restrict__ QKV, const float* __restrict__ KLT,
                             const float* __restrict__ Bm, const float* __restrict__ W,
                             float* __restrict__ O)
{
    extern __shared__ float sm[];
    float* Qs  = sm + A1_QS;
    float* KLt = sm + A1_KLT;
    float* Ps  = sm + A1_PS;
    float* Bms = sm + A1_BMS;
    float* ws  = sm + A1_WS;

    int h = blockIdx.y;
    int row0 = blockIdx.x * 64;
    int t = threadIdx.x;

    if (t < 33) ws[t] = W[h * LWIN + t];
    for (int lin = t; lin < 4096; lin += 256) {
        int r = lin >> 6, i = lin & 63;
        Qs[r * 65 + i] = QKV[(size_t)(row0 + r) * (3 * DMODEL) + h * DH + i];
    }
    for (int lin = t; lin < 16384; lin += 256) {
        int i = lin >> 8, m = lin & 255;
        KLt[i * 260 + m] = KLT[(size_t)h * DH * MLAND + lin];
    }
    for (int lin = t; lin < 16384; lin += 256) {
        Bms[lin] = Bm[(size_t)h * MLAND * DH + lin];
    }
    __syncthreads();

    int ty = t >> 5, tx = t & 31;
    float acc[8][8];
#pragma unroll
    for (int i = 0; i < 8; i++)
#pragma unroll
        for (int j = 0; j < 8; j++) acc[i][j] = 0.f;
    for (int i = 0; i < 64; i++) {
        float4 b0 = *reinterpret_cast<const float4*>(&KLt[i * 260 + tx * 8]);
        float4 b1 = *reinterpret_cast<const float4*>(&KLt[i * 260 + tx * 8 + 4]);
#pragma unroll
        for (int j = 0; j < 8; j++) {
            float a = Qs[(ty * 8 + j) * 65 + i];
            acc[j][0] += a * b0.x; acc[j][1] += a * b0.y;
            acc[j][2] += a * b0.z; acc[j][3] += a * b0.w;
            acc[j][4] += a * b1.x; acc[j][5] += a * b1.y;
            acc[j][6] += a * b1.z; acc[j][7] += a * b1.w;
        }
    }
#pragma unroll
    for (int j = 0; j < 8; j++) {
        float m = acc[j][0];
#pragma unroll
        for (int k = 1; k < 8; k++) m = fmaxf(m, acc[j][k]);
        for (int o = 16; o > 0; o >>= 1) m = fmaxf(m, __shfl_xor_sync(0xffffffffu, m, o));
        float s = 0.f;
#pragma unroll
        for (int k = 0; k < 8; k++) { acc[j][k] = __expf(acc[j][k] - m); s += acc[j][k]; }
        for (int o = 16; o > 0; o >>= 1) s += __shfl_xor_sync(0xffffffffu, s, o);
        float inv = 1.0f / s;
        *reinterpret_cast<float4*>(&Ps[(ty * 8 + j) * 260 + tx * 8]) =
            make_float4(acc[j][0] * inv, acc[j][1] * inv, acc[j][2] * inv, acc[j][3] * inv);
        *reinterpret_cast<float4*>(&Ps[(ty * 8 + j) * 260 + tx * 8 + 4]) =
            make_float4(acc[j][4] * inv, acc[j][5] * inv, acc[j][6] * inv, acc[j][7] * inv);
    }
    __syncthreads();

    float* Vc = KLt;
    for (int lin = t; lin < 96 * 64; lin += 256) {
        int r = lin >> 6, c = lin & 63;
        int n = row0 - 16 + r;
        Vc[lin] = (n >= 0 && n < NP)
                    ? QKV[(size_t)n * (3 * DMODEL) + 2 * DMODEL + h * DH + c] : 0.f;
    }

    int rr = t >> 4, cc = t & 15;
    float o4[4][4];
#pragma unroll
    for (int i = 0; i < 4; i++)
#pragma unroll
        for (int j = 0; j < 4; j++) o4[i][j] = 0.f;
    for (int c = 0; c < 256; c++) {
        float4 b = *reinterpret_cast<const float4*>(&Bms[c * 64 + cc * 4]);
#pragma unroll
        for (int k = 0; k < 4; k++) {
            float a = Ps[(rr * 4 + k) * 260 + c];
            o4[k][0] += a * b.x; o4[k][1] += a * b.y;
            o4[k][2] += a * b.z; o4[k][3] += a * b.w;
        }
    }
    __syncthreads();

#pragma unroll
    for (int k = 0; k < 4; k++) {
        int lrow = rr * 4 + k;
        float cv0 = 0.f, cv1 = 0.f, cv2 = 0.f, cv3 = 0.f;
#pragma unroll
        for (int t2 = 0; t2 < LWIN; t2++) {
            float wv = ws[t2];
            float4 v = *reinterpret_cast<const float4*>(&Vc[(lrow + t2) * 64 + cc * 4]);
            cv0 += wv * v.x; cv1 += wv * v.y; cv2 += wv * v.z; cv3 += wv * v.w;
        }
        *reinterpret_cast<float4*>(&O[(size_t)(row0 + lrow) * DMODEL + h * DH + cc * 4]) =
            make_float4(o4[k][0] + cv0, o4[k][1] + cv1, o4[k][2] + cv2, o4[k][3] + cv3);
    }
}

// ---------------------------------------------------------------------------
// PPEG tiled
// ---------------------------------------------------------------------------
#define PPEG_TILE (14 * 14 * 64)
#define PPEG_W7   PPEG_TILE
#define PPEG_W5   (PPEG_W7 + 64 * 49)
#define PPEG_W3   (PPEG_W5 + 64 * 25)
#define PPEG_TOT  (PPEG_W3 + 64 * 9)

__global__ void ppeg_tile_kernel(const float* __restrict__ Hin, float* __restrict__ Hout,
                                 const float* __restrict__ w7, const float* __restrict__ b7,
                                 const float* __restrict__ w5, const float* __restrict__ b5,
                                 const float* __restrict__ w3, const float* __restrict__ b3)
{
    extern __shared__ float sm[];
    float* tile = sm;
    float* ws7 = sm + PPEG_W7;
    float* ws5 = sm + PPEG_W5;
    float* ws3 = sm + PPEG_W3;

    int ti = blockIdx.x;
    int ty0 = (ti / 12) * 8, tx0 = (ti % 12) * 8;
    int cg = blockIdx.y * 64;
    int t = threadIdx.x;

    for (int lin = t; lin < PPEG_TILE; lin += 256) {
        int p = lin >> 6, c = lin & 63;
        int gy = ty0 + p / 14 - 3;
        int gx = tx0 + p % 14 - 3;
        float v = 0.f;
        if ((unsigned)gy < (unsigned)HSQ && (unsigned)gx < (unsigned)HSQ)
            v = Hin[(size_t)(1 + gy * HSQ + gx) * DMODEL + cg + c];
        tile[lin] = v;
    }
    for (int lin = t; lin < 64 * 49; lin += 256) ws7[lin] = w7[(size_t)cg * 49 + lin];
    for (int lin = t; lin < 64 * 25; lin += 256) ws5[lin] = w5[(size_t)cg * 25 + lin];
    for (int lin = t; lin < 64 * 9;  lin += 256) ws3[lin] = w3[(size_t)cg * 9 + lin];
    __syncthreads();

    int c = t & 63, pg = t >> 6;
    float bsum = b7[cg + c] + b5[cg + c] + b3[cg + c];
    for (int q = 0; q < 16; q++) {
        int p = pg * 16 + q;
        int oy = p >> 3, ox = p & 7;
        int gy = ty0 + oy, gx = tx0 + ox;
        if (gy >= HSQ || gx >= HSQ) continue;
        float acc = tile[((oy + 3) * 14 + ox + 3) * 64 + c] + bsum;
#pragma unroll
        for (int a = 0; a < 7; a++)
#pragma unroll
            for (int bq = 0; bq < 7; bq++)
                acc += ws7[c * 49 + a * 7 + bq] * tile[((oy + a) * 14 + ox + bq) * 64 + c];
#pragma unroll
        for (int a = 0; a < 5; a++)
#pragma unroll
            for (int bq = 0; bq < 5; bq++)
                acc += ws5[c * 25 + a * 5 + bq] * tile[((oy + a + 1) * 14 + ox + bq + 1) * 64 + c];
#pragma unroll
        for (int a = 0; a < 3; a++)
#pragma unroll
            for (int bq = 0; bq < 3; bq++)
                acc += ws3[c * 9 + a * 3 + bq] * tile[((oy + a + 2) * 14 + ox + bq + 2) * 64 + c];
        Hout[(size_t)(1 + gy * HSQ + gx) * DMODEL + cg + c] = acc;
    }
}

__global__ void copy_row0_kernel(const float* __restrict__ Hin, float* __restrict__ Hout)
{
    Hout[threadIdx.x] = Hin[threadIdx.x];
}

// ---------------------------------------------------------------------------
// Final head
// ---------------------------------------------------------------------------
__global__ void final_kernel(const float* __restrict__ H, const float* __restrict__ g,
                             const float* __restrict__ b, const float* __restrict__ w,
                             const float* __restrict__ bias2, float* __restrict__ out,
                             int out_size)
{
    int c = threadIdx.x;
    __shared__ float s1[512], s2[512];
    float x = H[c];
    s1[c] = x; s2[c] = x * x;
    __syncthreads();
    for (int o = 256; o > 0; o >>= 1) {
        if (c < o) { s1[c] += s1[c + o]; s2[c] += s2[c + o]; }
        __syncthreads();
    }
    float mean = s1[0] * (1.f / DMODEL);
    float var  = s2[0] * (1.f / DMODEL) - mean * mean;
    float e = (x - mean) * rsqrtf(var + EPSLN) * g[c] + b[c];
    __syncthreads();
    s1[c] = e * w[c * 2 + 0];
    s2[c] = e * w[c * 2 + 1];
    __syncthreads();
    for (int o = 256; o > 0; o >>= 1) {
        if (c < o) { s1[c] += s1[c + o]; s2[c] += s2[c + o]; }
        __syncthreads();
    }
    float l0 = s1[0] + bias2[0];
    float l1 = s2[0] + bias2[1];
    if (c == 0) {
        float m = fmaxf(l0, l1);
        float e0 = expf(l0 - m), e1 = expf(l1 - m);
        float ss = e0 + e1;
        if (out_size > 0) out[0] = l0;
        if (out_size > 1) out[1] = l1;
        if (out_size > 2) out[2] = e0 / ss;
        if (out_size > 3) out[3] = e1 / ss;
        if (out_size > 4) out[4] = (l1 > l0) ? 1.0f : 0.0f;
    }
    if (5 + c < out_size) out[5 + c] = e;
}

// ---------------------------------------------------------------------------
// Host orchestration
// ---------------------------------------------------------------------------
static float* symaddr(const void* sym)
{
    void* p = nullptr;
    cudaGetSymbolAddress(&p, sym);
    return (float*)p;
}
static __nv_bfloat16* symaddr_bf(const void* sym)
{
    void* p = nullptr;
    cudaGetSymbolAddress(&p, sym);
    return (__nv_bfloat16*)p;
}

static cudaStream_t g_side = nullptr;
static cudaEvent_t  g_evf  = nullptr;
static cudaEvent_t  g_evj  = nullptr;

extern "C" void kernel_launch(void* const* d_in, const int* in_sizes, int n_in,
                              void* d_out, int out_size)
{
    if (!g_side) {
        cudaStreamCreateWithFlags(&g_side, cudaStreamNonBlocking);
        cudaEventCreateWithFlags(&g_evf, cudaEventDisableTiming);
        cudaEventCreateWithFlags(&g_evj, cudaEventDisableTiming);
    }

    const float* x       = (const float*)d_in[0];
    const float* fc1_w   = (const float*)d_in[1];
    const float* fc1_b   = (const float*)d_in[2];
    const float* cls     = (const float*)d_in[3];
    const float* ln1_g   = (const float*)d_in[4];
    const float* ln1_b   = (const float*)d_in[5];
    const float* qkv1_w  = (const float*)d_in[6];
    const float* out1_w  = (const float*)d_in[7];
    const float* out1_b  = (const float*)d_in[8];
    const float* conv1_w = (const float*)d_in[9];
    const float* ln2_g   = (const float*)d_in[10];
    const float* ln2_b   = (const float*)d_in[11];
    const float* qkv2_w  = (const float*)d_in[12];
    const float* out2_w  = (const float*)d_in[13];
    const float* out2_b  = (const float*)d_in[14];
    const float* conv2_w = (const float*)d_in[15];
    const float* pg7_w   = (const float*)d_in[16];
    const float* pg7_b   = (const float*)d_in[17];
    const float* pg5_w   = (const float*)d_in[18];
    const float* pg5_b   = (const float*)d_in[19];
    const float* pg3_w   = (const float*)d_in[20];
    const float* pg3_b   = (const float*)d_in[21];
    const float* norm_g  = (const float*)d_in[22];
    const float* norm_b  = (const float*)d_in[23];
    const float* fc2_w   = (const float*)d_in[24];
    const float* fc2_b   = (const float*)d_in[25];

    float* H   = symaddr(g_H);
    float* H2  = symaddr(g_H2);
    float* XP  = symaddr(g_XP);
    float* QKV = symaddr(g_QKV);
    float* KT  = symaddr(g_KT);
    float* QL  = symaddr(g_QL);
    float* KL  = symaddr(g_KL);
    float* KLT = symaddr(g_KLT);
    float* A2  = symaddr(g_A2);
    float* Z0  = symaddr(g_Z0);
    float* Z1  = symaddr(g_Z1);
    float* W1  = symaddr(g_W1);
    float* W2  = symaddr(g_W2);
    float* W3  = symaddr(g_W3);
    float* PS  = symaddr(g_PS);
    float* A3V = symaddr(g_A3V);
    float* Bm  = symaddr(g_Bm);
    float* O   = symaddr(g_O);
    __nv_bfloat16* AH = symaddr_bf(g_AH);
    __nv_bfloat16* AL = symaddr_bf(g_AL);
    __nv_bfloat16* WH = symaddr_bf(g_WH);
    __nv_bfloat16* WL = symaddr_bf(g_WL);

    const int A3_SMEM   = A3_TOT * 4;
    const int A1_SMEM   = A1_TOT * 4;
    const int PPEG_SMEM = PPEG_TOT * 4;
    cudaFuncSetAttribute(a3_fused_kernel, cudaFuncAttributeMaxDynamicSharedMemorySize, A3_SMEM);
    cudaFuncSetAttribute(a1out_kernel,    cudaFuncAttributeMaxDynamicSharedMemorySize, A1_SMEM);
    cudaFuncSetAttribute(ppeg_tile_kernel, cudaFuncAttributeMaxDynamicSharedMemorySize, PPEG_SMEM);
    cudaFuncSetAttribute(tc_gemm_kernel,  cudaFuncAttributeMaxDynamicSharedMemorySize, TCG_SMEM);

    // ---- fc1 + relu via tensor cores (warp mma) ----
    wconv_kernel<<<dim3(DMODEL / 32, INDIM / 32), 256>>>(fc1_w, WH, WL, INDIM, DMODEL);
    aconv_kernel<<<NTOK, 128>>>(x, AH, AL, NTOK, INDIM);
    tc_gemm_kernel<<<dim3(DMODEL / 128, NTOK / 128), 256, TCG_SMEM>>>(
        AH, AL, WH, WL, H + DMODEL, fc1_b, NTOK, DMODEL, INDIM, FLAG_RELU, 0, 1.f);
    assemble_kernel<<<NWRAP + 1, DMODEL>>>(cls, H);

    auto attn = [&](float* Hbuf, const float* lng, const float* lnb, const float* qkvw,
                    const float* outw, const float* outb, const float* convw) {
        ln_pad_kernel<<<NP, 256>>>(Hbuf, XP, lng, lnb);
        // qkv projection via tensor cores (q cols scaled by 0.125)
        wconv_kernel<<<dim3(3 * DMODEL / 32, DMODEL / 32), 256>>>(qkvw, WH, WL, DMODEL, 3 * DMODEL);
        aconv_kernel<<<NP, 128>>>(XP, AH, AL, NP, DMODEL);
        tc_gemm_kernel<<<dim3(3 * DMODEL / 128, NP / 128), 256, TCG_SMEM>>>(
            AH, AL, WH, WL, QKV, nullptr, NP, 3 * DMODEL, DMODEL, 0, DMODEL, 0.125f);
        ktr_kernel<<<dim3(NP / 64, NHEADS), 256>>>(QKV, KT);
        landmarks_kernel<<<NHEADS * MLAND, 128>>>(QKV, QL, KL, KLT);
        a2_kernel<<<dim3(MLAND, NHEADS), 256>>>(QL, KL, A2);

        // fork: pinv chain on side stream, overlapped with a3_fused on main
        cudaEventRecord(g_evf, 0);
        cudaStreamWaitEvent(g_side, g_evf, 0);
        pinv_scale_kernel<<<NHEADS, 256, 0, g_side>>>(A2, PS);
        pinv_tr_kernel<<<dim3(16, NHEADS), 256, 0, g_side>>>(A2, PS, Z0);
        float* zi = Z0;
        float* zo = Z1;
        for (int it = 0; it < 6; it++) {
            nk256_kernel<<<dim3(4, 4, NHEADS), 256, 0, g_side>>>(A2, zi, W1, 1.f, 0.f);
            nk256_kernel<<<dim3(4, 4, NHEADS), 256, 0, g_side>>>(W1, W1, W2, -1.f, 7.f);
            nk256_kernel<<<dim3(4, 4, NHEADS), 256, 0, g_side>>>(W1, W2, W3, -1.f, 15.f);
            nk256_kernel<<<dim3(4, 4, NHEADS), 256, 0, g_side>>>(zi, W3, zo, -0.25f, 3.25f);
            float* t = zi; zi = zo; zo = t;
        }
        cudaEventRecord(g_evj, g_side);

        a3_fused_kernel<<<dim3(MLAND / 16, NHEADS), 256, A3_SMEM>>>(QKV, KT, QL, A3V);

        // join
        cudaStreamWaitEvent(0, g_evj, 0);
        bmat_kernel<<<dim3(MLAND / 4, NHEADS), 256>>>(zi, A3V, Bm);
        a1out_kernel<<<dim3(NP / 64, NHEADS), 256, A1_SMEM>>>(QKV, KLT, Bm, convw, O);
        // out projection via tensor cores (accumulate into Hbuf)
        wconv_kernel<<<dim3(DMODEL / 32, DMODEL / 32), 256>>>(outw, WH, WL, DMODEL, DMODEL);
        aconv_kernel<<<8320, 128>>>(O + (size_t)PADF * DMODEL, AH, AL, NHTOK, DMODEL);
        tc_gemm_kernel<<<dim3(DMODEL / 128, 65), 256, TCG_SMEM>>>(
            AH, AL, WH, WL, Hbuf, outb, NHTOK, DMODEL, DMODEL, FLAG_ACC, 0, 1.f);
    };

    attn(H, ln1_g, ln1_b, qkv1_w, out1_w, out1_b, conv1_w);

    ppeg_tile_kernel<<<dim3(144, NHEADS), 256, PPEG_SMEM>>>(
        H, H2, pg7_w, pg7_b, pg5_w, pg5_b, pg3_w, pg3_b);
    copy_row0_kernel<<<1, DMODEL>>>(H, H2);

    attn(H2, ln2_g, ln2_b, qkv2_w, out2_w, out2_b, conv2_w);

    final_kernel<<<1, DMODEL>>>(H2, norm_g, norm_b, fc2_w, fc2_b, (float*)d_out, out_size);
}

// round 7
// speedup vs baseline: 3.1907x; 1.0828x over previous
#include <cuda_runtime.h>
#include <cuda_bf16.h>
#include <math.h>
#include <stdint.h>

// ---------------------------------------------------------------------------
// Problem constants
// ---------------------------------------------------------------------------
#define NTOK   8192
#define INDIM  1024
#define DMODEL 512
#define NHEADS 8
#define DH     64
#define MLAND  256
#define LWIN   33
#define NP     8448          // padded attention length
#define NHTOK  8282          // tokens incl cls
#define PADF   166
#define HSQ    91
#define NFEAT  8281
#define NWRAP  89
#define EPSLN  1e-5f

#define FLAG_RELU 1
#define FLAG_ACC  2

// ---------------------------------------------------------------------------
// Scratch (device globals)
// ---------------------------------------------------------------------------
__device__ float g_H  [NHTOK * DMODEL];
__device__ float g_H2 [NHTOK * DMODEL];
__device__ float g_XP [NP * DMODEL];
__device__ float g_QKV[NP * 3 * DMODEL];
__device__ float g_QL [NHEADS * MLAND * DH];
__device__ float g_KL [NHEADS * MLAND * DH];
__device__ float g_A2 [NHEADS * MLAND * MLAND];
__device__ float g_Z0 [NHEADS * MLAND * MLAND];
__device__ float g_Z1 [NHEADS * MLAND * MLAND];
__device__ float g_W1 [NHEADS * MLAND * MLAND];
__device__ float g_W2 [NHEADS * MLAND * MLAND];
__device__ float g_W3 [NHEADS * MLAND * MLAND];
__device__ float g_PS [NHEADS];
__device__ float g_A3V[NHEADS * MLAND * DH];
__device__ float g_Bm [NHEADS * MLAND * DH];
__device__ float g_O  [NP * DMODEL];
__device__ float g_S  [NHEADS * NP * MLAND];     // logits scratch (S3 then S1)
// bf16 hi/lo staging
__device__ __nv_bfloat16 g_AH[NP * INDIM];       // also reused: Qh [8][NP][64] + Kh [8][NP][64]
__device__ __nv_bfloat16 g_AL[NP * INDIM];
__device__ __nv_bfloat16 g_WH[3 * DMODEL * DMODEL];
__device__ __nv_bfloat16 g_WL[3 * DMODEL * DMODEL];
__device__ __nv_bfloat16 g_QLH[NHEADS * MLAND * DH];
__device__ __nv_bfloat16 g_QLL[NHEADS * MLAND * DH];
__device__ __nv_bfloat16 g_KLH[NHEADS * MLAND * DH];
__device__ __nv_bfloat16 g_KLL[NHEADS * MLAND * DH];

#define QKOFF (NHEADS * NP * DH)   // offset of K half inside g_AH/g_AL reuse

// ---------------------------------------------------------------------------
// warp-mma helpers (sm_80+ PTX)
// ---------------------------------------------------------------------------
__device__ __forceinline__ uint32_t smem_u32(const void* p)
{
    uint32_t a;
    asm("{ .reg .u64 t; cvta.to.shared.u64 t, %1; cvt.u32.u64 %0, t; }" : "=r"(a) : "l"(p));
    return a;
}
__device__ __forceinline__ void ldsm_x4(uint32_t* r, uint32_t addr)
{
    asm volatile("ldmatrix.sync.aligned.m8n8.x4.shared.b16 {%0,%1,%2,%3}, [%4];"
                 : "=r"(r[0]), "=r"(r[1]), "=r"(r[2]), "=r"(r[3]) : "r"(addr));
}
__device__ __forceinline__ void ldsm_x2(uint32_t* r, uint32_t addr)
{
    asm volatile("ldmatrix.sync.aligned.m8n8.x2.shared.b16 {%0,%1}, [%2];"
                 : "=r"(r[0]), "=r"(r[1]) : "r"(addr));
}
__device__ __forceinline__ void mma_bf16(float* d, const uint32_t* a, const uint32_t* b)
{
    asm volatile("mma.sync.aligned.m16n8k16.row.col.f32.bf16.bf16.f32 "
                 "{%0,%1,%2,%3}, {%4,%5,%6,%7}, {%8,%9}, {%0,%1,%2,%3};"
                 : "+f"(d[0]), "+f"(d[1]), "+f"(d[2]), "+f"(d[3])
                 : "r"(a[0]), "r"(a[1]), "r"(a[2]), "r"(a[3]), "r"(b[0]), "r"(b[1]));
}

// ---------------------------------------------------------------------------
// Weight convert+transpose: W [K][N] f32 -> Whi/Wlo [N][K] bf16
// ---------------------------------------------------------------------------
__global__ void wconv_kernel(const float* __restrict__ W,
                             __nv_bfloat16* __restrict__ Whi, __nv_bfloat16* __restrict__ Wlo,
                             int K, int N)
{
    __shared__ float tl[32][33];
    int kb = blockIdx.y * 32, nb = blockIdx.x * 32;
    int t = threadIdx.x;
    for (int i = t; i < 1024; i += 256) {
        int r = i >> 5, c = i & 31;
        tl[r][c] = W[(size_t)(kb + r) * N + nb + c];
    }
    __syncthreads();
    for (int i = t; i < 1024; i += 256) {
        int n = i >> 5, k = i & 31;
        float v = tl[k][n];
        __nv_bfloat16 h = __float2bfloat16(v);
        float lo = v - __bfloat162float(h);
        size_t o = (size_t)(nb + n) * K + kb + k;
        Whi[o] = h;
        Wlo[o] = __float2bfloat16(lo);
    }
}

// ---------------------------------------------------------------------------
// Activation convert: A [Min][K] f32 -> Ahi/Alo [Mpad][K] bf16 (zero pad rows)
// ---------------------------------------------------------------------------
__global__ void aconv_kernel(const float* __restrict__ A,
                             __nv_bfloat16* __restrict__ Ahi, __nv_bfloat16* __restrict__ Alo,
                             int Min, int Kn)
{
    int r = blockIdx.x;
    size_t base = (size_t)r * Kn;
    if (r >= Min) {
        __nv_bfloat162 z = __float2bfloat162_rn(0.f);
        for (int c = threadIdx.x * 2; c < Kn; c += 256) {
            *reinterpret_cast<__nv_bfloat162*>(Ahi + base + c) = z;
            *reinterpret_cast<__nv_bfloat162*>(Alo + base + c) = z;
        }
        return;
    }
    for (int c = threadIdx.x * 2; c < Kn; c += 256) {
        float2 v = *reinterpret_cast<const float2*>(A + base + c);
        __nv_bfloat16 h0 = __float2bfloat16(v.x);
        __nv_bfloat16 h1 = __float2bfloat16(v.y);
        float l0 = v.x - __bfloat162float(h0);
        float l1 = v.y - __bfloat162float(h1);
        __nv_bfloat162 hp; hp.x = h0; hp.y = h1;
        __nv_bfloat162 lp; lp.x = __float2bfloat16(l0); lp.y = __float2bfloat16(l1);
        *reinterpret_cast<__nv_bfloat162*>(Ahi + base + c) = hp;
        *reinterpret_cast<__nv_bfloat162*>(Alo + base + c) = lp;
    }
}

// ---------------------------------------------------------------------------
// Q/K split: QKV f32 -> Qh/Ql [h][n][64], Kh/Kl [h][n][64] bf16 (into AH/AL)
// ---------------------------------------------------------------------------
__global__ void qk_split_kernel(const float* __restrict__ QKV,
                                __nv_bfloat16* __restrict__ BH, __nv_bfloat16* __restrict__ BL)
{
    int n = blockIdx.x;
    int t = threadIdx.x;
    for (int i = t; i < 1024; i += 256) {
        int part = i >> 9;            // 0 = q, 1 = k
        int hd = i & 511;
        int h = hd >> 6, d = hd & 63;
        float v = QKV[(size_t)n * (3 * DMODEL) + part * DMODEL + hd];
        __nv_bfloat16 hi = __float2bfloat16(v);
        float lo = v - __bfloat162float(hi);
        size_t o = (size_t)part * QKOFF + (size_t)h * NP * DH + (size_t)n * DH + d;
        BH[o] = hi;
        BL[o] = __float2bfloat16(lo);
    }
}

// ---------------------------------------------------------------------------
// warp-MMA GEMM: C[M][N] = op(A @ B^T); A hi/lo [Mpad][K] bf16, B hi/lo [N][K].
// 128x128 CTA tile, 8 warps (4x2), warp tile 32x64, K-chunks of 64.
// ---------------------------------------------------------------------------
#define TCB_STR  72
#define TCG_SMEM (4 * 128 * TCB_STR * 2)  // 73728 bytes

__global__ void __launch_bounds__(256)
tc_gemm_kernel(const __nv_bfloat16* __restrict__ Ahi, const __nv_bfloat16* __restrict__ Alo,
               const __nv_bfloat16* __restrict__ Bhi, const __nv_bfloat16* __restrict__ Blo,
               float* __restrict__ C, const float* __restrict__ bias,
               int Mn, int Nn, int Kn, int flags, int scale_cols, float scale)
{
    extern __shared__ __nv_bfloat16 smb[];
    __nv_bfloat16* sAh = smb;
    __nv_bfloat16* sAl = smb + 128 * TCB_STR;
    __nv_bfloat16* sBh = smb + 2 * 128 * TCB_STR;
    __nv_bfloat16* sBl = smb + 3 * 128 * TCB_STR;

    const int t = threadIdx.x, lane = t & 31, wid = t >> 5;
    const int m0 = blockIdx.y * 128, n0 = blockIdx.x * 128;
    const int wm = (wid & 3) * 32;
    const int wn = (wid >> 2) * 64;

    const uint32_t sAh_u = smem_u32(sAh), sAl_u = smem_u32(sAl);
    const uint32_t sBh_u = smem_u32(sBh), sBl_u = smem_u32(sBl);

    const int a_row = (lane & 7) + ((lane >> 3) & 1) * 8;
    const int a_col = (lane >> 4) * 8;
    const int b_row = lane & 7;
    const int b_col = ((lane >> 3) & 1) * 8;

    float acc[2][8][4];
#pragma unroll
    for (int i = 0; i < 2; i++)
#pragma unroll
        for (int j = 0; j < 8; j++)
#pragma unroll
            for (int k = 0; k < 4; k++) acc[i][j][k] = 0.f;

    for (int k0 = 0; k0 < Kn; k0 += 64) {
        for (int i = t; i < 1024; i += 256) {
            int r = i >> 3, kg = (i & 7) << 3;
            int off = r * TCB_STR + kg;
            size_t ga = (size_t)(m0 + r) * Kn + k0 + kg;
            size_t gb = (size_t)(n0 + r) * Kn + k0 + kg;
            *reinterpret_cast<uint4*>(sAh + off) = *reinterpret_cast<const uint4*>(Ahi + ga);
            *reinterpret_cast<uint4*>(sAl + off) = *reinterpret_cast<const uint4*>(Alo + ga);
            *reinterpret_cast<uint4*>(sBh + off) = *reinterpret_cast<const uint4*>(Bhi + gb);
            *reinterpret_cast<uint4*>(sBl + off) = *reinterpret_cast<const uint4*>(Blo + gb);
        }
        __syncthreads();
#pragma unroll
        for (int ks = 0; ks < 4; ks++) {
            const int kl = ks * 16;
            uint32_t ah[2][4], al[2][4];
#pragma unroll
            for (int mt = 0; mt < 2; mt++) {
                uint32_t off = (uint32_t)((wm + mt * 16 + a_row) * TCB_STR + kl + a_col) * 2;
                ldsm_x4(ah[mt], sAh_u + off);
                ldsm_x4(al[mt], sAl_u + off);
            }
#pragma unroll
            for (int ng = 0; ng < 2; ng++) {
                uint32_t bh[4][2], bl[4][2];
#pragma unroll
                for (int nt = 0; nt < 4; nt++) {
                    uint32_t off = (uint32_t)((wn + ng * 32 + nt * 8 + b_row) * TCB_STR + kl + b_col) * 2;
                    ldsm_x2(bh[nt], sBh_u + off);
                    ldsm_x2(bl[nt], sBl_u + off);
                }
#pragma unroll
                for (int mt = 0; mt < 2; mt++)
#pragma unroll
                    for (int nt = 0; nt < 4; nt++) {
                        float* d = acc[mt][ng * 4 + nt];
                        mma_bf16(d, ah[mt], bh[nt]);
                        mma_bf16(d, ah[mt], bl[nt]);
                        mma_bf16(d, al[mt], bh[nt]);
                    }
            }
        }
        __syncthreads();
    }

    const bool relu = (flags & FLAG_RELU) != 0;
    const bool accu = (flags & FLAG_ACC) != 0;
#pragma unroll
    for (int mt = 0; mt < 2; mt++) {
        int rbase = m0 + wm + mt * 16 + (lane >> 2);
#pragma unroll
        for (int nt = 0; nt < 8; nt++) {
            int c0 = n0 + wn + nt * 8 + (lane & 3) * 2;
#pragma unroll
            for (int half = 0; half < 2; half++) {
                int row = rbase + half * 8;
                if (row >= Mn) continue;
                float v0 = acc[mt][nt][half * 2 + 0];
                float v1 = acc[mt][nt][half * 2 + 1];
                if (c0 < scale_cols)     v0 *= scale;
                if (c0 + 1 < scale_cols) v1 *= scale;
                if (bias) { v0 += bias[c0]; v1 += bias[c0 + 1]; }
                if (relu) { v0 = fmaxf(v0, 0.f); v1 = fmaxf(v1, 0.f); }
                size_t o = (size_t)row * Nn + c0;
                if (accu) { C[o] += v0; C[o + 1] += v1; }
                else      { C[o] = v0;  C[o + 1] = v1; }
            }
        }
    }
}

// ---------------------------------------------------------------------------
// Batched logits MMA (K=64, one chunk): C[b][m][n] = A[b] @ B[b]^T
// A hi/lo rows [M][64], B hi/lo rows [N][64]; per-batch strides.
// ---------------------------------------------------------------------------
__global__ void __launch_bounds__(256)
slogits_kernel(const __nv_bfloat16* __restrict__ Ahi, const __nv_bfloat16* __restrict__ Alo,
               const __nv_bfloat16* __restrict__ Bhi, const __nv_bfloat16* __restrict__ Blo,
               float* __restrict__ C,
               size_t strideA, size_t strideB, size_t strideC, int ldc)
{
    extern __shared__ __nv_bfloat16 smb[];
    __nv_bfloat16* sAh = smb;
    __nv_bfloat16* sAl = smb + 128 * TCB_STR;
    __nv_bfloat16* sBh = smb + 2 * 128 * TCB_STR;
    __nv_bfloat16* sBl = smb + 3 * 128 * TCB_STR;

    const int t = threadIdx.x, lane = t & 31, wid = t >> 5;
    const int m0 = blockIdx.y * 128, n0 = blockIdx.x * 128;
    const int b = blockIdx.z;
    const __nv_bfloat16* Ah = Ahi + (size_t)b * strideA;
    const __nv_bfloat16* Al = Alo + (size_t)b * strideA;
    const __nv_bfloat16* Bh = Bhi + (size_t)b * strideB;
    const __nv_bfloat16* Bl = Blo + (size_t)b * strideB;
    float* Cb = C + (size_t)b * strideC;

    const int wm = (wid & 3) * 32;
    const int wn = (wid >> 2) * 64;

    const uint32_t sAh_u = smem_u32(sAh), sAl_u = smem_u32(sAl);
    const uint32_t sBh_u = smem_u32(sBh), sBl_u = smem_u32(sBl);

    const int a_row = (lane & 7) + ((lane >> 3) & 1) * 8;
    const int a_col = (lane >> 4) * 8;
    const int b_row = lane & 7;
    const int b_col = ((lane >> 3) & 1) * 8;

    float acc[2][8][4];
#pragma unroll
    for (int i = 0; i < 2; i++)
#pragma unroll
        for (int j = 0; j < 8; j++)
#pragma unroll
            for (int k = 0; k < 4; k++) acc[i][j][k] = 0.f;

    for (int i = t; i < 1024; i += 256) {
        int r = i >> 3, kg = (i & 7) << 3;
        int off = r * TCB_STR + kg;
        size_t ga = (size_t)(m0 + r) * DH + kg;
        size_t gb = (size_t)(n0 + r) * DH + kg;
        *reinterpret_cast<uint4*>(sAh + off) = *reinterpret_cast<const uint4*>(Ah + ga);
        *reinterpret_cast<uint4*>(sAl + off) = *reinterpret_cast<const uint4*>(Al + ga);
        *reinterpret_cast<uint4*>(sBh + off) = *reinterpret_cast<const uint4*>(Bh + gb);
        *reinterpret_cast<uint4*>(sBl + off) = *reinterpret_cast<const uint4*>(Bl + gb);
    }
    __syncthreads();
#pragma unroll
    for (int ks = 0; ks < 4; ks++) {
        const int kl = ks * 16;
        uint32_t ah[2][4], al[2][4];
#pragma unroll
        for (int mt = 0; mt < 2; mt++) {
            uint32_t off = (uint32_t)((wm + mt * 16 + a_row) * TCB_STR + kl + a_col) * 2;
            ldsm_x4(ah[mt], sAh_u + off);
            ldsm_x4(al[mt], sAl_u + off);
        }
#pragma unroll
        for (int ng = 0; ng < 2; ng++) {
            uint32_t bh[4][2], bl[4][2];
#pragma unroll
            for (int nt = 0; nt < 4; nt++) {
                uint32_t off = (uint32_t)((wn + ng * 32 + nt * 8 + b_row) * TCB_STR + kl + b_col) * 2;
                ldsm_x2(bh[nt], sBh_u + off);
                ldsm_x2(bl[nt], sBl_u + off);
            }
#pragma unroll
            for (int mt = 0; mt < 2; mt++)
#pragma unroll
                for (int nt = 0; nt < 4; nt++) {
                    float* d = acc[mt][nt + ng * 4];
                    mma_bf16(d, ah[mt], bh[nt]);
                    mma_bf16(d, ah[mt], bl[nt]);
                    mma_bf16(d, al[mt], bh[nt]);
                }
        }
    }

#pragma unroll
    for (int mt = 0; mt < 2; mt++) {
        int rbase = m0 + wm + mt * 16 + (lane >> 2);
#pragma unroll
        for (int nt = 0; nt < 8; nt++) {
            int c0 = n0 + wn + nt * 8 + (lane & 3) * 2;
#pragma unroll
            for (int half = 0; half < 2; half++) {
                int row = rbase + half * 8;
                size_t o = (size_t)row * ldc + c0;
                Cb[o]     = acc[mt][nt][half * 2 + 0];
                Cb[o + 1] = acc[mt][nt][half * 2 + 1];
            }
        }
    }
}

// ---------------------------------------------------------------------------
// Assemble h rows: cls + wrap
// ---------------------------------------------------------------------------
__global__ void assemble_kernel(const float* __restrict__ cls, float* __restrict__ H)
{
    int j = blockIdx.x;
    int c = threadIdx.x;
    if (j == 0) H[c] = cls[c];
    else        H[(size_t)(NTOK + j) * DMODEL + c] = H[(size_t)j * DMODEL + c];
}

// ---------------------------------------------------------------------------
// LayerNorm into padded XP
// ---------------------------------------------------------------------------
__global__ void ln_pad_kernel(const float* __restrict__ Hin, float* __restrict__ XP,
                              const float* __restrict__ g, const float* __restrict__ b)
{
    int row = blockIdx.x;
    int tid = threadIdx.x;
    if (row < PADF) {
        XP[(size_t)row * DMODEL + tid] = 0.f;
        XP[(size_t)row * DMODEL + tid + 256] = 0.f;
        return;
    }
    const float* x = Hin + (size_t)(row - PADF) * DMODEL;
    float v0 = x[tid], v1 = x[tid + 256];
    __shared__ float s1[256], s2[256];
    s1[tid] = v0 + v1;
    s2[tid] = v0 * v0 + v1 * v1;
    __syncthreads();
    for (int o = 128; o > 0; o >>= 1) {
        if (tid < o) { s1[tid] += s1[tid + o]; s2[tid] += s2[tid + o]; }
        __syncthreads();
    }
    float mean = s1[0] * (1.f / DMODEL);
    float var  = s2[0] * (1.f / DMODEL) - mean * mean;
    float rs = rsqrtf(var + EPSLN);
    XP[(size_t)row * DMODEL + tid]       = (v0 - mean) * rs * g[tid] + b[tid];
    XP[(size_t)row * DMODEL + tid + 256] = (v1 - mean) * rs * g[tid + 256] + b[tid + 256];
}

// ---------------------------------------------------------------------------
// Landmarks: means of 33-groups; f32 QL/KL + bf16 hi/lo copies
// ---------------------------------------------------------------------------
__global__ void landmarks_kernel(const float* __restrict__ QKV,
                                 float* __restrict__ QL, float* __restrict__ KL,
                                 __nv_bfloat16* __restrict__ QLH, __nv_bfloat16* __restrict__ QLL,
                                 __nv_bfloat16* __restrict__ KLH, __nv_bfloat16* __restrict__ KLL)
{
    int hm = blockIdx.x;
    int h = hm >> 8, m = hm & 255;
    int tid = threadIdx.x;
    int d = tid & 63;
    int off = (tid < 64) ? 0 : DMODEL;
    size_t base = (size_t)(m * LWIN) * (3 * DMODEL) + off + h * DH + d;
    float s = 0.f;
#pragma unroll
    for (int j = 0; j < LWIN; j++) s += QKV[base + (size_t)j * (3 * DMODEL)];
    s *= (1.0f / LWIN);
    __nv_bfloat16 hi = __float2bfloat16(s);
    __nv_bfloat16 lo = __float2bfloat16(s - __bfloat162float(hi));
    size_t o = (size_t)(h * MLAND + m) * DH + d;
    if (tid < 64) {
        QL[o] = s; QLH[o] = hi; QLL[o] = lo;
    } else {
        KL[o] = s; KLH[o] = hi; KLL[o] = lo;
    }
}

// ---------------------------------------------------------------------------
// a2 = softmax(q_l @ k_l^T)
// ---------------------------------------------------------------------------
__global__ void a2_kernel(const float* __restrict__ QL, const float* __restrict__ KL,
                          float* __restrict__ A2)
{
    int m = blockIdx.x, h = blockIdx.y;
    int tid = threadIdx.x;
    __shared__ float q[64];
    __shared__ float red[256];
    if (tid < 64) q[tid] = QL[(size_t)(h * MLAND + m) * DH + tid];
    __syncthreads();
    const float* kr = KL + (size_t)(h * MLAND + tid) * DH;
    float s = 0.f;
#pragma unroll
    for (int i = 0; i < 16; i++) {
        float4 kv = reinterpret_cast<const float4*>(kr)[i];
        float4 qv = reinterpret_cast<const float4*>(q)[i];
        s += kv.x * qv.x + kv.y * qv.y + kv.z * qv.z + kv.w * qv.w;
    }
    red[tid] = s; __syncthreads();
    for (int o = 128; o > 0; o >>= 1) {
        if (tid < o) red[tid] = fmaxf(red[tid], red[tid + o]);
        __syncthreads();
    }
    float mx = red[0]; __syncthreads();
    float e = __expf(s - mx);
    red[tid] = e; __syncthreads();
    for (int o = 128; o > 0; o >>= 1) {
        if (tid < o) red[tid] += red[tid + o];
        __syncthreads();
    }
    float sm = red[0];
    A2[(size_t)(h * MLAND + m) * MLAND + tid] = e / sm;
}

// ---------------------------------------------------------------------------
// pinv scale + transpose + NK256 chain (unchanged)
// ---------------------------------------------------------------------------
__global__ void pinv_scale_kernel(const float* __restrict__ A2, float* __restrict__ PS)
{
    int h = blockIdx.x;
    int t = threadIdx.x;
    int w = t >> 5, lane = t & 31;
    const float* Ah = A2 + (size_t)h * 65536;
    __shared__ float rs[256];
    __shared__ float cs2[256];
    for (int r = w; r < 256; r += 8) {
        float s = 0.f;
        for (int j = lane; j < 256; j += 32) s += fabsf(Ah[r * 256 + j]);
        for (int o = 16; o > 0; o >>= 1) s += __shfl_xor_sync(0xffffffffu, s, o);
        if (lane == 0) rs[r] = s;
    }
    float cs = 0.f;
    for (int i = 0; i < 256; i++) cs += fabsf(Ah[i * 256 + t]);
    cs2[t] = cs;
    __syncthreads();
    for (int o = 128; o > 0; o >>= 1) {
        if (t < o) { rs[t] = fmaxf(rs[t], rs[t + o]); cs2[t] = fmaxf(cs2[t], cs2[t + o]); }
        __syncthreads();
    }
    if (t == 0) PS[h] = 1.0f / (rs[0] * cs2[0]);
}

__global__ void pinv_tr_kernel(const float* __restrict__ A2, const float* __restrict__ PS,
                               float* __restrict__ Z0)
{
    __shared__ float tl[64][65];
    int h = blockIdx.y;
    int seg = blockIdx.x;
    int bi = (seg >> 2) * 64, bj = (seg & 3) * 64;
    int t = threadIdx.x;
    float inv = PS[h];
    const float* Ah = A2 + (size_t)h * 65536;
    float* Zh = Z0 + (size_t)h * 65536;
    for (int lin = t; lin < 4096; lin += 256) {
        int r = lin >> 6, c = lin & 63;
        tl[r][c] = Ah[(size_t)(bi + r) * 256 + bj + c];
    }
    __syncthreads();
    for (int lin = t; lin < 4096; lin += 256) {
        int r = lin >> 6, c = lin & 63;
        Zh[(size_t)(bj + r) * 256 + bi + c] = tl[c][r] * inv;
    }
}

__global__ void nk256_kernel(const float* __restrict__ A, const float* __restrict__ B,
                             float* __restrict__ C, float alpha, float gamma)
{
    const float* Ah = A + (size_t)blockIdx.z * 65536;
    const float* Bh = B + (size_t)blockIdx.z * 65536;
    float* Ch = C + (size_t)blockIdx.z * 65536;
    __shared__ float As[16][64];
    __shared__ float Bs[16][64];
    const int bm = blockIdx.y * 64;
    const int bn = blockIdx.x * 64;
    const int tid = threadIdx.x;
    const int tx = tid & 15, ty = tid >> 4;
    const int row0 = ty * 4, col0 = tx * 4;
    float acc[4][4];
#pragma unroll
    for (int i = 0; i < 4; i++)
#pragma unroll
        for (int j = 0; j < 4; j++) acc[i][j] = 0.f;

    for (int k0 = 0; k0 < 256; k0 += 16) {
        {
            int ar = tid >> 2;
            int ac = (tid & 3) << 2;
            float4 v = *reinterpret_cast<const float4*>(Ah + (size_t)(bm + ar) * 256 + k0 + ac);
            As[ac + 0][ar] = v.x; As[ac + 1][ar] = v.y;
            As[ac + 2][ar] = v.z; As[ac + 3][ar] = v.w;
        }
        {
            int br = tid >> 4;
            int bc = (tid & 15) << 2;
            float4 v = *reinterpret_cast<const float4*>(Bh + (size_t)(k0 + br) * 256 + bn + bc);
            *reinterpret_cast<float4*>(&Bs[br][bc]) = v;
        }
        __syncthreads();
#pragma unroll
        for (int k = 0; k < 16; k++) {
            float a[4], b[4];
            *reinterpret_cast<float4*>(a) = *reinterpret_cast<const float4*>(&As[k][row0]);
            *reinterpret_cast<float4*>(b) = *reinterpret_cast<const float4*>(&Bs[k][col0]);
#pragma unroll
            for (int i = 0; i < 4; i++)
#pragma unroll
                for (int j = 0; j < 4; j++) acc[i][j] += a[i] * b[j];
        }
        __syncthreads();
    }
#pragma unroll
    for (int i = 0; i < 4; i++)
#pragma unroll
        for (int j = 0; j < 4; j++) {
            size_t o = (size_t)(bm + row0 + i) * 256 + bn + col0 + j;
            Ch[o] = alpha * acc[i][j] + gamma * Ah[o];
        }
}

// ---------------------------------------------------------------------------
// a3 softmax + PV: reads precomputed S3[h][m][n], online softmax over n, @ v
// smem: Vs 256x64 + Ps 16x264 + stats -> ~83KB, 2 CTAs/SM
// ---------------------------------------------------------------------------
#define A3_VS   0
#define A3_PS   (256 * 64)                 // 16384
#define A3_M    (A3_PS + 16 * 264)         // 20608
#define A3_S    (A3_M + 16)
#define A3_SC   (A3_S + 16)
#define A3_RED  (A3_SC + 16)
#define A3_TOT  (A3_RED + 64)              // 20720 floats

__global__ void a3sm_pv_kernel(const float* __restrict__ QKV, const float* __restrict__ S,
                               float* __restrict__ A3V)
{
    extern __shared__ float sm[];
    float* Vs  = sm + A3_VS;
    float* Ps  = sm + A3_PS;
    float* Mr  = sm + A3_M;
    float* Sr  = sm + A3_S;
    float* Scl = sm + A3_SC;
    float* Red = sm + A3_RED;

    int h  = blockIdx.y;
    int m0 = blockIdx.x * 16;
    int t  = threadIdx.x;
    int lane = t & 31, w = t >> 5;

    int la = t >> 6, lc = t & 63;
    int gc = t >> 6, pr = (t >> 4) & 3, td = t & 15;

    if (t < 16) { Mr[t] = -1e30f; Sr[t] = 0.f; }

    float accv[4][4];
#pragma unroll
    for (int i = 0; i < 4; i++)
#pragma unroll
        for (int j = 0; j < 4; j++) accv[i][j] = 0.f;

    const float* Sh = S + (size_t)h * MLAND * NP;

    for (int n0 = 0; n0 < NP; n0 += 256) {
        for (int lin = t; lin < 4096; lin += 256) {
            int r = lin >> 4, c4 = (lin & 15) << 2;
            *reinterpret_cast<float4*>(&Vs[r * 64 + c4]) =
                *reinterpret_cast<const float4*>(&QKV[(size_t)(n0 + r) * (3 * DMODEL) + 2 * DMODEL + h * DH + c4]);
        }
        __syncthreads();

        // read logits tile from S3 (gmem, coalesced)
        float lacc[4][4];
#pragma unroll
        for (int rr = 0; rr < 4; rr++) {
            float4 v = *reinterpret_cast<const float4*>(
                &Sh[(size_t)(m0 + la * 4 + rr) * NP + n0 + (lc << 2)]);
            lacc[rr][0] = v.x; lacc[rr][1] = v.y; lacc[rr][2] = v.z; lacc[rr][3] = v.w;
        }
        float pm[4];
#pragma unroll
        for (int rr = 0; rr < 4; rr++)
            pm[rr] = fmaxf(fmaxf(lacc[rr][0], lacc[rr][1]), fmaxf(lacc[rr][2], lacc[rr][3]));
        for (int o = 16; o > 0; o >>= 1)
#pragma unroll
            for (int rr = 0; rr < 4; rr++)
                pm[rr] = fmaxf(pm[rr], __shfl_xor_sync(0xffffffffu, pm[rr], o));
        if (lane == 0)
#pragma unroll
            for (int rr = 0; rr < 4; rr++) Red[w * 4 + rr] = pm[rr];
        __syncthreads();
        if (t < 16) {
            int wb = (t >> 2) * 2;
            float tmax = fmaxf(Red[wb * 4 + (t & 3)], Red[(wb + 1) * 4 + (t & 3)]);
            float oldM = Mr[t], newM = fmaxf(oldM, tmax);
            Scl[t] = __expf(oldM - newM);
            Mr[t] = newM;
        }
        __syncthreads();
        float psum[4];
#pragma unroll
        for (int rr = 0; rr < 4; rr++) {
            float nm = Mr[la * 4 + rr];
            float p0 = __expf(lacc[rr][0] - nm);
            float p1 = __expf(lacc[rr][1] - nm);
            float p2 = __expf(lacc[rr][2] - nm);
            float p3 = __expf(lacc[rr][3] - nm);
            *reinterpret_cast<float4*>(&Ps[(la * 4 + rr) * 264 + (lc << 2)]) =
                make_float4(p0, p1, p2, p3);
            psum[rr] = p0 + p1 + p2 + p3;
        }
        for (int o = 16; o > 0; o >>= 1)
#pragma unroll
            for (int rr = 0; rr < 4; rr++)
                psum[rr] += __shfl_xor_sync(0xffffffffu, psum[rr], o);
        if (lane == 0)
#pragma unroll
            for (int rr = 0; rr < 4; rr++) Red[w * 4 + rr] = psum[rr];
        __syncthreads();
        if (t < 16) {
            int wb = (t >> 2) * 2;
            float ts = Red[wb * 4 + (t & 3)] + Red[(wb + 1) * 4 + (t & 3)];
            Sr[t] = Sr[t] * Scl[t] + ts;
        }
#pragma unroll
        for (int rr = 0; rr < 4; rr++) {
            float sc = Scl[pr * 4 + rr];
            accv[rr][0] *= sc; accv[rr][1] *= sc; accv[rr][2] *= sc; accv[rr][3] *= sc;
        }
#pragma unroll 4
        for (int c = 0; c < 64; c++) {
            int cg = gc * 64 + c;
            float4 v = *reinterpret_cast<const float4*>(&Vs[cg * 64 + (td << 2)]);
#pragma unroll
            for (int rr = 0; rr < 4; rr++) {
                float p = Ps[(pr * 4 + rr) * 264 + cg];
                accv[rr][0] += p * v.x; accv[rr][1] += p * v.y;
                accv[rr][2] += p * v.z; accv[rr][3] += p * v.w;
            }
        }
        __syncthreads();
    }
#pragma unroll
    for (int rr = 0; rr < 4; rr++)
        *reinterpret_cast<float4*>(&sm[gc * 1024 + (pr * 4 + rr) * 64 + (td << 2)]) =
            make_float4(accv[rr][0], accv[rr][1], accv[rr][2], accv[rr][3]);
    __syncthreads();
    for (int lin = t; lin < 1024; lin += 256) {
        int row = lin >> 6, d = lin & 63;
        float v = sm[row * 64 + d] + sm[1024 + row * 64 + d] +
                  sm[2048 + row * 64 + d] + sm[3072 + row * 64 + d];
        A3V[(size_t)(h * MLAND + m0 + row) * DH + d] = v / Sr[row];
    }
}

// ---------------------------------------------------------------------------
// Bm = pinv(a2) @ a3v
// ---------------------------------------------------------------------------
__global__ void bmat_kernel(const float* __restrict__ Z, const float* __restrict__ A3V,
                            float* __restrict__ Bm)
{
    int h = blockIdx.y;
    int m0 = blockIdx.x * 4;
    __shared__ float zs[4][256];
    int tid = threadIdx.x;
    int r = tid >> 6, d = tid & 63;
    for (int lin = tid; lin < 1024; lin += 256) {
        int rr = lin >> 8, k = lin & 255;
        zs[rr][k] = Z[(size_t)h * 65536 + (size_t)(m0 + rr) * 256 + k];
    }
    __syncthreads();
    float acc = 0.f;
    for (int k = 0; k < 256; k++)
        acc += zs[r][k] * A3V[(size_t)(h * MLAND + k) * DH + d];
    Bm[(size_t)(h * MLAND + m0 + r) * DH + d] = acc;
}

// ---------------------------------------------------------------------------
// a1 softmax + @Bm + fused conv: reads S1[h][n][m], 64 rows/block
// smem: Ps 64x260 + Bms 256x64 + Vc 96x64 + ws -> ~157KB
// ---------------------------------------------------------------------------
#define A1_PS   0
#define A1_BMS  (64 * 260)                  // 16640
#define A1_VC   (A1_BMS + 256 * 64)         // 33024
#define A1_WS   (A1_VC + 96 * 64)           // 39168
#define A1_TOT  (A1_WS + 40)                // 39208 floats

__global__ void a1sm_out_kernel(const float* __restrict__ QKV, const float* __restrict__ S,
                                const float* __restrict__ Bm, const float* __restrict__ W,
                                float* __restrict__ O)
{
    extern __shared__ float sm[];
    float* Ps  = sm + A1_PS;
    float* Bms = sm + A1_BMS;
    float* Vc  = sm + A1_VC;
    float* ws  = sm + A1_WS;

    int h = blockIdx.y;
    int row0 = blockIdx.x * 64;
    int t = threadIdx.x;

    if (t < 33) ws[t] = W[h * LWIN + t];
    const float* Sh = S + (size_t)h * NP * MLAND;
    for (int lin = t; lin < 16384; lin += 256) {
        int r = lin >> 8, m = lin & 255;
        Ps[r * 260 + m] = Sh[(size_t)(row0 + r) * MLAND + m];
    }
    for (int lin = t; lin < 16384; lin += 256) {
        Bms[lin] = Bm[(size_t)h * MLAND * DH + lin];
    }
    for (int lin = t; lin < 96 * 64; lin += 256) {
        int r = lin >> 6, c = lin & 63;
        int n = row0 - 16 + r;
        Vc[lin] = (n >= 0 && n < NP)
                    ? QKV[(size_t)n * (3 * DMODEL) + 2 * DMODEL + h * DH + c] : 0.f;
    }
    __syncthreads();

    // softmax over each row's 256 logits (row lives in one warp)
    int ty = t >> 5, tx = t & 31;
#pragma unroll
    for (int j = 0; j < 8; j++) {
        float a[8];
        *reinterpret_cast<float4*>(a)     = *reinterpret_cast<const float4*>(&Ps[(ty * 8 + j) * 260 + tx * 8]);
        *reinterpret_cast<float4*>(a + 4) = *reinterpret_cast<const float4*>(&Ps[(ty * 8 + j) * 260 + tx * 8 + 4]);
        float m = a[0];
#pragma unroll
        for (int k = 1; k < 8; k++) m = fmaxf(m, a[k]);
        for (int o = 16; o > 0; o >>= 1) m = fmaxf(m, __shfl_xor_sync(0xffffffffu, m, o));
        float s = 0.f;
#pragma unroll
        for (int k = 0; k < 8; k++) { a[k] = __expf(a[k] - m); s += a[k]; }
        for (int o = 16; o > 0; o >>= 1) s += __shfl_xor_sync(0xffffffffu, s, o);
        float inv = 1.0f / s;
        *reinterpret_cast<float4*>(&Ps[(ty * 8 + j) * 260 + tx * 8]) =
            make_float4(a[0] * inv, a[1] * inv, a[2] * inv, a[3] * inv);
        *reinterpret_cast<float4*>(&Ps[(ty * 8 + j) * 260 + tx * 8 + 4]) =
            make_float4(a[4] * inv, a[5] * inv, a[6] * inv, a[7] * inv);
    }
    __syncthreads();

    // out = P @ Bm + depthwise conv on v
    int rr = t >> 4, cc = t & 15;
    float o4[4][4];
#pragma unroll
    for (int i = 0; i < 4; i++)
#pragma unroll
        for (int j = 0; j < 4; j++) o4[i][j] = 0.f;
    for (int c = 0; c < 256; c++) {
        float4 b = *reinterpret_cast<const float4*>(&Bms[c * 64 + cc * 4]);
#pragma unroll
        for (int k = 0; k < 4; k++) {
            float a = Ps[(rr * 4 + k) * 260 + c];
            o4[k][0] += a * b.x; o4[k][1] += a * b.y;
            o4[k][2] += a * b.z; o4[k][3] += a * b.w;
        }
    }
#pragma unroll
    for (int k = 0; k < 4; k++) {
        int lrow = rr * 4 + k;
        float cv0 = 0.f, cv1 = 0.f, cv2 = 0.f, cv3 = 0.f;
#pragma unroll
        for (int t2 = 0; t2 < LWIN; t2++) {
            float wv = ws[t2];
            float4 v = *reinterpret_cast<const float4*>(&Vc[(lrow + t2) * 64 + cc * 4]);
            cv0 += wv * v.x; cv1 += wv * v.y; cv2 += wv * v.z; cv3 += wv * v.w;
        }
        *reinterpret_cast<float4*>(&O[(size_t)(row0 + lrow) * DMODEL + h * DH + cc * 4]) =
            make_float4(o4[k][0] + cv0, o4[k][1] + cv1, o4[k][2] + cv2, o4[k][3] + cv3);
    }
}

// ---------------------------------------------------------------------------
// PPEG tiled
// ---------------------------------------------------------------------------
#define PPEG_TILE (14 * 14 * 64)
#define PPEG_W7   PPEG_TILE
#define PPEG_W5   (PPEG_W7 + 64 * 49)
#define PPEG_W3   (PPEG_W5 + 64 * 25)
#define PPEG_TOT  (PPEG_W3 + 64 * 9)

__global__ void ppeg_tile_kernel(const float* __restrict__ Hin, float* __restrict__ Hout,
                                 const float* __restrict__ w7, const float* __restrict__ b7,
                                 const float* __restrict__ w5, const float* __restrict__ b5,
                                 const float* __restrict__ w3, const float* __restrict__ b3)
{
    extern __shared__ float sm[];
    float* tile = sm;
    float* ws7 = sm + PPEG_W7;
    float* ws5 = sm + PPEG_W5;
    float* ws3 = sm + PPEG_W3;

    int ti = blockIdx.x;
    int ty0 = (ti / 12) * 8, tx0 = (ti % 12) * 8;
    int cg = blockIdx.y * 64;
    int t = threadIdx.x;

    for (int lin = t; lin < PPEG_TILE; lin += 256) {
        int p = lin >> 6, c = lin & 63;
        int gy = ty0 + p / 14 - 3;
        int gx = tx0 + p % 14 - 3;
        float v = 0.f;
        if ((unsigned)gy < (unsigned)HSQ && (unsigned)gx < (unsigned)HSQ)
            v = Hin[(size_t)(1 + gy * HSQ + gx) * DMODEL + cg + c];
        tile[lin] = v;
    }
    for (int lin = t; lin < 64 * 49; lin += 256) ws7[lin] = w7[(size_t)cg * 49 + lin];
    for (int lin = t; lin < 64 * 25; lin += 256) ws5[lin] = w5[(size_t)cg * 25 + lin];
    for (int lin = t; lin < 64 * 9;  lin += 256) ws3[lin] = w3[(size_t)cg * 9 + lin];
    __syncthreads();

    int c = t & 63, pg = t >> 6;
    float bsum = b7[cg + c] + b5[cg + c] + b3[cg + c];
    for (int q = 0; q < 16; q++) {
        int p = pg * 16 + q;
        int oy = p >> 3, ox = p & 7;
        int gy = ty0 + oy, gx = tx0 + ox;
        if (gy >= HSQ || gx >= HSQ) continue;
        float acc = tile[((oy + 3) * 14 + ox + 3) * 64 + c] + bsum;
#pragma unroll
        for (int a = 0; a < 7; a++)
#pragma unroll
            for (int bq = 0; bq < 7; bq++)
                acc += ws7[c * 49 + a * 7 + bq] * tile[((oy + a) * 14 + ox + bq) * 64 + c];
#pragma unroll
        for (int a = 0; a < 5; a++)
#pragma unroll
            for (int bq = 0; bq < 5; bq++)
                acc += ws5[c * 25 + a * 5 + bq] * tile[((oy + a + 1) * 14 + ox + bq + 1) * 64 + c];
#pragma unroll
        for (int a = 0; a < 3; a++)
#pragma unroll
            for (int bq = 0; bq < 3; bq++)
                acc += ws3[c * 9 + a * 3 + bq] * tile[((oy + a + 2) * 14 + ox + bq + 2) * 64 + c];
        Hout[(size_t)(1 + gy * HSQ + gx) * DMODEL + cg + c] = acc;
    }
}

__global__ void copy_row0_kernel(const float* __restrict__ Hin, float* __restrict__ Hout)
{
    Hout[threadIdx.x] = Hin[threadIdx.x];
}

// ---------------------------------------------------------------------------
// Final head
// ---------------------------------------------------------------------------
__global__ void final_kernel(const float* __restrict__ H, const float* __restrict__ g,
                             const float* __restrict__ b, const float* __restrict__ w,
                             const float* __restrict__ bias2, float* __restrict__ out,
                             int out_size)
{
    int c = threadIdx.x;
    __shared__ float s1[512], s2[512];
    float x = H[c];
    s1[c] = x; s2[c] = x * x;
    __syncthreads();
    for (int o = 256; o > 0; o >>= 1) {
        if (c < o) { s1[c] += s1[c + o]; s2[c] += s2[c + o]; }
        __syncthreads();
    }
    float mean = s1[0] * (1.f / DMODEL);
    float var  = s2[0] * (1.f / DMODEL) - mean * mean;
    float e = (x - mean) * rsqrtf(var + EPSLN) * g[c] + b[c];
    __syncthreads();
    s1[c] = e * w[c * 2 + 0];
    s2[c] = e * w[c * 2 + 1];
    __syncthreads();
    for (int o = 256; o > 0; o >>= 1) {
        if (c < o) { s1[c] += s1[c + o]; s2[c] += s2[c + o]; }
        __syncthreads();
    }
    float l0 = s1[0] + bias2[0];
    float l1 = s2[0] + bias2[1];
    if (c == 0) {
        float m = fmaxf(l0, l1);
        float e0 = expf(l0 - m), e1 = expf(l1 - m);
        float ss = e0 + e1;
        if (out_size > 0) out[0] = l0;
        if (out_size > 1) out[1] = l1;
        if (out_size > 2) out[2] = e0 / ss;
        if (out_size > 3) out[3] = e1 / ss;
        if (out_size > 4) out[4] = (l1 > l0) ? 1.0f : 0.0f;
    }
    if (5 + c < out_size) out[5 + c] = e;
}

// ---------------------------------------------------------------------------
// Host orchestration
// ---------------------------------------------------------------------------
static float* symaddr(const void* sym)
{
    void* p = nullptr;
    cudaGetSymbolAddress(&p, sym);
    return (float*)p;
}
static __nv_bfloat16* symaddr_bf(const void* sym)
{
    void* p = nullptr;
    cudaGetSymbolAddress(&p, sym);
    return (__nv_bfloat16*)p;
}

static cudaStream_t g_side = nullptr;
static cudaEvent_t  g_evf  = nullptr;
static cudaEvent_t  g_evj  = nullptr;

extern "C" void kernel_launch(void* const* d_in, const int* in_sizes, int n_in,
                              void* d_out, int out_size)
{
    if (!g_side) {
        cudaStreamCreateWithFlags(&g_side, cudaStreamNonBlocking);
        cudaEventCreateWithFlags(&g_evf, cudaEventDisableTiming);
        cudaEventCreateWithFlags(&g_evj, cudaEventDisableTiming);
    }

    const float* x       = (const float*)d_in[0];
    const float* fc1_w   = (const float*)d_in[1];
    const float* fc1_b   = (const float*)d_in[2];
    const float* cls     = (const float*)d_in[3];
    const float* ln1_g   = (const float*)d_in[4];
    const float* ln1_b   = (const float*)d_in[5];
    const float* qkv1_w  = (const float*)d_in[6];
    const float* out1_w  = (const float*)d_in[7];
    const float* out1_b  = (const float*)d_in[8];
    const float* conv1_w = (const float*)d_in[9];
    const float* ln2_g   = (const float*)d_in[10];
    const float* ln2_b   = (const float*)d_in[11];
    const float* qkv2_w  = (const float*)d_in[12];
    const float* out2_w  = (const float*)d_in[13];
    const float* out2_b  = (const float*)d_in[14];
    const float* conv2_w = (const float*)d_in[15];
    const float* pg7_w   = (const float*)d_in[16];
    const float* pg7_b   = (const float*)d_in[17];
    const float* pg5_w   = (const float*)d_in[18];
    const float* pg5_b   = (const float*)d_in[19];
    const float* pg3_w   = (const float*)d_in[20];
    const float* pg3_b   = (const float*)d_in[21];
    const float* norm_g  = (const float*)d_in[22];
    const float* norm_b  = (const float*)d_in[23];
    const float* fc2_w   = (const float*)d_in[24];
    const float* fc2_b   = (const float*)d_in[25];

    float* H   = symaddr(g_H);
    float* H2  = symaddr(g_H2);
    float* XP  = symaddr(g_XP);
    float* QKV = symaddr(g_QKV);
    float* QL  = symaddr(g_QL);
    float* KL  = symaddr(g_KL);
    float* A2  = symaddr(g_A2);
    float* Z0  = symaddr(g_Z0);
    float* Z1  = symaddr(g_Z1);
    float* W1  = symaddr(g_W1);
    float* W2  = symaddr(g_W2);
    float* W3  = symaddr(g_W3);
    float* PS  = symaddr(g_PS);
    float* A3V = symaddr(g_A3V);
    float* Bm  = symaddr(g_Bm);
    float* O   = symaddr(g_O);
    float* S   = symaddr(g_S);
    __nv_bfloat16* AH  = symaddr_bf(g_AH);
    __nv_bfloat16* AL  = symaddr_bf(g_AL);
    __nv_bfloat16* WH  = symaddr_bf(g_WH);
    __nv_bfloat16* WL  = symaddr_bf(g_WL);
    __nv_bfloat16* QLH = symaddr_bf(g_QLH);
    __nv_bfloat16* QLL = symaddr_bf(g_QLL);
    __nv_bfloat16* KLH = symaddr_bf(g_KLH);
    __nv_bfloat16* KLL = symaddr_bf(g_KLL);

    const int A3_SMEM   = A3_TOT * 4;
    const int A1_SMEM   = A1_TOT * 4;
    const int PPEG_SMEM = PPEG_TOT * 4;
    cudaFuncSetAttribute(a3sm_pv_kernel,  cudaFuncAttributeMaxDynamicSharedMemorySize, A3_SMEM);
    cudaFuncSetAttribute(a1sm_out_kernel, cudaFuncAttributeMaxDynamicSharedMemorySize, A1_SMEM);
    cudaFuncSetAttribute(ppeg_tile_kernel, cudaFuncAttributeMaxDynamicSharedMemorySize, PPEG_SMEM);
    cudaFuncSetAttribute(tc_gemm_kernel,  cudaFuncAttributeMaxDynamicSharedMemorySize, TCG_SMEM);
    cudaFuncSetAttribute(slogits_kernel,  cudaFuncAttributeMaxDynamicSharedMemorySize, TCG_SMEM);

    // ---- fc1 + relu via tensor cores ----
    wconv_kernel<<<dim3(DMODEL / 32, INDIM / 32), 256>>>(fc1_w, WH, WL, INDIM, DMODEL);
    aconv_kernel<<<NTOK, 128>>>(x, AH, AL, NTOK, INDIM);
    tc_gemm_kernel<<<dim3(DMODEL / 128, NTOK / 128), 256, TCG_SMEM>>>(
        AH, AL, WH, WL, H + DMODEL, fc1_b, NTOK, DMODEL, INDIM, FLAG_RELU, 0, 1.f);
    assemble_kernel<<<NWRAP + 1, DMODEL>>>(cls, H);

    auto attn = [&](float* Hbuf, const float* lng, const float* lnb, const float* qkvw,
                    const float* outw, const float* outb, const float* convw) {
        ln_pad_kernel<<<NP, 256>>>(Hbuf, XP, lng, lnb);
        wconv_kernel<<<dim3(3 * DMODEL / 32, DMODEL / 32), 256>>>(qkvw, WH, WL, DMODEL, 3 * DMODEL);
        aconv_kernel<<<NP, 128>>>(XP, AH, AL, NP, DMODEL);
        tc_gemm_kernel<<<dim3(3 * DMODEL / 128, NP / 128), 256, TCG_SMEM>>>(
            AH, AL, WH, WL, QKV, nullptr, NP, 3 * DMODEL, DMODEL, 0, DMODEL, 0.125f);
        // stage Q/K as per-head bf16 hi/lo (AH/AL contents now dead)
        qk_split_kernel<<<NP, 256>>>(QKV, AH, AL);
        landmarks_kernel<<<NHEADS * MLAND, 128>>>(QKV, QL, KL, QLH, QLL, KLH, KLL);
        a2_kernel<<<dim3(MLAND, NHEADS), 256>>>(QL, KL, A2);

        // fork: pinv chain on side stream
        cudaEventRecord(g_evf, 0);
        cudaStreamWaitEvent(g_side, g_evf, 0);
        pinv_scale_kernel<<<NHEADS, 256, 0, g_side>>>(A2, PS);
        pinv_tr_kernel<<<dim3(16, NHEADS), 256, 0, g_side>>>(A2, PS, Z0);
        float* zi = Z0;
        float* zo = Z1;
        for (int it = 0; it < 6; it++) {
            nk256_kernel<<<dim3(4, 4, NHEADS), 256, 0, g_side>>>(A2, zi, W1, 1.f, 0.f);
            nk256_kernel<<<dim3(4, 4, NHEADS), 256, 0, g_side>>>(W1, W1, W2, -1.f, 7.f);
            nk256_kernel<<<dim3(4, 4, NHEADS), 256, 0, g_side>>>(W1, W2, W3, -1.f, 15.f);
            nk256_kernel<<<dim3(4, 4, NHEADS), 256, 0, g_side>>>(zi, W3, zo, -0.25f, 3.25f);
            float* t = zi; zi = zo; zo = t;
        }
        cudaEventRecord(g_evj, g_side);

        // S3 = QL @ K^T (per head), then softmax+PV
        slogits_kernel<<<dim3(NP / 128, MLAND / 128, NHEADS), 256, TCG_SMEM>>>(
            QLH, QLL, AH + QKOFF, AL + QKOFF, S,
            (size_t)MLAND * DH, (size_t)NP * DH, (size_t)MLAND * NP, NP);
        a3sm_pv_kernel<<<dim3(MLAND / 16, NHEADS), 256, A3_SMEM>>>(QKV, S, A3V);

        // join pinv
        cudaStreamWaitEvent(0, g_evj, 0);
        bmat_kernel<<<dim3(MLAND / 4, NHEADS), 256>>>(zi, A3V, Bm);

        // S1 = Q @ KL^T (per head), then softmax + @Bm + conv
        slogits_kernel<<<dim3(MLAND / 128, NP / 128, NHEADS), 256, TCG_SMEM>>>(
            AH, AL, KLH, KLL, S,
            (size_t)NP * DH, (size_t)MLAND * DH, (size_t)NP * MLAND, MLAND);
        a1sm_out_kernel<<<dim3(NP / 64, NHEADS), 256, A1_SMEM>>>(QKV, S, Bm, convw, O);

        // out projection via tensor cores (accumulate into Hbuf)
        wconv_kernel<<<dim3(DMODEL / 32, DMODEL / 32), 256>>>(outw, WH, WL, DMODEL, DMODEL);
        aconv_kernel<<<8320, 128>>>(O + (size_t)PADF * DMODEL, AH, AL, NHTOK, DMODEL);
        tc_gemm_kernel<<<dim3(DMODEL / 128, 65), 256, TCG_SMEM>>>(
            AH, AL, WH, WL, Hbuf, outb, NHTOK, DMODEL, DMODEL, FLAG_ACC, 0, 1.f);
    };

    attn(H, ln1_g, ln1_b, qkv1_w, out1_w, out1_b, conv1_w);

    ppeg_tile_kernel<<<dim3(144, NHEADS), 256, PPEG_SMEM>>>(
        H, H2, pg7_w, pg7_b, pg5_w, pg5_b, pg3_w, pg3_b);
    copy_row0_kernel<<<1, DMODEL>>>(H, H2);

    attn(H2, ln2_g, ln2_b, qkv2_w, out2_w, out2_b, conv2_w);

    final_kernel<<<1, DMODEL>>>(H2, norm_g, norm_b, fc2_w, fc2_b, (float*)d_out, out_size);
}

// round 8
// speedup vs baseline: 3.4066x; 1.0677x over previous
#include <cuda_runtime.h>
#include <cuda_bf16.h>
#include <math.h>
#include <stdint.h>

// ---------------------------------------------------------------------------
// Problem constants
// ---------------------------------------------------------------------------
#define NTOK   8192
#define INDIM  1024
#define DMODEL 512
#define NHEADS 8
#define DH     64
#define MLAND  256
#define LWIN   33
#define NP     8448          // padded attention length
#define NHTOK  8282          // tokens incl cls
#define PADF   166
#define HSQ    91
#define NFEAT  8281
#define NWRAP  89
#define EPSLN  1e-5f

#define FLAG_RELU 1
#define FLAG_ACC  2

// ---------------------------------------------------------------------------
// Scratch (device globals)
// ---------------------------------------------------------------------------
__device__ float g_H  [NHTOK * DMODEL];
__device__ float g_H2 [NHTOK * DMODEL];
__device__ float g_XP [NP * DMODEL];
__device__ float g_QKV[NP * 3 * DMODEL];
__device__ float g_QL [NHEADS * MLAND * DH];
__device__ float g_KL [NHEADS * MLAND * DH];
__device__ float g_A2 [NHEADS * MLAND * MLAND];
__device__ float g_Z0 [NHEADS * MLAND * MLAND];
__device__ float g_Z1 [NHEADS * MLAND * MLAND];
__device__ float g_W1 [NHEADS * MLAND * MLAND];
__device__ float g_W2 [NHEADS * MLAND * MLAND];
__device__ float g_W3 [NHEADS * MLAND * MLAND];
__device__ float g_PS [NHEADS];
__device__ float g_A3V[NHEADS * MLAND * DH];
__device__ float g_O  [NP * DMODEL];
__device__ float g_S  [NHEADS * NP * MLAND];     // logits scratch (S3 then S1)
__device__ float g_PVP[8 * NHEADS * MLAND * DH]; // split-K partials
// bf16 hi/lo staging
__device__ __nv_bfloat16 g_AH[NP * INDIM];       // reused: Qh [8][NP][64] + Kh [8][NP][64]
__device__ __nv_bfloat16 g_AL[NP * INDIM];
__device__ __nv_bfloat16 g_WH[3 * DMODEL * DMODEL];
__device__ __nv_bfloat16 g_WL[3 * DMODEL * DMODEL];
__device__ __nv_bfloat16 g_QLH[NHEADS * MLAND * DH];
__device__ __nv_bfloat16 g_QLL[NHEADS * MLAND * DH];
__device__ __nv_bfloat16 g_KLH[NHEADS * MLAND * DH];
__device__ __nv_bfloat16 g_KLL[NHEADS * MLAND * DH];
__device__ __nv_bfloat16 g_VH [NHEADS * NP * DH];
__device__ __nv_bfloat16 g_VL [NHEADS * NP * DH];
__device__ __nv_bfloat16 g_PH [NHEADS * NP * MLAND];
__device__ __nv_bfloat16 g_PL [NHEADS * NP * MLAND];
__device__ __nv_bfloat16 g_BmH[NHEADS * MLAND * DH];
__device__ __nv_bfloat16 g_BmL[NHEADS * MLAND * DH];

#define QKOFF (NHEADS * NP * DH)

// ---------------------------------------------------------------------------
// warp-mma helpers (sm_80+ PTX)
// ---------------------------------------------------------------------------
__device__ __forceinline__ uint32_t smem_u32(const void* p)
{
    uint32_t a;
    asm("{ .reg .u64 t; cvta.to.shared.u64 t, %1; cvt.u32.u64 %0, t; }" : "=r"(a) : "l"(p));
    return a;
}
__device__ __forceinline__ void ldsm_x4(uint32_t* r, uint32_t addr)
{
    asm volatile("ldmatrix.sync.aligned.m8n8.x4.shared.b16 {%0,%1,%2,%3}, [%4];"
                 : "=r"(r[0]), "=r"(r[1]), "=r"(r[2]), "=r"(r[3]) : "r"(addr));
}
__device__ __forceinline__ void ldsm_x2(uint32_t* r, uint32_t addr)
{
    asm volatile("ldmatrix.sync.aligned.m8n8.x2.shared.b16 {%0,%1}, [%2];"
                 : "=r"(r[0]), "=r"(r[1]) : "r"(addr));
}
__device__ __forceinline__ void ldsm_x2_trans(uint32_t* r, uint32_t addr)
{
    asm volatile("ldmatrix.sync.aligned.m8n8.x2.trans.shared.b16 {%0,%1}, [%2];"
                 : "=r"(r[0]), "=r"(r[1]) : "r"(addr));
}
__device__ __forceinline__ void mma_bf16(float* d, const uint32_t* a, const uint32_t* b)
{
    asm volatile("mma.sync.aligned.m16n8k16.row.col.f32.bf16.bf16.f32 "
                 "{%0,%1,%2,%3}, {%4,%5,%6,%7}, {%8,%9}, {%0,%1,%2,%3};"
                 : "+f"(d[0]), "+f"(d[1]), "+f"(d[2]), "+f"(d[3])
                 : "r"(a[0]), "r"(a[1]), "r"(a[2]), "r"(a[3]), "r"(b[0]), "r"(b[1]));
}

// ---------------------------------------------------------------------------
// Weight convert+transpose: W [K][N] f32 -> Whi/Wlo [N][K] bf16
// ---------------------------------------------------------------------------
__global__ void wconv_kernel(const float* __restrict__ W,
                             __nv_bfloat16* __restrict__ Whi, __nv_bfloat16* __restrict__ Wlo,
                             int K, int N)
{
    __shared__ float tl[32][33];
    int kb = blockIdx.y * 32, nb = blockIdx.x * 32;
    int t = threadIdx.x;
    for (int i = t; i < 1024; i += 256) {
        int r = i >> 5, c = i & 31;
        tl[r][c] = W[(size_t)(kb + r) * N + nb + c];
    }
    __syncthreads();
    for (int i = t; i < 1024; i += 256) {
        int n = i >> 5, k = i & 31;
        float v = tl[k][n];
        __nv_bfloat16 h = __float2bfloat16(v);
        float lo = v - __bfloat162float(h);
        size_t o = (size_t)(nb + n) * K + kb + k;
        Whi[o] = h;
        Wlo[o] = __float2bfloat16(lo);
    }
}

// ---------------------------------------------------------------------------
// Activation convert
// ---------------------------------------------------------------------------
__global__ void aconv_kernel(const float* __restrict__ A,
                             __nv_bfloat16* __restrict__ Ahi, __nv_bfloat16* __restrict__ Alo,
                             int Min, int Kn)
{
    int r = blockIdx.x;
    size_t base = (size_t)r * Kn;
    if (r >= Min) {
        __nv_bfloat162 z = __float2bfloat162_rn(0.f);
        for (int c = threadIdx.x * 2; c < Kn; c += 256) {
            *reinterpret_cast<__nv_bfloat162*>(Ahi + base + c) = z;
            *reinterpret_cast<__nv_bfloat162*>(Alo + base + c) = z;
        }
        return;
    }
    for (int c = threadIdx.x * 2; c < Kn; c += 256) {
        float2 v = *reinterpret_cast<const float2*>(A + base + c);
        __nv_bfloat16 h0 = __float2bfloat16(v.x);
        __nv_bfloat16 h1 = __float2bfloat16(v.y);
        float l0 = v.x - __bfloat162float(h0);
        float l1 = v.y - __bfloat162float(h1);
        __nv_bfloat162 hp; hp.x = h0; hp.y = h1;
        __nv_bfloat162 lp; lp.x = __float2bfloat16(l0); lp.y = __float2bfloat16(l1);
        *reinterpret_cast<__nv_bfloat162*>(Ahi + base + c) = hp;
        *reinterpret_cast<__nv_bfloat162*>(Alo + base + c) = lp;
    }
}

// ---------------------------------------------------------------------------
// Q/K/V split: QKV f32 -> Q,K per-head hi/lo (into BH/BL) + V per-head hi/lo
// ---------------------------------------------------------------------------
__global__ void qk_split_kernel(const float* __restrict__ QKV,
                                __nv_bfloat16* __restrict__ BH, __nv_bfloat16* __restrict__ BL,
                                __nv_bfloat16* __restrict__ VH, __nv_bfloat16* __restrict__ VL)
{
    int n = blockIdx.x;
    int t = threadIdx.x;
    for (int i = t; i < 1536; i += 256) {
        int part = i >> 9;            // 0=q, 1=k, 2=v
        int hd = i & 511;
        int h = hd >> 6, d = hd & 63;
        float v = QKV[(size_t)n * (3 * DMODEL) + part * DMODEL + hd];
        __nv_bfloat16 hi = __float2bfloat16(v);
        __nv_bfloat16 lo = __float2bfloat16(v - __bfloat162float(hi));
        size_t o = (size_t)h * NP * DH + (size_t)n * DH + d;
        if (part < 2) {
            BH[(size_t)part * QKOFF + o] = hi;
            BL[(size_t)part * QKOFF + o] = lo;
        } else {
            VH[o] = hi;
            VL[o] = lo;
        }
    }
}

// ---------------------------------------------------------------------------
// warp-MMA GEMM: C[M][N] = op(A @ B^T); 128x128 CTA tile
// ---------------------------------------------------------------------------
#define TCB_STR  72
#define TCG_SMEM (4 * 128 * TCB_STR * 2)  // 73728 bytes

__global__ void __launch_bounds__(256)
tc_gemm_kernel(const __nv_bfloat16* __restrict__ Ahi, const __nv_bfloat16* __restrict__ Alo,
               const __nv_bfloat16* __restrict__ Bhi, const __nv_bfloat16* __restrict__ Blo,
               float* __restrict__ C, const float* __restrict__ bias,
               int Mn, int Nn, int Kn, int flags, int scale_cols, float scale)
{
    extern __shared__ __nv_bfloat16 smb[];
    __nv_bfloat16* sAh = smb;
    __nv_bfloat16* sAl = smb + 128 * TCB_STR;
    __nv_bfloat16* sBh = smb + 2 * 128 * TCB_STR;
    __nv_bfloat16* sBl = smb + 3 * 128 * TCB_STR;

    const int t = threadIdx.x, lane = t & 31, wid = t >> 5;
    const int m0 = blockIdx.y * 128, n0 = blockIdx.x * 128;
    const int wm = (wid & 3) * 32;
    const int wn = (wid >> 2) * 64;

    const uint32_t sAh_u = smem_u32(sAh), sAl_u = smem_u32(sAl);
    const uint32_t sBh_u = smem_u32(sBh), sBl_u = smem_u32(sBl);

    const int a_row = (lane & 7) + ((lane >> 3) & 1) * 8;
    const int a_col = (lane >> 4) * 8;
    const int b_row = lane & 7;
    const int b_col = ((lane >> 3) & 1) * 8;

    float acc[2][8][4];
#pragma unroll
    for (int i = 0; i < 2; i++)
#pragma unroll
        for (int j = 0; j < 8; j++)
#pragma unroll
            for (int k = 0; k < 4; k++) acc[i][j][k] = 0.f;

    for (int k0 = 0; k0 < Kn; k0 += 64) {
        for (int i = t; i < 1024; i += 256) {
            int r = i >> 3, kg = (i & 7) << 3;
            int off = r * TCB_STR + kg;
            size_t ga = (size_t)(m0 + r) * Kn + k0 + kg;
            size_t gb = (size_t)(n0 + r) * Kn + k0 + kg;
            *reinterpret_cast<uint4*>(sAh + off) = *reinterpret_cast<const uint4*>(Ahi + ga);
            *reinterpret_cast<uint4*>(sAl + off) = *reinterpret_cast<const uint4*>(Alo + ga);
            *reinterpret_cast<uint4*>(sBh + off) = *reinterpret_cast<const uint4*>(Bhi + gb);
            *reinterpret_cast<uint4*>(sBl + off) = *reinterpret_cast<const uint4*>(Blo + gb);
        }
        __syncthreads();
#pragma unroll
        for (int ks = 0; ks < 4; ks++) {
            const int kl = ks * 16;
            uint32_t ah[2][4], al[2][4];
#pragma unroll
            for (int mt = 0; mt < 2; mt++) {
                uint32_t off = (uint32_t)((wm + mt * 16 + a_row) * TCB_STR + kl + a_col) * 2;
                ldsm_x4(ah[mt], sAh_u + off);
                ldsm_x4(al[mt], sAl_u + off);
            }
#pragma unroll
            for (int ng = 0; ng < 2; ng++) {
                uint32_t bh[4][2], bl[4][2];
#pragma unroll
                for (int nt = 0; nt < 4; nt++) {
                    uint32_t off = (uint32_t)((wn + ng * 32 + nt * 8 + b_row) * TCB_STR + kl + b_col) * 2;
                    ldsm_x2(bh[nt], sBh_u + off);
                    ldsm_x2(bl[nt], sBl_u + off);
                }
#pragma unroll
                for (int mt = 0; mt < 2; mt++)
#pragma unroll
                    for (int nt = 0; nt < 4; nt++) {
                        float* d = acc[mt][ng * 4 + nt];
                        mma_bf16(d, ah[mt], bh[nt]);
                        mma_bf16(d, ah[mt], bl[nt]);
                        mma_bf16(d, al[mt], bh[nt]);
                    }
            }
        }
        __syncthreads();
    }

    const bool relu = (flags & FLAG_RELU) != 0;
    const bool accu = (flags & FLAG_ACC) != 0;
#pragma unroll
    for (int mt = 0; mt < 2; mt++) {
        int rbase = m0 + wm + mt * 16 + (lane >> 2);
#pragma unroll
        for (int nt = 0; nt < 8; nt++) {
            int c0 = n0 + wn + nt * 8 + (lane & 3) * 2;
#pragma unroll
            for (int half = 0; half < 2; half++) {
                int row = rbase + half * 8;
                if (row >= Mn) continue;
                float v0 = acc[mt][nt][half * 2 + 0];
                float v1 = acc[mt][nt][half * 2 + 1];
                if (c0 < scale_cols)     v0 *= scale;
                if (c0 + 1 < scale_cols) v1 *= scale;
                if (bias) { v0 += bias[c0]; v1 += bias[c0 + 1]; }
                if (relu) { v0 = fmaxf(v0, 0.f); v1 = fmaxf(v1, 0.f); }
                size_t o = (size_t)row * Nn + c0;
                if (accu) { C[o] += v0; C[o + 1] += v1; }
                else      { C[o] = v0;  C[o + 1] = v1; }
            }
        }
    }
}

// ---------------------------------------------------------------------------
// Batched logits MMA (K=64, one chunk): C[b][m][n] = A[b] @ B[b]^T
// ---------------------------------------------------------------------------
__global__ void __launch_bounds__(256)
slogits_kernel(const __nv_bfloat16* __restrict__ Ahi, const __nv_bfloat16* __restrict__ Alo,
               const __nv_bfloat16* __restrict__ Bhi, const __nv_bfloat16* __restrict__ Blo,
               float* __restrict__ C,
               size_t strideA, size_t strideB, size_t strideC, int ldc)
{
    extern __shared__ __nv_bfloat16 smb[];
    __nv_bfloat16* sAh = smb;
    __nv_bfloat16* sAl = smb + 128 * TCB_STR;
    __nv_bfloat16* sBh = smb + 2 * 128 * TCB_STR;
    __nv_bfloat16* sBl = smb + 3 * 128 * TCB_STR;

    const int t = threadIdx.x, lane = t & 31, wid = t >> 5;
    const int m0 = blockIdx.y * 128, n0 = blockIdx.x * 128;
    const int b = blockIdx.z;
    const __nv_bfloat16* Ah = Ahi + (size_t)b * strideA;
    const __nv_bfloat16* Al = Alo + (size_t)b * strideA;
    const __nv_bfloat16* Bh = Bhi + (size_t)b * strideB;
    const __nv_bfloat16* Bl = Blo + (size_t)b * strideB;
    float* Cb = C + (size_t)b * strideC;

    const int wm = (wid & 3) * 32;
    const int wn = (wid >> 2) * 64;

    const uint32_t sAh_u = smem_u32(sAh), sAl_u = smem_u32(sAl);
    const uint32_t sBh_u = smem_u32(sBh), sBl_u = smem_u32(sBl);

    const int a_row = (lane & 7) + ((lane >> 3) & 1) * 8;
    const int a_col = (lane >> 4) * 8;
    const int b_row = lane & 7;
    const int b_col = ((lane >> 3) & 1) * 8;

    float acc[2][8][4];
#pragma unroll
    for (int i = 0; i < 2; i++)
#pragma unroll
        for (int j = 0; j < 8; j++)
#pragma unroll
            for (int k = 0; k < 4; k++) acc[i][j][k] = 0.f;

    for (int i = t; i < 1024; i += 256) {
        int r = i >> 3, kg = (i & 7) << 3;
        int off = r * TCB_STR + kg;
        size_t ga = (size_t)(m0 + r) * DH + kg;
        size_t gb = (size_t)(n0 + r) * DH + kg;
        *reinterpret_cast<uint4*>(sAh + off) = *reinterpret_cast<const uint4*>(Ah + ga);
        *reinterpret_cast<uint4*>(sAl + off) = *reinterpret_cast<const uint4*>(Al + ga);
        *reinterpret_cast<uint4*>(sBh + off) = *reinterpret_cast<const uint4*>(Bh + gb);
        *reinterpret_cast<uint4*>(sBl + off) = *reinterpret_cast<const uint4*>(Bl + gb);
    }
    __syncthreads();
#pragma unroll
    for (int ks = 0; ks < 4; ks++) {
        const int kl = ks * 16;
        uint32_t ah[2][4], al[2][4];
#pragma unroll
        for (int mt = 0; mt < 2; mt++) {
            uint32_t off = (uint32_t)((wm + mt * 16 + a_row) * TCB_STR + kl + a_col) * 2;
            ldsm_x4(ah[mt], sAh_u + off);
            ldsm_x4(al[mt], sAl_u + off);
        }
#pragma unroll
        for (int ng = 0; ng < 2; ng++) {
            uint32_t bh[4][2], bl[4][2];
#pragma unroll
            for (int nt = 0; nt < 4; nt++) {
                uint32_t off = (uint32_t)((wn + ng * 32 + nt * 8 + b_row) * TCB_STR + kl + b_col) * 2;
                ldsm_x2(bh[nt], sBh_u + off);
                ldsm_x2(bl[nt], sBl_u + off);
            }
#pragma unroll
            for (int mt = 0; mt < 2; mt++)
#pragma unroll
                for (int nt = 0; nt < 4; nt++) {
                    float* d = acc[mt][nt + ng * 4];
                    mma_bf16(d, ah[mt], bh[nt]);
                    mma_bf16(d, ah[mt], bl[nt]);
                    mma_bf16(d, al[mt], bh[nt]);
                }
        }
    }

#pragma unroll
    for (int mt = 0; mt < 2; mt++) {
        int rbase = m0 + wm + mt * 16 + (lane >> 2);
#pragma unroll
        for (int nt = 0; nt < 8; nt++) {
            int c0 = n0 + wn + nt * 8 + (lane & 3) * 2;
#pragma unroll
            for (int half = 0; half < 2; half++) {
                int row = rbase + half * 8;
                size_t o = (size_t)row * ldc + c0;
                Cb[o]     = acc[mt][nt][half * 2 + 0];
                Cb[o + 1] = acc[mt][nt][half * 2 + 1];
            }
        }
    }
}

// ---------------------------------------------------------------------------
// pgemm: C = P @ B where P hi/lo row-major [M][K], B hi/lo row-major [K][64]
// (B loaded with ldmatrix.trans). CTA tile 128x64; 8 warps (4m x 2n).
// mode 0: write split-K partial to PVP[((slice*8+head)*MLAND + row)*64 + col]
// mode 1: write O[row*DMODEL + head*64 + col]
// ---------------------------------------------------------------------------
#define PG_PH  0
#define PG_PL  (128 * TCB_STR)
#define PG_BH  (2 * 128 * TCB_STR)
#define PG_BL  (2 * 128 * TCB_STR + 64 * TCB_STR)
#define PG_SMEM ((2 * 128 * TCB_STR + 2 * 64 * TCB_STR) * 2)   // 55296 bytes

__global__ void __launch_bounds__(256)
pgemm_kernel(const __nv_bfloat16* __restrict__ Phi, const __nv_bfloat16* __restrict__ Plo,
             const __nv_bfloat16* __restrict__ Bhi, const __nv_bfloat16* __restrict__ Blo,
             float* __restrict__ Cout,
             int Pld, size_t pHeadStride, size_t bHeadStride,
             int chunksPerSliceBase, int mode)
{
    extern __shared__ __nv_bfloat16 smb[];
    __nv_bfloat16* sPh = smb + PG_PH;
    __nv_bfloat16* sPl = smb + PG_PL;
    __nv_bfloat16* sBh = smb + PG_BH;
    __nv_bfloat16* sBl = smb + PG_BL;

    const int t = threadIdx.x, lane = t & 31, wid = t >> 5;
    const int m0 = blockIdx.x * 128;
    const int kslice = blockIdx.y;
    const int head = blockIdx.z;

    int c0, nch;
    if (mode == 0) {
        // 132 chunks split 17,17,17,17,16,16,16,16
        if (kslice < 4) { c0 = kslice * (chunksPerSliceBase + 1); nch = chunksPerSliceBase + 1; }
        else { c0 = 4 * (chunksPerSliceBase + 1) + (kslice - 4) * chunksPerSliceBase; nch = chunksPerSliceBase; }
    } else {
        c0 = 0; nch = chunksPerSliceBase;
    }

    const __nv_bfloat16* Ph = Phi + (size_t)head * pHeadStride;
    const __nv_bfloat16* Pl = Plo + (size_t)head * pHeadStride;
    const __nv_bfloat16* Bh = Bhi + (size_t)head * bHeadStride;
    const __nv_bfloat16* Bl = Blo + (size_t)head * bHeadStride;

    const int wm = (wid & 3) * 32;       // warp m offset (4 warps x 32)
    const int wn = (wid >> 2) * 32;      // warp n offset (2 warps x 32)

    const uint32_t sPh_u = smem_u32(sPh), sPl_u = smem_u32(sPl);
    const uint32_t sBh_u = smem_u32(sBh), sBl_u = smem_u32(sBl);

    const int a_row = (lane & 7) + ((lane >> 3) & 1) * 8;
    const int a_col = (lane >> 4) * 8;
    const int bt_k = lane & 15;          // trans: lanes 0-15 give k-rows

    float acc[2][4][4];
#pragma unroll
    for (int i = 0; i < 2; i++)
#pragma unroll
        for (int j = 0; j < 4; j++)
#pragma unroll
            for (int k = 0; k < 4; k++) acc[i][j][k] = 0.f;

    for (int ci = 0; ci < nch; ci++) {
        int k0 = (c0 + ci) << 6;
        for (int i = t; i < 1024; i += 256) {
            int r = i >> 3, kg = (i & 7) << 3;
            int off = r * TCB_STR + kg;
            size_t gp = (size_t)(m0 + r) * Pld + k0 + kg;
            *reinterpret_cast<uint4*>(sPh + off) = *reinterpret_cast<const uint4*>(Ph + gp);
            *reinterpret_cast<uint4*>(sPl + off) = *reinterpret_cast<const uint4*>(Pl + gp);
        }
        for (int i = t; i < 512; i += 256) {
            int r = i >> 3, kg = (i & 7) << 3;
            int off = r * TCB_STR + kg;
            size_t gb = (size_t)(k0 + r) * 64 + kg;
            *reinterpret_cast<uint4*>(sBh + off) = *reinterpret_cast<const uint4*>(Bh + gb);
            *reinterpret_cast<uint4*>(sBl + off) = *reinterpret_cast<const uint4*>(Bl + gb);
        }
        __syncthreads();
#pragma unroll
        for (int ks = 0; ks < 4; ks++) {
            const int kl = ks * 16;
            uint32_t ph[2][4], pl[2][4];
#pragma unroll
            for (int mt = 0; mt < 2; mt++) {
                uint32_t off = (uint32_t)((wm + mt * 16 + a_row) * TCB_STR + kl + a_col) * 2;
                ldsm_x4(ph[mt], sPh_u + off);
                ldsm_x4(pl[mt], sPl_u + off);
            }
            uint32_t bh[4][2], bl[4][2];
#pragma unroll
            for (int nt = 0; nt < 4; nt++) {
                uint32_t off = (uint32_t)((kl + bt_k) * TCB_STR + wn + nt * 8) * 2;
                ldsm_x2_trans(bh[nt], sBh_u + off);
                ldsm_x2_trans(bl[nt], sBl_u + off);
            }
#pragma unroll
            for (int mt = 0; mt < 2; mt++)
#pragma unroll
                for (int nt = 0; nt < 4; nt++) {
                    float* d = acc[mt][nt];
                    mma_bf16(d, ph[mt], bh[nt]);
                    mma_bf16(d, ph[mt], bl[nt]);
                    mma_bf16(d, pl[mt], bh[nt]);
                }
        }
        __syncthreads();
    }

#pragma unroll
    for (int mt = 0; mt < 2; mt++) {
        int rbase = m0 + wm + mt * 16 + (lane >> 2);
#pragma unroll
        for (int nt = 0; nt < 4; nt++) {
            int c0c = wn + nt * 8 + (lane & 3) * 2;
#pragma unroll
            for (int half = 0; half < 2; half++) {
                int row = rbase + half * 8;
                float v0 = acc[mt][nt][half * 2 + 0];
                float v1 = acc[mt][nt][half * 2 + 1];
                if (mode == 0) {
                    size_t o = (((size_t)kslice * NHEADS + head) * MLAND + row) * 64 + c0c;
                    Cout[o] = v0; Cout[o + 1] = v1;
                } else {
                    size_t o = (size_t)row * DMODEL + head * 64 + c0c;
                    Cout[o] = v0; Cout[o + 1] = v1;
                }
            }
        }
    }
}

// ---------------------------------------------------------------------------
// split-K reduction: A3V = sum over 8 slices
// ---------------------------------------------------------------------------
__global__ void pvred_kernel(const float* __restrict__ PVP, float* __restrict__ A3V)
{
    int h = blockIdx.x & 7, seg = blockIdx.x >> 3;
    int idx = seg * 2048 + threadIdx.x * 8;
    for (int j = 0; j < 8; j++) {
        int li = idx + j;
        float s = 0.f;
#pragma unroll
        for (int sl = 0; sl < 8; sl++)
            s += PVP[(((size_t)sl * NHEADS + h) * MLAND * 64) + li];
        A3V[(size_t)h * MLAND * 64 + li] = s;
    }
}

// ---------------------------------------------------------------------------
// p3 softmax: S3 [h][m][NP] -> normalized P hi/lo (block per row)
// ---------------------------------------------------------------------------
__global__ void p3_kernel(const float* __restrict__ S,
                          __nv_bfloat16* __restrict__ PH, __nv_bfloat16* __restrict__ PL)
{
    int m = blockIdx.x, h = blockIdx.y;
    int t = threadIdx.x;
    const float* row = S + ((size_t)h * MLAND + m) * NP;
    float vals[33];
    float mx = -1e30f;
#pragma unroll
    for (int i = 0; i < 33; i++) {
        vals[i] = row[i * 256 + t];
        mx = fmaxf(mx, vals[i]);
    }
    __shared__ float red[256];
    red[t] = mx; __syncthreads();
    for (int o = 128; o > 0; o >>= 1) {
        if (t < o) red[t] = fmaxf(red[t], red[t + o]);
        __syncthreads();
    }
    mx = red[0]; __syncthreads();
    float sum = 0.f;
#pragma unroll
    for (int i = 0; i < 33; i++) {
        vals[i] = __expf(vals[i] - mx);
        sum += vals[i];
    }
    red[t] = sum; __syncthreads();
    for (int o = 128; o > 0; o >>= 1) {
        if (t < o) red[t] += red[t + o];
        __syncthreads();
    }
    float inv = 1.0f / red[0];
    __nv_bfloat16* ph = PH + ((size_t)h * MLAND + m) * NP;
    __nv_bfloat16* pl = PL + ((size_t)h * MLAND + m) * NP;
#pragma unroll
    for (int i = 0; i < 33; i++) {
        float p = vals[i] * inv;
        __nv_bfloat16 hi = __float2bfloat16(p);
        ph[i * 256 + t] = hi;
        pl[i * 256 + t] = __float2bfloat16(p - __bfloat162float(hi));
    }
}

// ---------------------------------------------------------------------------
// p1 softmax: S1 [h][n][256] -> normalized P hi/lo (warp per row)
// ---------------------------------------------------------------------------
__global__ void p1_kernel(const float* __restrict__ S,
                          __nv_bfloat16* __restrict__ PH, __nv_bfloat16* __restrict__ PL)
{
    int row = blockIdx.x * 8 + (threadIdx.x >> 5);
    int lane = threadIdx.x & 31;
    const float* r = S + (size_t)row * MLAND;
    float a[8];
#pragma unroll
    for (int k = 0; k < 8; k++) a[k] = r[lane + k * 32];
    float m = a[0];
#pragma unroll
    for (int k = 1; k < 8; k++) m = fmaxf(m, a[k]);
    for (int o = 16; o > 0; o >>= 1) m = fmaxf(m, __shfl_xor_sync(0xffffffffu, m, o));
    float s = 0.f;
#pragma unroll
    for (int k = 0; k < 8; k++) { a[k] = __expf(a[k] - m); s += a[k]; }
    for (int o = 16; o > 0; o >>= 1) s += __shfl_xor_sync(0xffffffffu, s, o);
    float inv = 1.0f / s;
    __nv_bfloat16* ph = PH + (size_t)row * MLAND;
    __nv_bfloat16* pl = PL + (size_t)row * MLAND;
#pragma unroll
    for (int k = 0; k < 8; k++) {
        float p = a[k] * inv;
        __nv_bfloat16 hi = __float2bfloat16(p);
        ph[lane + k * 32] = hi;
        pl[lane + k * 32] = __float2bfloat16(p - __bfloat162float(hi));
    }
}

// ---------------------------------------------------------------------------
// Assemble h rows: cls + wrap
// ---------------------------------------------------------------------------
__global__ void assemble_kernel(const float* __restrict__ cls, float* __restrict__ H)
{
    int j = blockIdx.x;
    int c = threadIdx.x;
    if (j == 0) H[c] = cls[c];
    else        H[(size_t)(NTOK + j) * DMODEL + c] = H[(size_t)j * DMODEL + c];
}

// ---------------------------------------------------------------------------
// LayerNorm into padded XP
// ---------------------------------------------------------------------------
__global__ void ln_pad_kernel(const float* __restrict__ Hin, float* __restrict__ XP,
                              const float* __restrict__ g, const float* __restrict__ b)
{
    int row = blockIdx.x;
    int tid = threadIdx.x;
    if (row < PADF) {
        XP[(size_t)row * DMODEL + tid] = 0.f;
        XP[(size_t)row * DMODEL + tid + 256] = 0.f;
        return;
    }
    const float* x = Hin + (size_t)(row - PADF) * DMODEL;
    float v0 = x[tid], v1 = x[tid + 256];
    __shared__ float s1[256], s2[256];
    s1[tid] = v0 + v1;
    s2[tid] = v0 * v0 + v1 * v1;
    __syncthreads();
    for (int o = 128; o > 0; o >>= 1) {
        if (tid < o) { s1[tid] += s1[tid + o]; s2[tid] += s2[tid + o]; }
        __syncthreads();
    }
    float mean = s1[0] * (1.f / DMODEL);
    float var  = s2[0] * (1.f / DMODEL) - mean * mean;
    float rs = rsqrtf(var + EPSLN);
    XP[(size_t)row * DMODEL + tid]       = (v0 - mean) * rs * g[tid] + b[tid];
    XP[(size_t)row * DMODEL + tid + 256] = (v1 - mean) * rs * g[tid + 256] + b[tid + 256];
}

// ---------------------------------------------------------------------------
// Landmarks: means of 33-groups; f32 QL/KL + bf16 hi/lo copies
// ---------------------------------------------------------------------------
__global__ void landmarks_kernel(const float* __restrict__ QKV,
                                 float* __restrict__ QL, float* __restrict__ KL,
                                 __nv_bfloat16* __restrict__ QLH, __nv_bfloat16* __restrict__ QLL,
                                 __nv_bfloat16* __restrict__ KLH, __nv_bfloat16* __restrict__ KLL)
{
    int hm = blockIdx.x;
    int h = hm >> 8, m = hm & 255;
    int tid = threadIdx.x;
    int d = tid & 63;
    int off = (tid < 64) ? 0 : DMODEL;
    size_t base = (size_t)(m * LWIN) * (3 * DMODEL) + off + h * DH + d;
    float s = 0.f;
#pragma unroll
    for (int j = 0; j < LWIN; j++) s += QKV[base + (size_t)j * (3 * DMODEL)];
    s *= (1.0f / LWIN);
    __nv_bfloat16 hi = __float2bfloat16(s);
    __nv_bfloat16 lo = __float2bfloat16(s - __bfloat162float(hi));
    size_t o = (size_t)(h * MLAND + m) * DH + d;
    if (tid < 64) {
        QL[o] = s; QLH[o] = hi; QLL[o] = lo;
    } else {
        KL[o] = s; KLH[o] = hi; KLL[o] = lo;
    }
}

// ---------------------------------------------------------------------------
// a2 = softmax(q_l @ k_l^T)
// ---------------------------------------------------------------------------
__global__ void a2_kernel(const float* __restrict__ QL, const float* __restrict__ KL,
                          float* __restrict__ A2)
{
    int m = blockIdx.x, h = blockIdx.y;
    int tid = threadIdx.x;
    __shared__ float q[64];
    __shared__ float red[256];
    if (tid < 64) q[tid] = QL[(size_t)(h * MLAND + m) * DH + tid];
    __syncthreads();
    const float* kr = KL + (size_t)(h * MLAND + tid) * DH;
    float s = 0.f;
#pragma unroll
    for (int i = 0; i < 16; i++) {
        float4 kv = reinterpret_cast<const float4*>(kr)[i];
        float4 qv = reinterpret_cast<const float4*>(q)[i];
        s += kv.x * qv.x + kv.y * qv.y + kv.z * qv.z + kv.w * qv.w;
    }
    red[tid] = s; __syncthreads();
    for (int o = 128; o > 0; o >>= 1) {
        if (tid < o) red[tid] = fmaxf(red[tid], red[tid + o]);
        __syncthreads();
    }
    float mx = red[0]; __syncthreads();
    float e = __expf(s - mx);
    red[tid] = e; __syncthreads();
    for (int o = 128; o > 0; o >>= 1) {
        if (tid < o) red[tid] += red[tid + o];
        __syncthreads();
    }
    float sm = red[0];
    A2[(size_t)(h * MLAND + m) * MLAND + tid] = e / sm;
}

// ---------------------------------------------------------------------------
// pinv chain (unchanged)
// ---------------------------------------------------------------------------
__global__ void pinv_scale_kernel(const float* __restrict__ A2, float* __restrict__ PS)
{
    int h = blockIdx.x;
    int t = threadIdx.x;
    int w = t >> 5, lane = t & 31;
    const float* Ah = A2 + (size_t)h * 65536;
    __shared__ float rs[256];
    __shared__ float cs2[256];
    for (int r = w; r < 256; r += 8) {
        float s = 0.f;
        for (int j = lane; j < 256; j += 32) s += fabsf(Ah[r * 256 + j]);
        for (int o = 16; o > 0; o >>= 1) s += __shfl_xor_sync(0xffffffffu, s, o);
        if (lane == 0) rs[r] = s;
    }
    float cs = 0.f;
    for (int i = 0; i < 256; i++) cs += fabsf(Ah[i * 256 + t]);
    cs2[t] = cs;
    __syncthreads();
    for (int o = 128; o > 0; o >>= 1) {
        if (t < o) { rs[t] = fmaxf(rs[t], rs[t + o]); cs2[t] = fmaxf(cs2[t], cs2[t + o]); }
        __syncthreads();
    }
    if (t == 0) PS[h] = 1.0f / (rs[0] * cs2[0]);
}

__global__ void pinv_tr_kernel(const float* __restrict__ A2, const float* __restrict__ PS,
                               float* __restrict__ Z0)
{
    __shared__ float tl[64][65];
    int h = blockIdx.y;
    int seg = blockIdx.x;
    int bi = (seg >> 2) * 64, bj = (seg & 3) * 64;
    int t = threadIdx.x;
    float inv = PS[h];
    const float* Ah = A2 + (size_t)h * 65536;
    float* Zh = Z0 + (size_t)h * 65536;
    for (int lin = t; lin < 4096; lin += 256) {
        int r = lin >> 6, c = lin & 63;
        tl[r][c] = Ah[(size_t)(bi + r) * 256 + bj + c];
    }
    __syncthreads();
    for (int lin = t; lin < 4096; lin += 256) {
        int r = lin >> 6, c = lin & 63;
        Zh[(size_t)(bj + r) * 256 + bi + c] = tl[c][r] * inv;
    }
}

__global__ void nk256_kernel(const float* __restrict__ A, const float* __restrict__ B,
                             float* __restrict__ C, float alpha, float gamma)
{
    const float* Ah = A + (size_t)blockIdx.z * 65536;
    const float* Bh = B + (size_t)blockIdx.z * 65536;
    float* Ch = C + (size_t)blockIdx.z * 65536;
    __shared__ float As[16][64];
    __shared__ float Bs[16][64];
    const int bm = blockIdx.y * 64;
    const int bn = blockIdx.x * 64;
    const int tid = threadIdx.x;
    const int tx = tid & 15, ty = tid >> 4;
    const int row0 = ty * 4, col0 = tx * 4;
    float acc[4][4];
#pragma unroll
    for (int i = 0; i < 4; i++)
#pragma unroll
        for (int j = 0; j < 4; j++) acc[i][j] = 0.f;

    for (int k0 = 0; k0 < 256; k0 += 16) {
        {
            int ar = tid >> 2;
            int ac = (tid & 3) << 2;
            float4 v = *reinterpret_cast<const float4*>(Ah + (size_t)(bm + ar) * 256 + k0 + ac);
            As[ac + 0][ar] = v.x; As[ac + 1][ar] = v.y;
            As[ac + 2][ar] = v.z; As[ac + 3][ar] = v.w;
        }
        {
            int br = tid >> 4;
            int bc = (tid & 15) << 2;
            float4 v = *reinterpret_cast<const float4*>(Bh + (size_t)(k0 + br) * 256 + bn + bc);
            *reinterpret_cast<float4*>(&Bs[br][bc]) = v;
        }
        __syncthreads();
#pragma unroll
        for (int k = 0; k < 16; k++) {
            float a[4], b[4];
            *reinterpret_cast<float4*>(a) = *reinterpret_cast<const float4*>(&As[k][row0]);
            *reinterpret_cast<float4*>(b) = *reinterpret_cast<const float4*>(&Bs[k][col0]);
#pragma unroll
            for (int i = 0; i < 4; i++)
#pragma unroll
                for (int j = 0; j < 4; j++) acc[i][j] += a[i] * b[j];
        }
        __syncthreads();
    }
#pragma unroll
    for (int i = 0; i < 4; i++)
#pragma unroll
        for (int j = 0; j < 4; j++) {
            size_t o = (size_t)(bm + row0 + i) * 256 + bn + col0 + j;
            Ch[o] = alpha * acc[i][j] + gamma * Ah[o];
        }
}

// ---------------------------------------------------------------------------
// Bm = pinv(a2) @ a3v  -> bf16 hi/lo
// ---------------------------------------------------------------------------
__global__ void bmat_kernel(const float* __restrict__ Z, const float* __restrict__ A3V,
                            __nv_bfloat16* __restrict__ BmH, __nv_bfloat16* __restrict__ BmL)
{
    int h = blockIdx.y;
    int m0 = blockIdx.x * 4;
    __shared__ float zs[4][256];
    int tid = threadIdx.x;
    int r = tid >> 6, d = tid & 63;
    for (int lin = tid; lin < 1024; lin += 256) {
        int rr = lin >> 8, k = lin & 255;
        zs[rr][k] = Z[(size_t)h * 65536 + (size_t)(m0 + rr) * 256 + k];
    }
    __syncthreads();
    float acc = 0.f;
    for (int k = 0; k < 256; k++)
        acc += zs[r][k] * A3V[(size_t)(h * MLAND + k) * DH + d];
    size_t o = (size_t)(h * MLAND + m0 + r) * DH + d;
    __nv_bfloat16 hi = __float2bfloat16(acc);
    BmH[o] = hi;
    BmL[o] = __float2bfloat16(acc - __bfloat162float(hi));
}

// ---------------------------------------------------------------------------
// Depthwise seq-conv (k=33) on v, tiled in smem; adds into O
// ---------------------------------------------------------------------------
__global__ void conv_tile_kernel(const float* __restrict__ QKV, const float* __restrict__ W,
                                 float* __restrict__ O)
{
    __shared__ float vs[160 * 64];
    __shared__ float ws[33];
    int h = blockIdx.y;
    int n0 = blockIdx.x * 128;
    int t = threadIdx.x;
    if (t < 33) ws[t] = W[h * LWIN + t];
    for (int lin = t; lin < 160 * 64; lin += 256) {
        int r = lin >> 6, c = lin & 63;
        int n = n0 + r - 16;
        vs[lin] = (n >= 0 && n < NP)
                    ? QKV[(size_t)n * (3 * DMODEL) + 2 * DMODEL + h * DH + c] : 0.f;
    }
    __syncthreads();
    int c = t & 63, rg = t >> 6;
    for (int q = 0; q < 32; q++) {
        int r = rg * 32 + q;
        float acc = 0.f;
#pragma unroll
        for (int k = 0; k < LWIN; k++) acc += ws[k] * vs[(r + k) * 64 + c];
        O[(size_t)(n0 + r) * DMODEL + h * DH + c] += acc;
    }
}

// ---------------------------------------------------------------------------
// PPEG tiled
// ---------------------------------------------------------------------------
#define PPEG_TILE (14 * 14 * 64)
#define PPEG_W7   PPEG_TILE
#define PPEG_W5   (PPEG_W7 + 64 * 49)
#define PPEG_W3   (PPEG_W5 + 64 * 25)
#define PPEG_TOT  (PPEG_W3 + 64 * 9)

__global__ void ppeg_tile_kernel(const float* __restrict__ Hin, float* __restrict__ Hout,
                                 const float* __restrict__ w7, const float* __restrict__ b7,
                                 const float* __restrict__ w5, const float* __restrict__ b5,
                                 const float* __restrict__ w3, const float* __restrict__ b3)
{
    extern __shared__ float sm[];
    float* tile = sm;
    float* ws7 = sm + PPEG_W7;
    float* ws5 = sm + PPEG_W5;
    float* ws3 = sm + PPEG_W3;

    int ti = blockIdx.x;
    int ty0 = (ti / 12) * 8, tx0 = (ti % 12) * 8;
    int cg = blockIdx.y * 64;
    int t = threadIdx.x;

    for (int lin = t; lin < PPEG_TILE; lin += 256) {
        int p = lin >> 6, c = lin & 63;
        int gy = ty0 + p / 14 - 3;
        int gx = tx0 + p % 14 - 3;
        float v = 0.f;
        if ((unsigned)gy < (unsigned)HSQ && (unsigned)gx < (unsigned)HSQ)
            v = Hin[(size_t)(1 + gy * HSQ + gx) * DMODEL + cg + c];
        tile[lin] = v;
    }
    for (int lin = t; lin < 64 * 49; lin += 256) ws7[lin] = w7[(size_t)cg * 49 + lin];
    for (int lin = t; lin < 64 * 25; lin += 256) ws5[lin] = w5[(size_t)cg * 25 + lin];
    for (int lin = t; lin < 64 * 9;  lin += 256) ws3[lin] = w3[(size_t)cg * 9 + lin];
    __syncthreads();

    int c = t & 63, pg = t >> 6;
    float bsum = b7[cg + c] + b5[cg + c] + b3[cg + c];
    for (int q = 0; q < 16; q++) {
        int p = pg * 16 + q;
        int oy = p >> 3, ox = p & 7;
        int gy = ty0 + oy, gx = tx0 + ox;
        if (gy >= HSQ || gx >= HSQ) continue;
        float acc = tile[((oy + 3) * 14 + ox + 3) * 64 + c] + bsum;
#pragma unroll
        for (int a = 0; a < 7; a++)
#pragma unroll
            for (int bq = 0; bq < 7; bq++)
                acc += ws7[c * 49 + a * 7 + bq] * tile[((oy + a) * 14 + ox + bq) * 64 + c];
#pragma unroll
        for (int a = 0; a < 5; a++)
#pragma unroll
            for (int bq = 0; bq < 5; bq++)
                acc += ws5[c * 25 + a * 5 + bq] * tile[((oy + a + 1) * 14 + ox + bq + 1) * 64 + c];
#pragma unroll
        for (int a = 0; a < 3; a++)
#pragma unroll
            for (int bq = 0; bq < 3; bq++)
                acc += ws3[c * 9 + a * 3 + bq] * tile[((oy + a + 2) * 14 + ox + bq + 2) * 64 + c];
        Hout[(size_t)(1 + gy * HSQ + gx) * DMODEL + cg + c] = acc;
    }
}

__global__ void copy_row0_kernel(const float* __restrict__ Hin, float* __restrict__ Hout)
{
    Hout[threadIdx.x] = Hin[threadIdx.x];
}

// ---------------------------------------------------------------------------
// Final head
// ---------------------------------------------------------------------------
__global__ void final_kernel(const float* __restrict__ H, const float* __restrict__ g,
                             const float* __restrict__ b, const float* __restrict__ w,
                             const float* __restrict__ bias2, float* __restrict__ out,
                             int out_size)
{
    int c = threadIdx.x;
    __shared__ float s1[512], s2[512];
    float x = H[c];
    s1[c] = x; s2[c] = x * x;
    __syncthreads();
    for (int o = 256; o > 0; o >>= 1) {
        if (c < o) { s1[c] += s1[c + o]; s2[c] += s2[c + o]; }
        __syncthreads();
    }
    float mean = s1[0] * (1.f / DMODEL);
    float var  = s2[0] * (1.f / DMODEL) - mean * mean;
    float e = (x - mean) * rsqrtf(var + EPSLN) * g[c] + b[c];
    __syncthreads();
    s1[c] = e * w[c * 2 + 0];
    s2[c] = e * w[c * 2 + 1];
    __syncthreads();
    for (int o = 256; o > 0; o >>= 1) {
        if (c < o) { s1[c] += s1[c + o]; s2[c] += s2[c + o]; }
        __syncthreads();
    }
    float l0 = s1[0] + bias2[0];
    float l1 = s2[0] + bias2[1];
    if (c == 0) {
        float m = fmaxf(l0, l1);
        float e0 = expf(l0 - m), e1 = expf(l1 - m);
        float ss = e0 + e1;
        if (out_size > 0) out[0] = l0;
        if (out_size > 1) out[1] = l1;
        if (out_size > 2) out[2] = e0 / ss;
        if (out_size > 3) out[3] = e1 / ss;
        if (out_size > 4) out[4] = (l1 > l0) ? 1.0f : 0.0f;
    }
    if (5 + c < out_size) out[5 + c] = e;
}

// ---------------------------------------------------------------------------
// Host orchestration
// ---------------------------------------------------------------------------
static float* symaddr(const void* sym)
{
    void* p = nullptr;
    cudaGetSymbolAddress(&p, sym);
    return (float*)p;
}
static __nv_bfloat16* symaddr_bf(const void* sym)
{
    void* p = nullptr;
    cudaGetSymbolAddress(&p, sym);
    return (__nv_bfloat16*)p;
}

static cudaStream_t g_side = nullptr;
static cudaEvent_t  g_evf  = nullptr;
static cudaEvent_t  g_evj  = nullptr;

extern "C" void kernel_launch(void* const* d_in, const int* in_sizes, int n_in,
                              void* d_out, int out_size)
{
    if (!g_side) {
        cudaStreamCreateWithFlags(&g_side, cudaStreamNonBlocking);
        cudaEventCreateWithFlags(&g_evf, cudaEventDisableTiming);
        cudaEventCreateWithFlags(&g_evj, cudaEventDisableTiming);
    }

    const float* x       = (const float*)d_in[0];
    const float* fc1_w   = (const float*)d_in[1];
    const float* fc1_b   = (const float*)d_in[2];
    const float* cls     = (const float*)d_in[3];
    const float* ln1_g   = (const float*)d_in[4];
    const float* ln1_b   = (const float*)d_in[5];
    const float* qkv1_w  = (const float*)d_in[6];
    const float* out1_w  = (const float*)d_in[7];
    const float* out1_b  = (const float*)d_in[8];
    const float* conv1_w = (const float*)d_in[9];
    const float* ln2_g   = (const float*)d_in[10];
    const float* ln2_b   = (const float*)d_in[11];
    const float* qkv2_w  = (const float*)d_in[12];
    const float* out2_w  = (const float*)d_in[13];
    const float* out2_b  = (const float*)d_in[14];
    const float* conv2_w = (const float*)d_in[15];
    const float* pg7_w   = (const float*)d_in[16];
    const float* pg7_b   = (const float*)d_in[17];
    const float* pg5_w   = (const float*)d_in[18];
    const float* pg5_b   = (const float*)d_in[19];
    const float* pg3_w   = (const float*)d_in[20];
    const float* pg3_b   = (const float*)d_in[21];
    const float* norm_g  = (const float*)d_in[22];
    const float* norm_b  = (const float*)d_in[23];
    const float* fc2_w   = (const float*)d_in[24];
    const float* fc2_b   = (const float*)d_in[25];

    float* H   = symaddr(g_H);
    float* H2  = symaddr(g_H2);
    float* XP  = symaddr(g_XP);
    float* QKV = symaddr(g_QKV);
    float* QL  = symaddr(g_QL);
    float* KL  = symaddr(g_KL);
    float* A2  = symaddr(g_A2);
    float* Z0  = symaddr(g_Z0);
    float* Z1  = symaddr(g_Z1);
    float* W1  = symaddr(g_W1);
    float* W2  = symaddr(g_W2);
    float* W3  = symaddr(g_W3);
    float* PS  = symaddr(g_PS);
    float* A3V = symaddr(g_A3V);
    float* O   = symaddr(g_O);
    float* S   = symaddr(g_S);
    float* PVP = symaddr(g_PVP);
    __nv_bfloat16* AH  = symaddr_bf(g_AH);
    __nv_bfloat16* AL  = symaddr_bf(g_AL);
    __nv_bfloat16* WH  = symaddr_bf(g_WH);
    __nv_bfloat16* WL  = symaddr_bf(g_WL);
    __nv_bfloat16* QLH = symaddr_bf(g_QLH);
    __nv_bfloat16* QLL = symaddr_bf(g_QLL);
    __nv_bfloat16* KLH = symaddr_bf(g_KLH);
    __nv_bfloat16* KLL = symaddr_bf(g_KLL);
    __nv_bfloat16* VH  = symaddr_bf(g_VH);
    __nv_bfloat16* VL  = symaddr_bf(g_VL);
    __nv_bfloat16* PH  = symaddr_bf(g_PH);
    __nv_bfloat16* PL  = symaddr_bf(g_PL);
    __nv_bfloat16* BmH = symaddr_bf(g_BmH);
    __nv_bfloat16* BmL = symaddr_bf(g_BmL);

    const int PPEG_SMEM = PPEG_TOT * 4;
    cudaFuncSetAttribute(ppeg_tile_kernel, cudaFuncAttributeMaxDynamicSharedMemorySize, PPEG_SMEM);
    cudaFuncSetAttribute(tc_gemm_kernel,  cudaFuncAttributeMaxDynamicSharedMemorySize, TCG_SMEM);
    cudaFuncSetAttribute(slogits_kernel,  cudaFuncAttributeMaxDynamicSharedMemorySize, TCG_SMEM);
    cudaFuncSetAttribute(pgemm_kernel,    cudaFuncAttributeMaxDynamicSharedMemorySize, PG_SMEM);

    // ---- fc1 + relu via tensor cores ----
    wconv_kernel<<<dim3(DMODEL / 32, INDIM / 32), 256>>>(fc1_w, WH, WL, INDIM, DMODEL);
    aconv_kernel<<<NTOK, 128>>>(x, AH, AL, NTOK, INDIM);
    tc_gemm_kernel<<<dim3(DMODEL / 128, NTOK / 128), 256, TCG_SMEM>>>(
        AH, AL, WH, WL, H + DMODEL, fc1_b, NTOK, DMODEL, INDIM, FLAG_RELU, 0, 1.f);
    assemble_kernel<<<NWRAP + 1, DMODEL>>>(cls, H);

    auto attn = [&](float* Hbuf, const float* lng, const float* lnb, const float* qkvw,
                    const float* outw, const float* outb, const float* convw) {
        ln_pad_kernel<<<NP, 256>>>(Hbuf, XP, lng, lnb);
        wconv_kernel<<<dim3(3 * DMODEL / 32, DMODEL / 32), 256>>>(qkvw, WH, WL, DMODEL, 3 * DMODEL);
        aconv_kernel<<<NP, 128>>>(XP, AH, AL, NP, DMODEL);
        tc_gemm_kernel<<<dim3(3 * DMODEL / 128, NP / 128), 256, TCG_SMEM>>>(
            AH, AL, WH, WL, QKV, nullptr, NP, 3 * DMODEL, DMODEL, 0, DMODEL, 0.125f);
        qk_split_kernel<<<NP, 256>>>(QKV, AH, AL, VH, VL);
        landmarks_kernel<<<NHEADS * MLAND, 128>>>(QKV, QL, KL, QLH, QLL, KLH, KLL);
        a2_kernel<<<dim3(MLAND, NHEADS), 256>>>(QL, KL, A2);

        // fork: pinv chain on side stream
        cudaEventRecord(g_evf, 0);
        cudaStreamWaitEvent(g_side, g_evf, 0);
        pinv_scale_kernel<<<NHEADS, 256, 0, g_side>>>(A2, PS);
        pinv_tr_kernel<<<dim3(16, NHEADS), 256, 0, g_side>>>(A2, PS, Z0);
        float* zi = Z0;
        float* zo = Z1;
        for (int it = 0; it < 6; it++) {
            nk256_kernel<<<dim3(4, 4, NHEADS), 256, 0, g_side>>>(A2, zi, W1, 1.f, 0.f);
            nk256_kernel<<<dim3(4, 4, NHEADS), 256, 0, g_side>>>(W1, W1, W2, -1.f, 7.f);
            nk256_kernel<<<dim3(4, 4, NHEADS), 256, 0, g_side>>>(W1, W2, W3, -1.f, 15.f);
            nk256_kernel<<<dim3(4, 4, NHEADS), 256, 0, g_side>>>(zi, W3, zo, -0.25f, 3.25f);
            float* t = zi; zi = zo; zo = t;
        }
        cudaEventRecord(g_evj, g_side);

        // S3 = QL @ K^T -> softmax -> A3V = P3 @ V (split-K MMA)
        slogits_kernel<<<dim3(NP / 128, MLAND / 128, NHEADS), 256, TCG_SMEM>>>(
            QLH, QLL, AH + QKOFF, AL + QKOFF, S,
            (size_t)MLAND * DH, (size_t)NP * DH, (size_t)MLAND * NP, NP);
        p3_kernel<<<dim3(MLAND, NHEADS), 256>>>(S, PH, PL);
        pgemm_kernel<<<dim3(MLAND / 128, 8, NHEADS), 256, PG_SMEM>>>(
            PH, PL, VH, VL, PVP, NP, (size_t)MLAND * NP, (size_t)NP * DH, 16, 0);
        pvred_kernel<<<64, 256>>>(PVP, A3V);

        // S1 = Q @ KL^T -> softmax  (independent of pinv)
        slogits_kernel<<<dim3(MLAND / 128, NP / 128, NHEADS), 256, TCG_SMEM>>>(
            AH, AL, KLH, KLL, S,
            (size_t)NP * DH, (size_t)MLAND * DH, (size_t)NP * MLAND, MLAND);
        p1_kernel<<<NP * NHEADS / 8, 256>>>(S, PH, PL);

        // join pinv; Bm; O = P1 @ Bm; += conv
        cudaStreamWaitEvent(0, g_evj, 0);
        bmat_kernel<<<dim3(MLAND / 4, NHEADS), 256>>>(zi, A3V, BmH, BmL);
        pgemm_kernel<<<dim3(NP / 128, 1, NHEADS), 256, PG_SMEM>>>(
            PH, PL, BmH, BmL, O, MLAND, (size_t)NP * MLAND, (size_t)MLAND * DH, 4, 1);
        conv_tile_kernel<<<dim3(NP / 128, NHEADS), 256>>>(QKV, convw, O);

        // out projection (accumulate into Hbuf)
        wconv_kernel<<<dim3(DMODEL / 32, DMODEL / 32), 256>>>(outw, WH, WL, DMODEL, DMODEL);
        aconv_kernel<<<8320, 128>>>(O + (size_t)PADF * DMODEL, AH, AL, NHTOK, DMODEL);
        tc_gemm_kernel<<<dim3(DMODEL / 128, 65), 256, TCG_SMEM>>>(
            AH, AL, WH, WL, Hbuf, outb, NHTOK, DMODEL, DMODEL, FLAG_ACC, 0, 1.f);
    };

    attn(H, ln1_g, ln1_b, qkv1_w, out1_w, out1_b, conv1_w);

    ppeg_tile_kernel<<<dim3(144, NHEADS), 256, PPEG_SMEM>>>(
        H, H2, pg7_w, pg7_b, pg5_w, pg5_b, pg3_w, pg3_b);
    copy_row0_kernel<<<1, DMODEL>>>(H, H2);

    attn(H2, ln2_g, ln2_b, qkv2_w, out2_w, out2_b, conv2_w);

    final_kernel<<<1, DMODEL>>>(H2, norm_g, norm_b, fc2_w, fc2_b, (float*)d_out, out_size);
}